// round 1
// baseline (speedup 1.0000x reference)
#include <cuda_runtime.h>

// ---------------------------------------------------------------------------
// MGMQTorchModel: dual-stream lane GAT -> fuse MLP -> mean -> proj -> biGRU -> out
// B=8192, K=4, NUM_LANES=12, LANE_F=4, HEADS=4, OUT=32, EMB=128, HID=64, GRU_H=32
// Kernel 1: one block per node (B*5 = 40960 nodes), 128 threads.
// Kernel 2: one block per batch element (8192), 192 threads (96 fwd / 96 bwd GRU).
// ---------------------------------------------------------------------------

#define NB 8192
#define NODES (NB*5)

// scratch: neighbor embeddings (B, 4, 128)
__device__ float g_nbr_emb[NB * 4 * 128];

__global__ __launch_bounds__(128) void mgmq_k1(
    const float* __restrict__ self_f,      // (B,48)
    const float* __restrict__ nbr_f,       // (B,4,48)
    const float* __restrict__ W_coop,      // (4,4,32)
    const float* __restrict__ a_src_coop,  // (4,32)
    const float* __restrict__ a_dst_coop,
    const float* __restrict__ W_conf,
    const float* __restrict__ a_src_conf,
    const float* __restrict__ a_dst_conf,
    const float* __restrict__ W_fuse,      // (256,128)
    const float* __restrict__ b_fuse,      // (128)
    float* __restrict__ out)               // (B,192)
{
    const int n = blockIdx.x;
    const int b = n / 5;
    const int slot = n - b * 5;
    const int t = threadIdx.x;

    __shared__ float sx[48];
    __shared__ float sWh[2][4][12][32];   // 12 KB
    __shared__ float sES[2][4][12];
    __shared__ float sED[2][4][12];
    __shared__ float sAtt[2][4][12][12];  // 4.5 KB
    __shared__ float sCat[12][256];       // 12 KB

    // ---- load node features (12 lanes x 4 feats) ----
    const float* xsrc = (slot == 0) ? (self_f + (size_t)b * 48)
                                    : (nbr_f + ((size_t)b * 4 + (slot - 1)) * 48);
    if (t < 48) sx[t] = xsrc[t];
    __syncthreads();

    // ---- Wh[s][h][l][o] = sum_f x[l][f] * W[s][h][f][o] ----
    for (int idx = t; idx < 2 * 4 * 12 * 32; idx += 128) {
        int s = idx / 1536;
        int r = idx - s * 1536;
        int h = r / 384;
        int rem = r - h * 384;
        int l = rem >> 5;
        int o = rem & 31;
        const float* W = s ? W_conf : W_coop;
        float acc = 0.f;
        #pragma unroll
        for (int f = 0; f < 4; f++)
            acc += sx[l * 4 + f] * __ldg(&W[(h * 4 + f) * 32 + o]);
        sWh[s][h][l][o] = acc;
    }
    __syncthreads();

    // ---- e_s, e_d : 2*4*12 = 96 rows, dot of 32 each ----
    if (t < 96) {
        int s = t / 48;
        int r = t - s * 48;
        int h = r / 12;
        int l = r - h * 12;
        const float* as = s ? a_src_conf : a_src_coop;
        const float* ad = s ? a_dst_conf : a_dst_coop;
        float es = 0.f, ed = 0.f;
        #pragma unroll
        for (int o = 0; o < 32; o++) {
            float w = sWh[s][h][l][o];
            es += w * __ldg(&as[h * 32 + o]);
            ed += w * __ldg(&ad[h * 32 + o]);
        }
        sES[s][h][l] = es;
        sED[s][h][l] = ed;
    }
    __syncthreads();

    // ---- masked softmax rows: att[s][h][i][j] ----
    if (t < 96) {
        int s = t / 48;
        int r = t - s * 48;
        int h = r / 12;
        int i = r - h * 12;
        int gi = i / 3;
        float es = sES[s][h][i];
        float ev[12];
        float m = -1e30f;
        #pragma unroll
        for (int j = 0; j < 12; j++) {
            bool same = ((j / 3) == gi);
            bool valid = (s == 0) ? same : !same;
            float e = es + sED[s][h][j];
            e = (e > 0.f) ? e : 0.2f * e;   // leaky_relu alpha=0.2
            ev[j] = valid ? e : -1e30f;
            if (valid && e > m) m = e;
        }
        float sum = 0.f;
        float ex[12];
        #pragma unroll
        for (int j = 0; j < 12; j++) {
            float v = (ev[j] > -1e29f) ? __expf(ev[j] - m) : 0.f;
            ex[j] = v;
            sum += v;
        }
        float inv = 1.f / sum;
        #pragma unroll
        for (int j = 0; j < 12; j++) sAtt[s][h][i][j] = ex[j] * inv;
    }
    __syncthreads();

    // ---- aggregation + elu -> sCat[i][s*128 + h*32 + o] ----
    {
        int o = t & 31;
        int h = (t >> 5) & 3;
        #pragma unroll
        for (int s = 0; s < 2; s++) {
            float wh[12];
            #pragma unroll
            for (int j = 0; j < 12; j++) wh[j] = sWh[s][h][j][o];
            #pragma unroll
            for (int i = 0; i < 12; i++) {
                float acc = 0.f;
                #pragma unroll
                for (int j = 0; j < 12; j++) acc += sAtt[s][h][i][j] * wh[j];
                float v = (acc > 0.f) ? acc : (__expf(acc) - 1.f);  // elu
                sCat[i][s * 128 + h * 32 + o] = v;
            }
        }
    }
    __syncthreads();

    // ---- fuse GEMM: (12 x 256) @ (256 x 128), thread t = output column ----
    float acc[12];
    #pragma unroll
    for (int l = 0; l < 12; l++) acc[l] = 0.f;

    #pragma unroll 4
    for (int kk = 0; kk < 256; kk++) {
        float w = __ldg(&W_fuse[kk * 128 + t]);
        #pragma unroll
        for (int l = 0; l < 12; l++) acc[l] += sCat[l][kk] * w;
    }

    float bb = __ldg(&b_fuse[t]);
    float mean = 0.f;
    #pragma unroll
    for (int l = 0; l < 12; l++) {
        float v = acc[l] + bb;
        v = (v > 0.f) ? v : (__expf(v) - 1.f);  // elu
        mean += v;
    }
    mean *= (1.f / 12.f);

    if (slot == 0)
        out[(size_t)b * 192 + t] = mean;                         // self_emb
    else
        g_nbr_emb[((size_t)b * 4 + (slot - 1)) * 128 + t] = mean;
}

__global__ __launch_bounds__(192) void mgmq_k2(
    const float* __restrict__ mask,    // (B,4)
    const float* __restrict__ dirs,    // (B,4)
    const float* __restrict__ W_proj,  // (129,64)
    const float* __restrict__ b_proj,  // (64)
    const float* __restrict__ Wih_f,   // (64,96)
    const float* __restrict__ Whh_f,   // (32,96)
    const float* __restrict__ bih_f,   // (96)
    const float* __restrict__ bhh_f,   // (96)
    const float* __restrict__ Wih_b,
    const float* __restrict__ Whh_b,
    const float* __restrict__ bih_b,
    const float* __restrict__ bhh_b,
    const float* __restrict__ W_out,   // (192,64)
    const float* __restrict__ b_out,   // (64)
    float* __restrict__ out)           // (B,192)
{
    const int b = blockIdx.x;
    const int t = threadIdx.x;

    __shared__ float s_nbr[4][132];   // emb(128) + dir at [128]
    __shared__ float s_x[4][64];
    __shared__ float s_gi[2][96];
    __shared__ float s_gh[2][96];
    __shared__ float s_h[2][32];
    __shared__ float s_cat[192];

    // load neighbor embeddings + self_emb (written by k1 into out[b][0:128])
    for (int idx = t; idx < 512; idx += 192) {
        int kk = idx >> 7;
        int c = idx & 127;
        s_nbr[kk][c] = g_nbr_emb[((size_t)b * 4 + kk) * 128 + c];
    }
    if (t < 4) s_nbr[t][128] = dirs[b * 4 + t];
    for (int idx = t; idx < 128; idx += 192) s_cat[idx] = out[(size_t)b * 192 + idx];
    if (t < 64) s_h[t >> 5][t & 31] = 0.f;
    __syncthreads();

    // proj: x[k] = relu(nbr_in[k] @ W_proj + b_proj) * mask[k]
    for (int idx = t; idx < 256; idx += 192) {
        int kk = idx >> 6;
        int j = idx & 63;
        float acc = __ldg(&b_proj[j]);
        #pragma unroll 4
        for (int i = 0; i < 129; i++)
            acc += s_nbr[kk][i] * __ldg(&W_proj[i * 64 + j]);
        acc = (acc > 0.f) ? acc : 0.f;
        s_x[kk][j] = acc * mask[b * 4 + kk];
    }
    __syncthreads();

    // bidirectional GRU: threads [0,96)=fwd, [96,192)=bwd
    const int d = t / 96;
    const int tt = t - d * 96;
    const float* Wih = d ? Wih_b : Wih_f;
    const float* Whh = d ? Whh_b : Whh_f;
    const float* bih = d ? bih_b : bih_f;
    const float* bhh = d ? bhh_b : bhh_f;

    for (int step = 0; step < 4; step++) {
        int kf = d ? (3 - step) : step;
        float gi = __ldg(&bih[tt]);
        #pragma unroll 4
        for (int i = 0; i < 64; i++) gi += s_x[kf][i] * __ldg(&Wih[i * 96 + tt]);
        float gh = __ldg(&bhh[tt]);
        #pragma unroll 4
        for (int i = 0; i < 32; i++) gh += s_h[d][i] * __ldg(&Whh[i * 96 + tt]);
        s_gi[d][tt] = gi;
        s_gh[d][tt] = gh;
        __syncthreads();
        if (tt < 32) {
            float r = 1.f / (1.f + __expf(-(s_gi[d][tt] + s_gh[d][tt])));
            float z = 1.f / (1.f + __expf(-(s_gi[d][32 + tt] + s_gh[d][32 + tt])));
            float nn = tanhf(s_gi[d][64 + tt] + r * s_gh[d][64 + tt]);
            s_h[d][tt] = (1.f - z) * nn + z * s_h[d][tt];
        }
        __syncthreads();
    }

    // concat(self_emb, h_f, h_b)
    if (t >= 128 && t < 192) {
        int j = t - 128;             // 0..63
        s_cat[128 + j] = s_h[j >> 5][j & 31];
    }
    __syncthreads();

    // net = relu(cat @ W_out + b_out); out[b][128:192] = net
    if (t < 64) {
        float acc = __ldg(&b_out[t]);
        #pragma unroll 4
        for (int i = 0; i < 192; i++) acc += s_cat[i] * __ldg(&W_out[i * 64 + t]);
        out[(size_t)b * 192 + 128 + t] = (acc > 0.f) ? acc : 0.f;
    }
}

extern "C" void kernel_launch(void* const* d_in, const int* in_sizes, int n_in,
                              void* d_out, int out_size) {
    const float* self_f    = (const float*)d_in[0];
    const float* nbr_f     = (const float*)d_in[1];
    const float* mask      = (const float*)d_in[2];
    const float* dirs      = (const float*)d_in[3];
    const float* W_coop    = (const float*)d_in[4];
    const float* a_src_c   = (const float*)d_in[5];
    const float* a_dst_c   = (const float*)d_in[6];
    const float* W_conf    = (const float*)d_in[7];
    const float* a_src_f2  = (const float*)d_in[8];
    const float* a_dst_f2  = (const float*)d_in[9];
    const float* W_fuse    = (const float*)d_in[10];
    const float* b_fuse    = (const float*)d_in[11];
    const float* W_proj    = (const float*)d_in[12];
    const float* b_proj    = (const float*)d_in[13];
    const float* Wih_f     = (const float*)d_in[14];
    const float* Whh_f     = (const float*)d_in[15];
    const float* bih_f     = (const float*)d_in[16];
    const float* bhh_f     = (const float*)d_in[17];
    const float* Wih_b     = (const float*)d_in[18];
    const float* Whh_b     = (const float*)d_in[19];
    const float* bih_b     = (const float*)d_in[20];
    const float* bhh_b     = (const float*)d_in[21];
    const float* W_out     = (const float*)d_in[22];
    const float* b_out     = (const float*)d_in[23];
    float* out = (float*)d_out;

    mgmq_k1<<<NODES, 128>>>(self_f, nbr_f,
                            W_coop, a_src_c, a_dst_c,
                            W_conf, a_src_f2, a_dst_f2,
                            W_fuse, b_fuse, out);

    mgmq_k2<<<NB, 192>>>(mask, dirs, W_proj, b_proj,
                         Wih_f, Whh_f, bih_f, bhh_f,
                         Wih_b, Whh_b, bih_b, bhh_b,
                         W_out, b_out, out);
}

// round 2
// speedup vs baseline: 1.0667x; 1.0667x over previous
#include <cuda_runtime.h>

// ---------------------------------------------------------------------------
// MGMQTorchModel: dual-stream lane GAT -> fuse MLP -> mean -> proj -> biGRU -> out
// B=8192, K=4, NUM_LANES=12, LANE_F=4, HEADS=4, OUT=32, EMB=128, HID=64, GRU_H=32
// R2: f32x2 packed FFMA in fuse GEMM, float4 weight loads, hoisted GRU gates.
// ---------------------------------------------------------------------------

#define NB 8192
#define NODES (NB*5)

__device__ float g_nbr_emb[NB * 4 * 128];

// ---- f32x2 packed helpers -------------------------------------------------
__device__ __forceinline__ unsigned long long pack2(float lo, float hi) {
    unsigned long long r;
    asm("mov.b64 %0, {%1, %2};" : "=l"(r) : "f"(lo), "f"(hi));
    return r;
}
__device__ __forceinline__ void fma2(unsigned long long& d,
                                     unsigned long long a,
                                     unsigned long long b) {
    asm("fma.rn.f32x2 %0, %1, %2, %0;" : "+l"(d) : "l"(a), "l"(b));
}
__device__ __forceinline__ void unpack2(unsigned long long v, float& lo, float& hi) {
    asm("mov.b64 {%0, %1}, %2;" : "=f"(lo), "=f"(hi) : "l"(v));
}
__device__ __forceinline__ float tanh_fast(float x) {
    float y; asm("tanh.approx.f32 %0, %1;" : "=f"(y) : "f"(x)); return y;
}
__device__ __forceinline__ float sigmoid_fast(float x) {
    return 1.f / (1.f + __expf(-x));
}

// ============================ KERNEL 1 ======================================
__global__ __launch_bounds__(128) void mgmq_k1(
    const float* __restrict__ self_f,      // (B,48)
    const float* __restrict__ nbr_f,       // (B,4,48)
    const float* __restrict__ W_coop,      // (4,4,32)
    const float* __restrict__ a_src_coop,  // (4,32)
    const float* __restrict__ a_dst_coop,
    const float* __restrict__ W_conf,
    const float* __restrict__ a_src_conf,
    const float* __restrict__ a_dst_conf,
    const float* __restrict__ W_fuse,      // (256,128)
    const float* __restrict__ b_fuse,      // (128)
    float* __restrict__ out)               // (B,192)
{
    const int n = blockIdx.x;
    const int b = n / 5;
    const int slot = n - b * 5;
    const int t = threadIdx.x;

    __shared__ float sx[48];
    __shared__ float sWh[2][4][12][32];   // 12 KB
    __shared__ float sES[2][4][12];
    __shared__ float sED[2][4][12];
    __shared__ float sAtt[2][4][12][12];  // 4.5 KB
    __shared__ float sCatT[256][12];      // transposed cat: [feature][row], 12 KB

    // ---- load node features ----
    const float* xsrc = (slot == 0) ? (self_f + (size_t)b * 48)
                                    : (nbr_f + ((size_t)b * 4 + (slot - 1)) * 48);
    if (t < 48) sx[t] = xsrc[t];
    __syncthreads();

    // ---- Wh[s][h][l][o] = sum_f x[l][f] * W[s][h][f][o], float4 over o ----
    for (int idx = t; idx < 768; idx += 128) {
        int s = idx / 384;
        int r = idx - s * 384;
        int h = r / 96;
        int rem = r - h * 96;
        int l = rem >> 3;
        int oq = (rem & 7) << 2;
        const float* W = s ? W_conf : W_coop;
        float4 acc = make_float4(0.f, 0.f, 0.f, 0.f);
        #pragma unroll
        for (int f = 0; f < 4; f++) {
            float xv = sx[l * 4 + f];
            float4 w = __ldg((const float4*)&W[(h * 4 + f) * 32 + oq]);
            acc.x += xv * w.x; acc.y += xv * w.y;
            acc.z += xv * w.z; acc.w += xv * w.w;
        }
        *(float4*)&sWh[s][h][l][oq] = acc;
    }
    __syncthreads();

    // ---- e_s, e_d : 96 rows, dot of 32 (float4) ----
    if (t < 96) {
        int s = t / 48;
        int r = t - s * 48;
        int h = r / 12;
        int l = r - h * 12;
        const float* as = s ? a_src_conf : a_src_coop;
        const float* ad = s ? a_dst_conf : a_dst_coop;
        float es = 0.f, ed = 0.f;
        #pragma unroll
        for (int oq = 0; oq < 32; oq += 4) {
            float4 w = *(const float4*)&sWh[s][h][l][oq];
            float4 a1 = __ldg((const float4*)&as[h * 32 + oq]);
            float4 a2 = __ldg((const float4*)&ad[h * 32 + oq]);
            es += w.x * a1.x + w.y * a1.y + w.z * a1.z + w.w * a1.w;
            ed += w.x * a2.x + w.y * a2.y + w.z * a2.z + w.w * a2.w;
        }
        sES[s][h][l] = es;
        sED[s][h][l] = ed;
    }
    __syncthreads();

    // ---- masked softmax rows ----
    if (t < 96) {
        int s = t / 48;
        int r = t - s * 48;
        int h = r / 12;
        int i = r - h * 12;
        int gi = i / 3;
        float es = sES[s][h][i];
        float ev[12];
        float m = -1e30f;
        #pragma unroll
        for (int j = 0; j < 12; j++) {
            bool same = ((j / 3) == gi);
            bool valid = (s == 0) ? same : !same;
            float e = es + sED[s][h][j];
            e = (e > 0.f) ? e : 0.2f * e;   // leaky_relu(0.2)
            ev[j] = valid ? e : -1e30f;
            if (valid && e > m) m = e;
        }
        float sum = 0.f;
        float ex[12];
        #pragma unroll
        for (int j = 0; j < 12; j++) {
            float v = (ev[j] > -1e29f) ? __expf(ev[j] - m) : 0.f;
            ex[j] = v;
            sum += v;
        }
        float inv = 1.f / sum;
        #pragma unroll
        for (int j = 0; j < 12; j++) sAtt[s][h][i][j] = ex[j] * inv;
    }
    __syncthreads();

    // ---- aggregation + elu -> sCatT[c][i] (transposed) ----
    {
        int o = t & 31;
        int h = (t >> 5) & 3;
        #pragma unroll
        for (int s = 0; s < 2; s++) {
            float wh[12];
            #pragma unroll
            for (int j = 0; j < 12; j++) wh[j] = sWh[s][h][j][o];
            int c = s * 128 + h * 32 + o;
            #pragma unroll
            for (int i = 0; i < 12; i++) {
                const float4* ar = (const float4*)sAtt[s][h][i];
                float4 a0 = ar[0], a1 = ar[1], a2 = ar[2];
                float acc = a0.x * wh[0] + a0.y * wh[1] + a0.z * wh[2] + a0.w * wh[3]
                          + a1.x * wh[4] + a1.y * wh[5] + a1.z * wh[6] + a1.w * wh[7]
                          + a2.x * wh[8] + a2.y * wh[9] + a2.z * wh[10] + a2.w * wh[11];
                float v = (acc > 0.f) ? acc : (__expf(acc) - 1.f);  // elu
                sCatT[c][i] = v;
            }
        }
    }
    __syncthreads();

    // ---- fuse GEMM (12 x 256)@(256 x 128) with packed f32x2 FMA ----
    // acc[p] lanes = rows (2p, 2p+1); thread t = output column.
    unsigned long long acc[6] = {0ull, 0ull, 0ull, 0ull, 0ull, 0ull};

    #pragma unroll 4
    for (int kk = 0; kk < 256; kk++) {
        float w = __ldg(&W_fuse[kk * 128 + t]);
        unsigned long long ww = pack2(w, w);
        const ulonglong2* row = (const ulonglong2*)&sCatT[kk][0];
        ulonglong2 p0 = row[0];
        ulonglong2 p1 = row[1];
        ulonglong2 p2 = row[2];
        fma2(acc[0], p0.x, ww);
        fma2(acc[1], p0.y, ww);
        fma2(acc[2], p1.x, ww);
        fma2(acc[3], p1.y, ww);
        fma2(acc[4], p2.x, ww);
        fma2(acc[5], p2.y, ww);
    }

    float bb = __ldg(&b_fuse[t]);
    float mean = 0.f;
    #pragma unroll
    for (int p = 0; p < 6; p++) {
        float lo, hi;
        unpack2(acc[p], lo, hi);
        float v0 = lo + bb;
        v0 = (v0 > 0.f) ? v0 : (__expf(v0) - 1.f);
        float v1 = hi + bb;
        v1 = (v1 > 0.f) ? v1 : (__expf(v1) - 1.f);
        mean += v0 + v1;
    }
    mean *= (1.f / 12.f);

    if (slot == 0)
        out[(size_t)b * 192 + t] = mean;
    else
        g_nbr_emb[((size_t)b * 4 + (slot - 1)) * 128 + t] = mean;
}

// ============================ KERNEL 2 ======================================
__global__ __launch_bounds__(192) void mgmq_k2(
    const float* __restrict__ mask,    // (B,4)
    const float* __restrict__ dirs,    // (B,4)
    const float* __restrict__ W_proj,  // (129,64)
    const float* __restrict__ b_proj,  // (64)
    const float* __restrict__ Wih_f,   // (64,96)
    const float* __restrict__ Whh_f,   // (32,96)
    const float* __restrict__ bih_f,   // (96)
    const float* __restrict__ bhh_f,   // (96)
    const float* __restrict__ Wih_b,
    const float* __restrict__ Whh_b,
    const float* __restrict__ bih_b,
    const float* __restrict__ bhh_b,
    const float* __restrict__ W_out,   // (192,64)
    const float* __restrict__ b_out,   // (64)
    float* __restrict__ out)           // (B,192)
{
    const int b = blockIdx.x;
    const int t = threadIdx.x;

    __shared__ float s_nbr[4][132];   // emb(128) + dir at [128]
    __shared__ float s_x[4][64];
    __shared__ float s_gi[2][4][96];  // all input-gate pre-activations hoisted
    __shared__ float s_gh[2][96];
    __shared__ float s_h[2][32];
    __shared__ float s_cat[192];

    // load neighbor embeddings + self_emb
    for (int idx = t; idx < 512; idx += 192) {
        int kk = idx >> 7;
        int c = idx & 127;
        s_nbr[kk][c] = g_nbr_emb[((size_t)b * 4 + kk) * 128 + c];
    }
    if (t < 4) s_nbr[t][128] = dirs[b * 4 + t];
    for (int idx = t; idx < 128; idx += 192) s_cat[idx] = out[(size_t)b * 192 + idx];
    if (t < 64) s_h[t >> 5][t & 31] = 0.f;
    __syncthreads();

    // proj: 64 threads, each one (k, 4-col quad): x[k] = relu(nbr_in@W_proj+b)*mask
    if (t < 64) {
        int kk = t >> 4;
        int j4 = (t & 15) << 2;
        float4 acc = __ldg((const float4*)&b_proj[j4]);
        #pragma unroll 4
        for (int i = 0; i < 129; i++) {
            float xv = s_nbr[kk][i];
            float4 w = __ldg((const float4*)&W_proj[i * 64 + j4]);
            acc.x += xv * w.x; acc.y += xv * w.y;
            acc.z += xv * w.z; acc.w += xv * w.w;
        }
        float m = mask[b * 4 + kk];
        acc.x = (acc.x > 0.f ? acc.x : 0.f) * m;
        acc.y = (acc.y > 0.f ? acc.y : 0.f) * m;
        acc.z = (acc.z > 0.f ? acc.z : 0.f) * m;
        acc.w = (acc.w > 0.f ? acc.w : 0.f) * m;
        *(float4*)&s_x[kk][j4] = acc;
    }
    __syncthreads();

    // hoisted gi: 2 dir x 4 steps x 24 quads = 192 items -> one per thread
    {
        int d = t / 96;
        int r = t - d * 96;
        int kk = r / 24;
        int j4 = (r % 24) << 2;
        const float* Wih = d ? Wih_b : Wih_f;
        const float* bih = d ? bih_b : bih_f;
        float4 acc = __ldg((const float4*)&bih[j4]);
        #pragma unroll 4
        for (int i = 0; i < 64; i++) {
            float xv = s_x[kk][i];
            float4 w = __ldg((const float4*)&Wih[i * 96 + j4]);
            acc.x += xv * w.x; acc.y += xv * w.y;
            acc.z += xv * w.z; acc.w += xv * w.w;
        }
        *(float4*)&s_gi[d][kk][j4] = acc;
    }
    __syncthreads();

    // sequential GRU (fwd + bwd concurrently)
    for (int step = 0; step < 4; step++) {
        if (t < 48) {
            int d = t / 24;
            int j4 = (t % 24) << 2;
            const float* Whh = d ? Whh_b : Whh_f;
            const float* bhh = d ? bhh_b : bhh_f;
            float4 acc = __ldg((const float4*)&bhh[j4]);
            #pragma unroll
            for (int i = 0; i < 32; i++) {
                float hv = s_h[d][i];
                float4 w = __ldg((const float4*)&Whh[i * 96 + j4]);
                acc.x += hv * w.x; acc.y += hv * w.y;
                acc.z += hv * w.z; acc.w += hv * w.w;
            }
            *(float4*)&s_gh[d][j4] = acc;
        }
        __syncthreads();
        if (t < 64) {
            int d = t >> 5;
            int g = t & 31;
            int kf = d ? (3 - step) : step;
            float r = sigmoid_fast(s_gi[d][kf][g]      + s_gh[d][g]);
            float z = sigmoid_fast(s_gi[d][kf][32 + g] + s_gh[d][32 + g]);
            float nn = tanh_fast(s_gi[d][kf][64 + g] + r * s_gh[d][64 + g]);
            s_h[d][g] = (1.f - z) * nn + z * s_h[d][g];
        }
        __syncthreads();
    }

    if (t < 64) s_cat[128 + t] = s_h[t >> 5][t & 31];
    __syncthreads();

    // out GEMV: 16 threads x float4 columns
    if (t < 16) {
        int j4 = t << 2;
        float4 acc = __ldg((const float4*)&b_out[j4]);
        #pragma unroll 4
        for (int i = 0; i < 192; i++) {
            float cv = s_cat[i];
            float4 w = __ldg((const float4*)&W_out[i * 64 + j4]);
            acc.x += cv * w.x; acc.y += cv * w.y;
            acc.z += cv * w.z; acc.w += cv * w.w;
        }
        acc.x = acc.x > 0.f ? acc.x : 0.f;
        acc.y = acc.y > 0.f ? acc.y : 0.f;
        acc.z = acc.z > 0.f ? acc.z : 0.f;
        acc.w = acc.w > 0.f ? acc.w : 0.f;
        *(float4*)&out[(size_t)b * 192 + 128 + j4] = acc;
    }
}

extern "C" void kernel_launch(void* const* d_in, const int* in_sizes, int n_in,
                              void* d_out, int out_size) {
    const float* self_f    = (const float*)d_in[0];
    const float* nbr_f     = (const float*)d_in[1];
    const float* mask      = (const float*)d_in[2];
    const float* dirs      = (const float*)d_in[3];
    const float* W_coop    = (const float*)d_in[4];
    const float* a_src_c   = (const float*)d_in[5];
    const float* a_dst_c   = (const float*)d_in[6];
    const float* W_conf    = (const float*)d_in[7];
    const float* a_src_f2  = (const float*)d_in[8];
    const float* a_dst_f2  = (const float*)d_in[9];
    const float* W_fuse    = (const float*)d_in[10];
    const float* b_fuse    = (const float*)d_in[11];
    const float* W_proj    = (const float*)d_in[12];
    const float* b_proj    = (const float*)d_in[13];
    const float* Wih_f     = (const float*)d_in[14];
    const float* Whh_f     = (const float*)d_in[15];
    const float* bih_f     = (const float*)d_in[16];
    const float* bhh_f     = (const float*)d_in[17];
    const float* Wih_b     = (const float*)d_in[18];
    const float* Whh_b     = (const float*)d_in[19];
    const float* bih_b     = (const float*)d_in[20];
    const float* bhh_b     = (const float*)d_in[21];
    const float* W_out     = (const float*)d_in[22];
    const float* b_out     = (const float*)d_in[23];
    float* out = (float*)d_out;

    mgmq_k1<<<NODES, 128>>>(self_f, nbr_f,
                            W_coop, a_src_c, a_dst_c,
                            W_conf, a_src_f2, a_dst_f2,
                            W_fuse, b_fuse, out);

    mgmq_k2<<<NB, 192>>>(mask, dirs, W_proj, b_proj,
                         Wih_f, Whh_f, bih_f, bhh_f,
                         Wih_b, Whh_b, bih_b, bhh_b,
                         W_out, b_out, out);
}

// round 4
// speedup vs baseline: 1.4052x; 1.3174x over previous
#include <cuda_runtime.h>
#include <cuda_bf16.h>
#include <cstdint>

// ---------------------------------------------------------------------------
// MGMQTorchModel R4:
//   wsplit: W_fuse -> transposed bf16 hi/lo images  Wt[term][n=128][k=256]
//   k1    : GAT per node -> cat rows as bf16 hi/lo linear tiles (A images)
//   gemm  : mma.sync m16n8k16 bf16 3-term compensated fuse GEMM + bias+elu+mean
//   k2    : proj + biGRU + out, 4 batch elements per 256-thread block
// (compute_103 virtual target: no tcgen05/TMEM — HMMA via mma.sync only)
// ---------------------------------------------------------------------------

#define NB 8192
#define NODES (NB*5)          // 40960
#define NTILES (NODES/8)      // 5120 M-tiles (8 nodes x 16 padded rows)

__device__ float g_nbr_emb[NB * 4 * 128];
// A images: [tile][row 128][col 256] bf16, hi and lo
__device__ __nv_bfloat16 g_catA_hi[(size_t)NTILES * 32768];
__device__ __nv_bfloat16 g_catA_lo[(size_t)NTILES * 32768];
// B images: Wt[term][n 128][k 256] bf16  (term 0 = hi, 1 = lo)
__device__ __nv_bfloat16 g_WtT[2 * 32768];

__device__ __forceinline__ float tanh_fast(float x) {
    float y; asm("tanh.approx.f32 %0, %1;" : "=f"(y) : "f"(x)); return y;
}
__device__ __forceinline__ float sigmoid_fast(float x) {
    return 1.f / (1.f + __expf(-x));
}
__device__ __forceinline__ float elu_f(float x) {
    return (x > 0.f) ? x : (__expf(x) - 1.f);
}

__device__ __forceinline__ void mma16816(float* d, const uint32_t* a,
                                         uint32_t b0, uint32_t b1) {
    asm volatile(
        "mma.sync.aligned.m16n8k16.row.col.f32.bf16.bf16.f32 "
        "{%0,%1,%2,%3}, {%4,%5,%6,%7}, {%8,%9}, {%0,%1,%2,%3};"
        : "+f"(d[0]), "+f"(d[1]), "+f"(d[2]), "+f"(d[3])
        : "r"(a[0]), "r"(a[1]), "r"(a[2]), "r"(a[3]), "r"(b0), "r"(b1));
}

// ======================= setup: W_fuse -> Wt images =========================
__global__ void mgmq_wsplit(const float* __restrict__ W_fuse) {
    int idx = blockIdx.x * blockDim.x + threadIdx.x;   // 32768 items
    if (idx >= 128 * 256) return;
    int n = idx >> 8;          // output col of W_fuse
    int k = idx & 255;
    float w = W_fuse[k * 128 + n];
    __nv_bfloat16 hi = __float2bfloat16(w);
    __nv_bfloat16 lo = __float2bfloat16(w - __bfloat162float(hi));
    g_WtT[n * 256 + k] = hi;
    g_WtT[32768 + n * 256 + k] = lo;
}

// ============================ KERNEL 1 (GAT) ================================
__global__ __launch_bounds__(128) void mgmq_k1(
    const float* __restrict__ self_f, const float* __restrict__ nbr_f,
    const float* __restrict__ W_coop, const float* __restrict__ a_src_coop,
    const float* __restrict__ a_dst_coop, const float* __restrict__ W_conf,
    const float* __restrict__ a_src_conf, const float* __restrict__ a_dst_conf)
{
    const int n = blockIdx.x;
    const int b = n / 5;
    const int slot = n - b * 5;
    const int t = threadIdx.x;

    __shared__ float sx[48];
    __shared__ float sWh[2][4][12][32];
    __shared__ float sES[2][4][12];
    __shared__ float sED[2][4][12];
    __shared__ float sAtt[2][4][12][12];
    __shared__ float sCat[12][256];

    const float* xsrc = (slot == 0) ? (self_f + (size_t)b * 48)
                                    : (nbr_f + ((size_t)b * 4 + (slot - 1)) * 48);
    if (t < 48) sx[t] = xsrc[t];
    __syncthreads();

    for (int idx = t; idx < 768; idx += 128) {
        int s = idx / 384, r = idx - s * 384, h = r / 96;
        int rem = r - h * 96, l = rem >> 3, oq = (rem & 7) << 2;
        const float* W = s ? W_conf : W_coop;
        float4 acc = make_float4(0.f, 0.f, 0.f, 0.f);
        #pragma unroll
        for (int f = 0; f < 4; f++) {
            float xv = sx[l * 4 + f];
            float4 w = __ldg((const float4*)&W[(h * 4 + f) * 32 + oq]);
            acc.x += xv * w.x; acc.y += xv * w.y; acc.z += xv * w.z; acc.w += xv * w.w;
        }
        *(float4*)&sWh[s][h][l][oq] = acc;
    }
    __syncthreads();

    if (t < 96) {
        int s = t / 48, r = t - s * 48, h = r / 12, l = r - h * 12;
        const float* as = s ? a_src_conf : a_src_coop;
        const float* ad = s ? a_dst_conf : a_dst_coop;
        float es = 0.f, ed = 0.f;
        #pragma unroll
        for (int oq = 0; oq < 32; oq += 4) {
            float4 w = *(const float4*)&sWh[s][h][l][oq];
            float4 a1 = __ldg((const float4*)&as[h * 32 + oq]);
            float4 a2 = __ldg((const float4*)&ad[h * 32 + oq]);
            es += w.x*a1.x + w.y*a1.y + w.z*a1.z + w.w*a1.w;
            ed += w.x*a2.x + w.y*a2.y + w.z*a2.z + w.w*a2.w;
        }
        sES[s][h][l] = es; sED[s][h][l] = ed;
    }
    __syncthreads();

    if (t < 96) {
        int s = t / 48, r = t - s * 48, h = r / 12, i = r - h * 12;
        int gi = i / 3;
        float es = sES[s][h][i];
        float ev[12], m = -1e30f;
        #pragma unroll
        for (int j = 0; j < 12; j++) {
            bool same = ((j / 3) == gi);
            bool valid = (s == 0) ? same : !same;
            float e = es + sED[s][h][j];
            e = (e > 0.f) ? e : 0.2f * e;
            ev[j] = valid ? e : -1e30f;
            if (valid && e > m) m = e;
        }
        float sum = 0.f, ex[12];
        #pragma unroll
        for (int j = 0; j < 12; j++) {
            float v = (ev[j] > -1e29f) ? __expf(ev[j] - m) : 0.f;
            ex[j] = v; sum += v;
        }
        float inv = 1.f / sum;
        #pragma unroll
        for (int j = 0; j < 12; j++) sAtt[s][h][i][j] = ex[j] * inv;
    }
    __syncthreads();

    {
        int o = t & 31, h = (t >> 5) & 3;
        #pragma unroll
        for (int s = 0; s < 2; s++) {
            float wh[12];
            #pragma unroll
            for (int j = 0; j < 12; j++) wh[j] = sWh[s][h][j][o];
            int c = s * 128 + h * 32 + o;
            #pragma unroll
            for (int i = 0; i < 12; i++) {
                const float4* ar = (const float4*)sAtt[s][h][i];
                float4 a0 = ar[0], a1 = ar[1], a2 = ar[2];
                float acc = a0.x*wh[0] + a0.y*wh[1] + a0.z*wh[2] + a0.w*wh[3]
                          + a1.x*wh[4] + a1.y*wh[5] + a1.z*wh[6] + a1.w*wh[7]
                          + a2.x*wh[8] + a2.y*wh[9] + a2.z*wh[10] + a2.w*wh[11];
                sCat[i][c] = elu_f(acc);
            }
        }
    }
    __syncthreads();

    // ---- write cat rows (padded to 16) as bf16 hi/lo, linear layout ----
    const int tile = n >> 3;
    const int rbase = (n & 7) * 16;
    __nv_bfloat16* gH = g_catA_hi + (size_t)tile * 32768;
    __nv_bfloat16* gL = g_catA_lo + (size_t)tile * 32768;
    for (int seg = t; seg < 512; seg += 128) {     // 16 rows x 32 segs of 8 cols
        int r = seg >> 5;
        int c8 = (seg & 31) << 3;
        float v[8];
        if (r < 12) {
            float4 p0 = *(const float4*)&sCat[r][c8];
            float4 p1 = *(const float4*)&sCat[r][c8 + 4];
            v[0]=p0.x; v[1]=p0.y; v[2]=p0.z; v[3]=p0.w;
            v[4]=p1.x; v[5]=p1.y; v[6]=p1.z; v[7]=p1.w;
        } else {
            #pragma unroll
            for (int j = 0; j < 8; j++) v[j] = 0.f;
        }
        uint32_t hw[4], lw[4];
        #pragma unroll
        for (int j = 0; j < 4; j++) {
            __nv_bfloat16 h0 = __float2bfloat16(v[2*j]);
            __nv_bfloat16 h1 = __float2bfloat16(v[2*j+1]);
            float r0 = v[2*j]   - __bfloat162float(h0);
            float r1 = v[2*j+1] - __bfloat162float(h1);
            __nv_bfloat16 l0 = __float2bfloat16(r0);
            __nv_bfloat16 l1 = __float2bfloat16(r1);
            hw[j] = (uint32_t)__bfloat16_as_ushort(h0) | ((uint32_t)__bfloat16_as_ushort(h1) << 16);
            lw[j] = (uint32_t)__bfloat16_as_ushort(l0) | ((uint32_t)__bfloat16_as_ushort(l1) << 16);
        }
        size_t eoff = (size_t)(rbase + r) * 256 + c8;
        *(uint4*)(gH + eoff) = make_uint4(hw[0], hw[1], hw[2], hw[3]);
        *(uint4*)(gL + eoff) = make_uint4(lw[0], lw[1], lw[2], lw[3]);
    }
}

// ======================== GEMM kernel (mma.sync bf16) =======================
// D[128,128] = A_tile[128,256] @ Wt^T, 3-term bf16 compensation, fp32 accum.
// smem layout (dynamic):
//   Ah [128][264] bf16 @ 0       (67584 B)
//   Al [128][264] bf16 @ 67584
//   Bh [128 n][136 k] bf16 @ 135168 (34816 B)   one K-chunk (128) at a time
//   Bl @ 169984
#define AH_OFF 0
#define AL_OFF 67584
#define BH_OFF 135168
#define BL_OFF 169984
#define SMEM_GEMM 204800
#define A_RS 528   // A row stride bytes
#define B_RS 272   // B row stride bytes

__global__ __launch_bounds__(512) void mgmq_gemm(
    const float* __restrict__ b_fuse,
    float* __restrict__ out)
{
    extern __shared__ char dsm[];
    __shared__ float sbias[128];
    __shared__ float sepi[8][128];

    const int t = threadIdx.x;
    const int wid = t >> 5;
    const int lid = t & 31;
    const int tile = blockIdx.x;

    if (t < 128) sbias[t] = __ldg(&b_fuse[t]);

    // ---- load A hi/lo into padded smem ----
    {
        const uint4* gH = (const uint4*)(g_catA_hi + (size_t)tile * 32768);
        const uint4* gL = (const uint4*)(g_catA_lo + (size_t)tile * 32768);
        for (int i = t; i < 4096; i += 512) {
            int row = i >> 5, c16 = i & 31;
            *(uint4*)(dsm + AH_OFF + row * A_RS + c16 * 16) = gH[i];
            *(uint4*)(dsm + AL_OFF + row * A_RS + c16 * 16) = gL[i];
        }
    }

    const int mtile = wid >> 1;       // 0..7
    const int nhalf = wid & 1;        // 0..1
    const int g = lid >> 2;           // 0..7
    const int q = lid & 3;            // 0..3
    const int row0 = mtile * 16 + g;
    const int row1 = row0 + 8;

    float d[8][4];
    #pragma unroll
    for (int nt = 0; nt < 8; nt++) {
        d[nt][0] = 0.f; d[nt][1] = 0.f; d[nt][2] = 0.f; d[nt][3] = 0.f;
    }

    #pragma unroll
    for (int kc = 0; kc < 2; kc++) {
        __syncthreads();
        // ---- load B chunk (both terms) ----
        {
            const uint4* gBh = (const uint4*)g_WtT;
            const uint4* gBl = (const uint4*)(g_WtT + 32768);
            for (int i = t; i < 2048; i += 512) {       // 128 n-rows x 16 uint4
                int nr = i >> 4, c16 = i & 15;
                *(uint4*)(dsm + BH_OFF + nr * B_RS + c16 * 16) = gBh[nr * 32 + kc * 16 + c16];
                *(uint4*)(dsm + BL_OFF + nr * B_RS + c16 * 16) = gBl[nr * 32 + kc * 16 + c16];
            }
        }
        __syncthreads();

        #pragma unroll
        for (int ks = 0; ks < 8; ks++) {
            // A fragments (full-K smem: col = kc*128 + ks*16 + q*2)
            const int acol = (kc * 128 + ks * 16 + q * 2) * 2;
            uint32_t ah[4], al[4];
            ah[0] = *(const uint32_t*)(dsm + AH_OFF + row0 * A_RS + acol);
            ah[1] = *(const uint32_t*)(dsm + AH_OFF + row1 * A_RS + acol);
            ah[2] = *(const uint32_t*)(dsm + AH_OFF + row0 * A_RS + acol + 16);
            ah[3] = *(const uint32_t*)(dsm + AH_OFF + row1 * A_RS + acol + 16);
            al[0] = *(const uint32_t*)(dsm + AL_OFF + row0 * A_RS + acol);
            al[1] = *(const uint32_t*)(dsm + AL_OFF + row1 * A_RS + acol);
            al[2] = *(const uint32_t*)(dsm + AL_OFF + row0 * A_RS + acol + 16);
            al[3] = *(const uint32_t*)(dsm + AL_OFF + row1 * A_RS + acol + 16);

            const int bcol = (ks * 16 + q * 2) * 2;
            #pragma unroll
            for (int nt = 0; nt < 8; nt++) {
                const int nrow = nhalf * 64 + nt * 8 + g;
                uint32_t bh0 = *(const uint32_t*)(dsm + BH_OFF + nrow * B_RS + bcol);
                uint32_t bh1 = *(const uint32_t*)(dsm + BH_OFF + nrow * B_RS + bcol + 16);
                uint32_t bl0 = *(const uint32_t*)(dsm + BL_OFF + nrow * B_RS + bcol);
                uint32_t bl1 = *(const uint32_t*)(dsm + BL_OFF + nrow * B_RS + bcol + 16);
                mma16816(d[nt], ah, bh0, bh1);
                mma16816(d[nt], ah, bl0, bl1);
                mma16816(d[nt], al, bh0, bh1);
            }
        }
    }

    // ---- epilogue: bias + elu + masked row-mean (12 of 16 rows) ----
    // D rows: g (always < 12) and g+8 (valid iff g < 4)
    #pragma unroll
    for (int nt = 0; nt < 8; nt++) {
        int c0 = nhalf * 64 + nt * 8 + q * 2;
        float b0 = sbias[c0], b1 = sbias[c0 + 1];
        float s0 = elu_f(d[nt][0] + b0);
        float s1 = elu_f(d[nt][1] + b1);
        if (g < 4) {
            s0 += elu_f(d[nt][2] + b0);
            s1 += elu_f(d[nt][3] + b1);
        }
        s0 += __shfl_xor_sync(0xFFFFFFFFu, s0, 4);
        s0 += __shfl_xor_sync(0xFFFFFFFFu, s0, 8);
        s0 += __shfl_xor_sync(0xFFFFFFFFu, s0, 16);
        s1 += __shfl_xor_sync(0xFFFFFFFFu, s1, 4);
        s1 += __shfl_xor_sync(0xFFFFFFFFu, s1, 8);
        s1 += __shfl_xor_sync(0xFFFFFFFFu, s1, 16);
        if (lid < 4) {
            sepi[mtile][c0]     = s0 * (1.f / 12.f);
            sepi[mtile][c0 + 1] = s1 * (1.f / 12.f);
        }
    }
    __syncthreads();

    // ---- scatter 8 node embeddings ----
    if (t < 256) {
        int nl = t >> 5;                 // 0..7
        int c4 = (t & 31) << 2;          // 0..124
        int node = tile * 8 + nl;
        int b = node / 5, slot = node - b * 5;
        float4 val = *(const float4*)&sepi[nl][c4];
        if (slot == 0) *(float4*)&out[(size_t)b * 192 + c4] = val;
        else *(float4*)&g_nbr_emb[((size_t)b * 4 + (slot - 1)) * 128 + c4] = val;
    }
}

// ============================ KERNEL 2 ======================================
__global__ __launch_bounds__(256) void mgmq_k2(
    const float* __restrict__ mask, const float* __restrict__ dirs,
    const float* __restrict__ W_proj, const float* __restrict__ b_proj,
    const float* __restrict__ Wih_f, const float* __restrict__ Whh_f,
    const float* __restrict__ bih_f, const float* __restrict__ bhh_f,
    const float* __restrict__ Wih_b, const float* __restrict__ Whh_b,
    const float* __restrict__ bih_b, const float* __restrict__ bhh_b,
    const float* __restrict__ W_out, const float* __restrict__ b_out,
    float* __restrict__ out)
{
    const int b0 = blockIdx.x * 4;
    const int t = threadIdx.x;

    __shared__ float s_nbr[4][4][132];
    __shared__ float s_x[4][4][64];
    __shared__ float s_gi[4][2][4][96];
    __shared__ float s_gh[4][2][96];
    __shared__ float s_h[4][2][32];
    __shared__ float s_cat[4][192];

    for (int idx = t; idx < 2048; idx += 256) {
        int bb = idx >> 9, kk = (idx >> 7) & 3, c = idx & 127;
        s_nbr[bb][kk][c] = g_nbr_emb[(((size_t)(b0 + bb)) * 4 + kk) * 128 + c];
    }
    if (t < 16) s_nbr[t >> 2][t & 3][128] = dirs[(b0 + (t >> 2)) * 4 + (t & 3)];
    for (int idx = t; idx < 512; idx += 256) {
        int bb = idx >> 7, c = idx & 127;
        s_cat[bb][c] = out[(size_t)(b0 + bb) * 192 + c];
    }
    { int bb = t >> 6, r = t & 63; s_h[bb][r >> 5][r & 31] = 0.f; }
    __syncthreads();

    {
        int bb = t >> 6, kk = (t >> 4) & 3, j4 = (t & 15) << 2;
        float4 acc = __ldg((const float4*)&b_proj[j4]);
        #pragma unroll 4
        for (int i = 0; i < 129; i++) {
            float xv = s_nbr[bb][kk][i];
            float4 w = __ldg((const float4*)&W_proj[i * 64 + j4]);
            acc.x += xv * w.x; acc.y += xv * w.y; acc.z += xv * w.z; acc.w += xv * w.w;
        }
        float m = mask[(b0 + bb) * 4 + kk];
        acc.x = (acc.x > 0.f ? acc.x : 0.f) * m;
        acc.y = (acc.y > 0.f ? acc.y : 0.f) * m;
        acc.z = (acc.z > 0.f ? acc.z : 0.f) * m;
        acc.w = (acc.w > 0.f ? acc.w : 0.f) * m;
        *(float4*)&s_x[bb][kk][j4] = acc;
    }
    __syncthreads();

    for (int idx = t; idx < 768; idx += 256) {
        int bb = idx / 192, r = idx % 192;
        int d = r / 96, qq = r % 96, kk = qq / 24, j4 = (qq % 24) << 2;
        const float* Wih = d ? Wih_b : Wih_f;
        const float* bih = d ? bih_b : bih_f;
        float4 acc = __ldg((const float4*)&bih[j4]);
        #pragma unroll 4
        for (int i = 0; i < 64; i++) {
            float xv = s_x[bb][kk][i];
            float4 w = __ldg((const float4*)&Wih[i * 96 + j4]);
            acc.x += xv * w.x; acc.y += xv * w.y; acc.z += xv * w.z; acc.w += xv * w.w;
        }
        *(float4*)&s_gi[bb][d][kk][j4] = acc;
    }
    __syncthreads();

    for (int step = 0; step < 4; step++) {
        if (t < 192) {
            int bb = t / 48, r = t % 48, d = r / 24, j4 = (r % 24) << 2;
            const float* Whh = d ? Whh_b : Whh_f;
            const float* bhh = d ? bhh_b : bhh_f;
            float4 acc = __ldg((const float4*)&bhh[j4]);
            #pragma unroll
            for (int i = 0; i < 32; i++) {
                float hv = s_h[bb][d][i];
                float4 w = __ldg((const float4*)&Whh[i * 96 + j4]);
                acc.x += hv * w.x; acc.y += hv * w.y; acc.z += hv * w.z; acc.w += hv * w.w;
            }
            *(float4*)&s_gh[bb][d][j4] = acc;
        }
        __syncthreads();
        {
            int bb = t >> 6, d = (t >> 5) & 1, gg = t & 31;
            int kf = d ? (3 - step) : step;
            float r = sigmoid_fast(s_gi[bb][d][kf][gg]      + s_gh[bb][d][gg]);
            float z = sigmoid_fast(s_gi[bb][d][kf][32 + gg] + s_gh[bb][d][32 + gg]);
            float nn = tanh_fast(s_gi[bb][d][kf][64 + gg] + r * s_gh[bb][d][64 + gg]);
            s_h[bb][d][gg] = (1.f - z) * nn + z * s_h[bb][d][gg];
        }
        __syncthreads();
    }

    { int bb = t >> 6, r = t & 63; s_cat[bb][128 + r] = s_h[bb][r >> 5][r & 31]; }
    __syncthreads();

    if (t < 64) {
        int bb = t >> 4, j4 = (t & 15) << 2;
        float4 acc = __ldg((const float4*)&b_out[j4]);
        #pragma unroll 4
        for (int i = 0; i < 192; i++) {
            float cv = s_cat[bb][i];
            float4 w = __ldg((const float4*)&W_out[i * 64 + j4]);
            acc.x += cv * w.x; acc.y += cv * w.y; acc.z += cv * w.z; acc.w += cv * w.w;
        }
        acc.x = acc.x > 0.f ? acc.x : 0.f;
        acc.y = acc.y > 0.f ? acc.y : 0.f;
        acc.z = acc.z > 0.f ? acc.z : 0.f;
        acc.w = acc.w > 0.f ? acc.w : 0.f;
        *(float4*)&out[(size_t)(b0 + bb) * 192 + 128 + j4] = acc;
    }
}

// ============================ launch ========================================
extern "C" void kernel_launch(void* const* d_in, const int* in_sizes, int n_in,
                              void* d_out, int out_size) {
    const float* self_f   = (const float*)d_in[0];
    const float* nbr_f    = (const float*)d_in[1];
    const float* mask     = (const float*)d_in[2];
    const float* dirs     = (const float*)d_in[3];
    const float* W_coop   = (const float*)d_in[4];
    const float* a_src_c  = (const float*)d_in[5];
    const float* a_dst_c  = (const float*)d_in[6];
    const float* W_conf   = (const float*)d_in[7];
    const float* a_src_f2 = (const float*)d_in[8];
    const float* a_dst_f2 = (const float*)d_in[9];
    const float* W_fuse   = (const float*)d_in[10];
    const float* b_fuse   = (const float*)d_in[11];
    const float* W_proj   = (const float*)d_in[12];
    const float* b_proj   = (const float*)d_in[13];
    const float* Wih_f    = (const float*)d_in[14];
    const float* Whh_f    = (const float*)d_in[15];
    const float* bih_f    = (const float*)d_in[16];
    const float* bhh_f    = (const float*)d_in[17];
    const float* Wih_b    = (const float*)d_in[18];
    const float* Whh_b    = (const float*)d_in[19];
    const float* bih_b    = (const float*)d_in[20];
    const float* bhh_b    = (const float*)d_in[21];
    const float* W_out    = (const float*)d_in[22];
    const float* b_out    = (const float*)d_in[23];
    float* out = (float*)d_out;

    cudaFuncSetAttribute(mgmq_gemm, cudaFuncAttributeMaxDynamicSharedMemorySize, SMEM_GEMM);

    mgmq_wsplit<<<128, 256>>>(W_fuse);
    mgmq_k1<<<NODES, 128>>>(self_f, nbr_f, W_coop, a_src_c, a_dst_c,
                            W_conf, a_src_f2, a_dst_f2);
    mgmq_gemm<<<NTILES, 512, SMEM_GEMM>>>(b_fuse, out);
    mgmq_k2<<<NB / 4, 256>>>(mask, dirs, W_proj, b_proj,
                             Wih_f, Whh_f, bih_f, bhh_f,
                             Wih_b, Whh_b, bih_b, bhh_b,
                             W_out, b_out, out);
}

// round 5
// speedup vs baseline: 1.6087x; 1.1448x over previous
#include <cuda_runtime.h>
#include <cuda_bf16.h>
#include <cstdint>

// ---------------------------------------------------------------------------
// MGMQTorchModel R5:
//   wsplit: W_fuse -> transposed bf16 hi/lo images  Wt[term][n=128][k=256]
//   k1    : GAT per node -> cat rows as bf16 hi/lo tight-packed tiles (M=96)
//   gemm  : mma.sync m16n8k16 bf16 3-term compensated, M=96 (8 nodes x 12 rows,
//           zero padding eliminated), smem-staged epilogue mean
//   k2    : proj + biGRU + out, 8 batch elements per 256-thread block
// ---------------------------------------------------------------------------

#define NB 8192
#define NODES (NB*5)          // 40960
#define NTILES (NODES/8)      // 5120 M-tiles (8 nodes x 12 rows = 96)

__device__ float g_nbr_emb[NB * 4 * 128];
// A images: [tile][row 96][col 256] bf16, hi and lo (tight packed)
__device__ __nv_bfloat16 g_catA_hi[(size_t)NTILES * 24576];
__device__ __nv_bfloat16 g_catA_lo[(size_t)NTILES * 24576];
// B images: Wt[term][n 128][k 256] bf16  (term 0 = hi, 1 = lo)
__device__ __nv_bfloat16 g_WtT[2 * 32768];

__device__ __forceinline__ float tanh_fast(float x) {
    float y; asm("tanh.approx.f32 %0, %1;" : "=f"(y) : "f"(x)); return y;
}
__device__ __forceinline__ float sigmoid_fast(float x) {
    return 1.f / (1.f + __expf(-x));
}
__device__ __forceinline__ float elu_f(float x) {
    return (x > 0.f) ? x : (__expf(x) - 1.f);
}

__device__ __forceinline__ void mma16816(float* d, const uint32_t* a,
                                         uint32_t b0, uint32_t b1) {
    asm volatile(
        "mma.sync.aligned.m16n8k16.row.col.f32.bf16.bf16.f32 "
        "{%0,%1,%2,%3}, {%4,%5,%6,%7}, {%8,%9}, {%0,%1,%2,%3};"
        : "+f"(d[0]), "+f"(d[1]), "+f"(d[2]), "+f"(d[3])
        : "r"(a[0]), "r"(a[1]), "r"(a[2]), "r"(a[3]), "r"(b0), "r"(b1));
}

// ======================= setup: W_fuse -> Wt images =========================
__global__ void mgmq_wsplit(const float* __restrict__ W_fuse) {
    int idx = blockIdx.x * blockDim.x + threadIdx.x;   // 32768 items
    if (idx >= 128 * 256) return;
    int n = idx >> 8;
    int k = idx & 255;
    float w = W_fuse[k * 128 + n];
    __nv_bfloat16 hi = __float2bfloat16(w);
    __nv_bfloat16 lo = __float2bfloat16(w - __bfloat162float(hi));
    g_WtT[n * 256 + k] = hi;
    g_WtT[32768 + n * 256 + k] = lo;
}

// ============================ KERNEL 1 (GAT) ================================
__global__ __launch_bounds__(128) void mgmq_k1(
    const float* __restrict__ self_f, const float* __restrict__ nbr_f,
    const float* __restrict__ W_coop, const float* __restrict__ a_src_coop,
    const float* __restrict__ a_dst_coop, const float* __restrict__ W_conf,
    const float* __restrict__ a_src_conf, const float* __restrict__ a_dst_conf)
{
    const int n = blockIdx.x;
    const int b = n / 5;
    const int slot = n - b * 5;
    const int t = threadIdx.x;

    __shared__ float sx[48];
    __shared__ float sWh[2][4][12][32];
    __shared__ float sES[2][4][12];
    __shared__ float sED[2][4][12];
    __shared__ float sAtt[2][4][12][12];
    __shared__ float sCat[12][256];

    const float* xsrc = (slot == 0) ? (self_f + (size_t)b * 48)
                                    : (nbr_f + ((size_t)b * 4 + (slot - 1)) * 48);
    if (t < 48) sx[t] = xsrc[t];
    __syncthreads();

    for (int idx = t; idx < 768; idx += 128) {
        int s = idx / 384, r = idx - s * 384, h = r / 96;
        int rem = r - h * 96, l = rem >> 3, oq = (rem & 7) << 2;
        const float* W = s ? W_conf : W_coop;
        float4 acc = make_float4(0.f, 0.f, 0.f, 0.f);
        #pragma unroll
        for (int f = 0; f < 4; f++) {
            float xv = sx[l * 4 + f];
            float4 w = __ldg((const float4*)&W[(h * 4 + f) * 32 + oq]);
            acc.x += xv * w.x; acc.y += xv * w.y; acc.z += xv * w.z; acc.w += xv * w.w;
        }
        *(float4*)&sWh[s][h][l][oq] = acc;
    }
    __syncthreads();

    if (t < 96) {
        int s = t / 48, r = t - s * 48, h = r / 12, l = r - h * 12;
        const float* as = s ? a_src_conf : a_src_coop;
        const float* ad = s ? a_dst_conf : a_dst_coop;
        float es = 0.f, ed = 0.f;
        #pragma unroll
        for (int oq = 0; oq < 32; oq += 4) {
            float4 w = *(const float4*)&sWh[s][h][l][oq];
            float4 a1 = __ldg((const float4*)&as[h * 32 + oq]);
            float4 a2 = __ldg((const float4*)&ad[h * 32 + oq]);
            es += w.x*a1.x + w.y*a1.y + w.z*a1.z + w.w*a1.w;
            ed += w.x*a2.x + w.y*a2.y + w.z*a2.z + w.w*a2.w;
        }
        sES[s][h][l] = es; sED[s][h][l] = ed;
    }
    __syncthreads();

    if (t < 96) {
        int s = t / 48, r = t - s * 48, h = r / 12, i = r - h * 12;
        int gi = i / 3;
        float es = sES[s][h][i];
        float ev[12], m = -1e30f;
        #pragma unroll
        for (int j = 0; j < 12; j++) {
            bool same = ((j / 3) == gi);
            bool valid = (s == 0) ? same : !same;
            float e = es + sED[s][h][j];
            e = (e > 0.f) ? e : 0.2f * e;
            ev[j] = valid ? e : -1e30f;
            if (valid && e > m) m = e;
        }
        float sum = 0.f, ex[12];
        #pragma unroll
        for (int j = 0; j < 12; j++) {
            float v = (ev[j] > -1e29f) ? __expf(ev[j] - m) : 0.f;
            ex[j] = v; sum += v;
        }
        float inv = 1.f / sum;
        #pragma unroll
        for (int j = 0; j < 12; j++) sAtt[s][h][i][j] = ex[j] * inv;
    }
    __syncthreads();

    {
        int o = t & 31, h = (t >> 5) & 3;
        #pragma unroll
        for (int s = 0; s < 2; s++) {
            float wh[12];
            #pragma unroll
            for (int j = 0; j < 12; j++) wh[j] = sWh[s][h][j][o];
            int c = s * 128 + h * 32 + o;
            #pragma unroll
            for (int i = 0; i < 12; i++) {
                const float4* ar = (const float4*)sAtt[s][h][i];
                float4 a0 = ar[0], a1 = ar[1], a2 = ar[2];
                float acc = a0.x*wh[0] + a0.y*wh[1] + a0.z*wh[2] + a0.w*wh[3]
                          + a1.x*wh[4] + a1.y*wh[5] + a1.z*wh[6] + a1.w*wh[7]
                          + a2.x*wh[8] + a2.y*wh[9] + a2.z*wh[10] + a2.w*wh[11];
                sCat[i][c] = elu_f(acc);
            }
        }
    }
    __syncthreads();

    // ---- write 12 cat rows as bf16 hi/lo, tight-packed tiles (M=96) ----
    const int tile = n >> 3;
    const int rbase = (n & 7) * 12;
    __nv_bfloat16* gH = g_catA_hi + (size_t)tile * 24576;
    __nv_bfloat16* gL = g_catA_lo + (size_t)tile * 24576;
    for (int seg = t; seg < 384; seg += 128) {     // 12 rows x 32 segs of 8 cols
        int r = seg >> 5;
        int c8 = (seg & 31) << 3;
        float4 p0 = *(const float4*)&sCat[r][c8];
        float4 p1 = *(const float4*)&sCat[r][c8 + 4];
        float v[8] = {p0.x, p0.y, p0.z, p0.w, p1.x, p1.y, p1.z, p1.w};
        uint32_t hw[4], lw[4];
        #pragma unroll
        for (int j = 0; j < 4; j++) {
            __nv_bfloat16 h0 = __float2bfloat16(v[2*j]);
            __nv_bfloat16 h1 = __float2bfloat16(v[2*j+1]);
            float r0 = v[2*j]   - __bfloat162float(h0);
            float r1 = v[2*j+1] - __bfloat162float(h1);
            __nv_bfloat16 l0 = __float2bfloat16(r0);
            __nv_bfloat16 l1 = __float2bfloat16(r1);
            hw[j] = (uint32_t)__bfloat16_as_ushort(h0) | ((uint32_t)__bfloat16_as_ushort(h1) << 16);
            lw[j] = (uint32_t)__bfloat16_as_ushort(l0) | ((uint32_t)__bfloat16_as_ushort(l1) << 16);
        }
        size_t eoff = (size_t)(rbase + r) * 256 + c8;
        *(uint4*)(gH + eoff) = make_uint4(hw[0], hw[1], hw[2], hw[3]);
        *(uint4*)(gL + eoff) = make_uint4(lw[0], lw[1], lw[2], lw[3]);
    }
}

// ======================== GEMM kernel (mma.sync bf16) =======================
// D[96,128] = A_tile[96,256] @ Wt^T, 3-term bf16, M tight-packed.
// smem per K-chunk (stride 136 elems = 272 B, bank-conflict-free):
//   Ah @0 (26112) | Al @26112 | Bh @52224 (34816) | Bl @87040   total 121856
// epilogue Dbuf[96][132] f32 (50688 B) reuses the A region.
#define AH_OFF 0
#define AL_OFF 26112
#define BH_OFF 52224
#define BL_OFF 87040
#define SMEM_GEMM 121856
#define CH_RS 272   // chunk row stride bytes

__global__ __launch_bounds__(384) void mgmq_gemm(
    const float* __restrict__ b_fuse,
    float* __restrict__ out)
{
    extern __shared__ char dsm[];
    __shared__ float sbias[128];

    const int t = threadIdx.x;
    const int wid = t >> 5;           // 0..11
    const int lid = t & 31;
    const int tile = blockIdx.x;

    if (t < 128) sbias[t] = __ldg(&b_fuse[t]);

    const int mtile = wid >> 1;       // 0..5
    const int nhalf = wid & 1;
    const int g = lid >> 2;
    const int q = lid & 3;
    const int row0 = mtile * 16 + g;
    const int row1 = row0 + 8;

    float d[8][4];
    #pragma unroll
    for (int nt = 0; nt < 8; nt++) {
        d[nt][0] = 0.f; d[nt][1] = 0.f; d[nt][2] = 0.f; d[nt][3] = 0.f;
    }

    const uint4* gAH = (const uint4*)(g_catA_hi + (size_t)tile * 24576);
    const uint4* gAL = (const uint4*)(g_catA_lo + (size_t)tile * 24576);
    const uint4* gBH = (const uint4*)g_WtT;
    const uint4* gBL = (const uint4*)(g_WtT + 32768);

    #pragma unroll
    for (int kc = 0; kc < 2; kc++) {
        __syncthreads();
        // A chunk: 96 rows x 16 uint4 per term
        for (int i = t; i < 1536; i += 384) {
            int row = i >> 4, c16 = i & 15;
            *(uint4*)(dsm + AH_OFF + row * CH_RS + c16 * 16) = gAH[row * 32 + kc * 16 + c16];
            *(uint4*)(dsm + AL_OFF + row * CH_RS + c16 * 16) = gAL[row * 32 + kc * 16 + c16];
        }
        // B chunk: 128 rows x 16 uint4 per term
        for (int i = t; i < 2048; i += 384) {
            int nr = i >> 4, c16 = i & 15;
            *(uint4*)(dsm + BH_OFF + nr * CH_RS + c16 * 16) = gBH[nr * 32 + kc * 16 + c16];
            *(uint4*)(dsm + BL_OFF + nr * CH_RS + c16 * 16) = gBL[nr * 32 + kc * 16 + c16];
        }
        __syncthreads();

        #pragma unroll
        for (int ks = 0; ks < 8; ks++) {
            const int col = (ks * 16 + q * 2) * 2;   // byte offset within chunk row
            uint32_t ah[4], al[4];
            ah[0] = *(const uint32_t*)(dsm + AH_OFF + row0 * CH_RS + col);
            ah[1] = *(const uint32_t*)(dsm + AH_OFF + row1 * CH_RS + col);
            ah[2] = *(const uint32_t*)(dsm + AH_OFF + row0 * CH_RS + col + 16);
            ah[3] = *(const uint32_t*)(dsm + AH_OFF + row1 * CH_RS + col + 16);
            al[0] = *(const uint32_t*)(dsm + AL_OFF + row0 * CH_RS + col);
            al[1] = *(const uint32_t*)(dsm + AL_OFF + row1 * CH_RS + col);
            al[2] = *(const uint32_t*)(dsm + AL_OFF + row0 * CH_RS + col + 16);
            al[3] = *(const uint32_t*)(dsm + AL_OFF + row1 * CH_RS + col + 16);

            #pragma unroll
            for (int nt = 0; nt < 8; nt++) {
                const int nrow = nhalf * 64 + nt * 8 + g;
                uint32_t bh0 = *(const uint32_t*)(dsm + BH_OFF + nrow * CH_RS + col);
                uint32_t bh1 = *(const uint32_t*)(dsm + BH_OFF + nrow * CH_RS + col + 16);
                uint32_t bl0 = *(const uint32_t*)(dsm + BL_OFF + nrow * CH_RS + col);
                uint32_t bl1 = *(const uint32_t*)(dsm + BL_OFF + nrow * CH_RS + col + 16);
                mma16816(d[nt], ah, bh0, bh1);
                mma16816(d[nt], ah, bl0, bl1);
                mma16816(d[nt], al, bh0, bh1);
            }
        }
    }
    __syncthreads();

    // ---- stage elu(D + bias) into Dbuf[96][132] (reuses A region) ----
    float* Dbuf = (float*)dsm;
    #pragma unroll
    for (int nt = 0; nt < 8; nt++) {
        int c0 = nhalf * 64 + nt * 8 + q * 2;
        float b0 = sbias[c0], b1 = sbias[c0 + 1];
        float2 v0 = make_float2(elu_f(d[nt][0] + b0), elu_f(d[nt][1] + b1));
        float2 v1 = make_float2(elu_f(d[nt][2] + b0), elu_f(d[nt][3] + b1));
        *(float2*)&Dbuf[row0 * 132 + c0] = v0;
        *(float2*)&Dbuf[row1 * 132 + c0] = v1;
    }
    __syncthreads();

    // ---- per-node 12-row mean + scatter ----
    if (t < 256) {
        int nl = t >> 5;                 // 0..7
        int c4 = (t & 31) << 2;
        float4 s = make_float4(0.f, 0.f, 0.f, 0.f);
        #pragma unroll
        for (int j = 0; j < 12; j++) {
            float4 v = *(const float4*)&Dbuf[(nl * 12 + j) * 132 + c4];
            s.x += v.x; s.y += v.y; s.z += v.z; s.w += v.w;
        }
        s.x *= (1.f/12.f); s.y *= (1.f/12.f); s.z *= (1.f/12.f); s.w *= (1.f/12.f);
        int node = tile * 8 + nl;
        int b = node / 5, slot = node - b * 5;
        if (slot == 0) *(float4*)&out[(size_t)b * 192 + c4] = s;
        else *(float4*)&g_nbr_emb[((size_t)b * 4 + (slot - 1)) * 128 + c4] = s;
    }
}

// ============================ KERNEL 2 ======================================
// 8 batch elements per 256-thread block, dynamic smem
struct K2Smem {
    float nbr[8][4][132];
    float x[8][4][64];
    float gi[8][2][4][96];
    float gh[8][2][96];
    float h[8][2][32];
    float cat[8][192];
};
#define SMEM_K2 ((int)sizeof(K2Smem))

__global__ __launch_bounds__(256) void mgmq_k2(
    const float* __restrict__ mask, const float* __restrict__ dirs,
    const float* __restrict__ W_proj, const float* __restrict__ b_proj,
    const float* __restrict__ Wih_f, const float* __restrict__ Whh_f,
    const float* __restrict__ bih_f, const float* __restrict__ bhh_f,
    const float* __restrict__ Wih_b, const float* __restrict__ Whh_b,
    const float* __restrict__ bih_b, const float* __restrict__ bhh_b,
    const float* __restrict__ W_out, const float* __restrict__ b_out,
    float* __restrict__ out)
{
    extern __shared__ char k2dsm[];
    K2Smem* S = (K2Smem*)k2dsm;
    const int b0 = blockIdx.x * 8;
    const int t = threadIdx.x;

    for (int i = t; i < 1024; i += 256) {
        int bb = i >> 7, kk = (i >> 5) & 3, c4 = (i & 31) << 2;
        *(float4*)&S->nbr[bb][kk][c4] =
            *(const float4*)&g_nbr_emb[(((size_t)(b0 + bb)) * 4 + kk) * 128 + c4];
    }
    if (t < 32) S->nbr[t >> 2][t & 3][128] = dirs[(b0 + (t >> 2)) * 4 + (t & 3)];
    {
        int bb = t >> 5, c4 = (t & 31) << 2;
        *(float4*)&S->cat[bb][c4] = *(const float4*)&out[(size_t)(b0 + bb) * 192 + c4];
    }
    if (t < 128) {
        int bb = t >> 4, d = (t >> 3) & 1, g8 = (t & 7) << 2;
        *(float4*)&S->h[bb][d][g8] = make_float4(0.f, 0.f, 0.f, 0.f);
    }
    __syncthreads();

    // proj: 64 weight-combos x 4 groups, each group handles 2 batches
    {
        int combo = t & 63, grp = t >> 6;
        int kk = combo >> 4, j4 = (combo & 15) << 2;
        int bA = grp, bB = grp + 4;
        float4 bs = __ldg((const float4*)&b_proj[j4]);
        float4 a0 = bs, a1 = bs;
        #pragma unroll 4
        for (int i = 0; i < 129; i++) {
            float4 w = __ldg((const float4*)&W_proj[i * 64 + j4]);
            float x0 = S->nbr[bA][kk][i], x1 = S->nbr[bB][kk][i];
            a0.x += x0*w.x; a0.y += x0*w.y; a0.z += x0*w.z; a0.w += x0*w.w;
            a1.x += x1*w.x; a1.y += x1*w.y; a1.z += x1*w.z; a1.w += x1*w.w;
        }
        float m0 = mask[(b0 + bA) * 4 + kk], m1 = mask[(b0 + bB) * 4 + kk];
        a0.x = (a0.x > 0.f ? a0.x : 0.f) * m0; a0.y = (a0.y > 0.f ? a0.y : 0.f) * m0;
        a0.z = (a0.z > 0.f ? a0.z : 0.f) * m0; a0.w = (a0.w > 0.f ? a0.w : 0.f) * m0;
        a1.x = (a1.x > 0.f ? a1.x : 0.f) * m1; a1.y = (a1.y > 0.f ? a1.y : 0.f) * m1;
        a1.z = (a1.z > 0.f ? a1.z : 0.f) * m1; a1.w = (a1.w > 0.f ? a1.w : 0.f) * m1;
        *(float4*)&S->x[bA][kk][j4] = a0;
        *(float4*)&S->x[bB][kk][j4] = a1;
    }
    __syncthreads();

    // gi: 192 threads = (d, kk, j4-quad); each loops all 8 batches (weight loaded once)
    if (t < 192) {
        int d = t / 96, r = t % 96, kk = r / 24, j4 = (r % 24) << 2;
        const float* Wih = d ? Wih_b : Wih_f;
        const float* bih = d ? bih_b : bih_f;
        float4 bs = __ldg((const float4*)&bih[j4]);
        float4 acc[8];
        #pragma unroll
        for (int bb = 0; bb < 8; bb++) acc[bb] = bs;
        for (int i = 0; i < 64; i++) {
            float4 w = __ldg((const float4*)&Wih[i * 96 + j4]);
            #pragma unroll
            for (int bb = 0; bb < 8; bb++) {
                float xv = S->x[bb][kk][i];
                acc[bb].x += xv*w.x; acc[bb].y += xv*w.y;
                acc[bb].z += xv*w.z; acc[bb].w += xv*w.w;
            }
        }
        #pragma unroll
        for (int bb = 0; bb < 8; bb++) *(float4*)&S->gi[bb][d][kk][j4] = acc[bb];
    }
    __syncthreads();

    for (int step = 0; step < 4; step++) {
        if (t < 192) {
            int combo = t % 48, grp = t / 48;       // grp 0..3
            int d = combo / 24, j4 = (combo % 24) << 2;
            int bA = grp, bB = grp + 4;
            const float* Whh = d ? Whh_b : Whh_f;
            const float* bhh = d ? bhh_b : bhh_f;
            float4 bs = __ldg((const float4*)&bhh[j4]);
            float4 a0 = bs, a1 = bs;
            #pragma unroll
            for (int i = 0; i < 32; i++) {
                float4 w = __ldg((const float4*)&Whh[i * 96 + j4]);
                float h0 = S->h[bA][d][i], h1 = S->h[bB][d][i];
                a0.x += h0*w.x; a0.y += h0*w.y; a0.z += h0*w.z; a0.w += h0*w.w;
                a1.x += h1*w.x; a1.y += h1*w.y; a1.z += h1*w.z; a1.w += h1*w.w;
            }
            *(float4*)&S->gh[bA][d][j4] = a0;
            *(float4*)&S->gh[bB][d][j4] = a1;
        }
        __syncthreads();
        {
            int bA = t >> 6, d = (t >> 5) & 1, g = t & 31;
            #pragma unroll
            for (int p = 0; p < 2; p++) {
                int bb = bA + p * 4;
                int kf = d ? (3 - step) : step;
                float r = sigmoid_fast(S->gi[bb][d][kf][g]      + S->gh[bb][d][g]);
                float z = sigmoid_fast(S->gi[bb][d][kf][32 + g] + S->gh[bb][d][32 + g]);
                float nn = tanh_fast(S->gi[bb][d][kf][64 + g] + r * S->gh[bb][d][64 + g]);
                S->h[bb][d][g] = (1.f - z) * nn + z * S->h[bb][d][g];
            }
        }
        __syncthreads();
    }

    for (int i = t; i < 512; i += 256) {
        int bb = i >> 6, r = i & 63;
        S->cat[bb][128 + r] = S->h[bb][r >> 5][r & 31];
    }
    __syncthreads();

    if (t < 128) {
        int bb = t >> 4, j4 = (t & 15) << 2;
        float4 acc = __ldg((const float4*)&b_out[j4]);
        #pragma unroll 4
        for (int i = 0; i < 192; i++) {
            float cv = S->cat[bb][i];
            float4 w = __ldg((const float4*)&W_out[i * 64 + j4]);
            acc.x += cv*w.x; acc.y += cv*w.y; acc.z += cv*w.z; acc.w += cv*w.w;
        }
        acc.x = acc.x > 0.f ? acc.x : 0.f;
        acc.y = acc.y > 0.f ? acc.y : 0.f;
        acc.z = acc.z > 0.f ? acc.z : 0.f;
        acc.w = acc.w > 0.f ? acc.w : 0.f;
        *(float4*)&out[(size_t)(b0 + bb) * 192 + 128 + j4] = acc;
    }
}

// ============================ launch ========================================
extern "C" void kernel_launch(void* const* d_in, const int* in_sizes, int n_in,
                              void* d_out, int out_size) {
    const float* self_f   = (const float*)d_in[0];
    const float* nbr_f    = (const float*)d_in[1];
    const float* mask     = (const float*)d_in[2];
    const float* dirs     = (const float*)d_in[3];
    const float* W_coop   = (const float*)d_in[4];
    const float* a_src_c  = (const float*)d_in[5];
    const float* a_dst_c  = (const float*)d_in[6];
    const float* W_conf   = (const float*)d_in[7];
    const float* a_src_f2 = (const float*)d_in[8];
    const float* a_dst_f2 = (const float*)d_in[9];
    const float* W_fuse   = (const float*)d_in[10];
    const float* b_fuse   = (const float*)d_in[11];
    const float* W_proj   = (const float*)d_in[12];
    const float* b_proj   = (const float*)d_in[13];
    const float* Wih_f    = (const float*)d_in[14];
    const float* Whh_f    = (const float*)d_in[15];
    const float* bih_f    = (const float*)d_in[16];
    const float* bhh_f    = (const float*)d_in[17];
    const float* Wih_b    = (const float*)d_in[18];
    const float* Whh_b    = (const float*)d_in[19];
    const float* bih_b    = (const float*)d_in[20];
    const float* bhh_b    = (const float*)d_in[21];
    const float* W_out    = (const float*)d_in[22];
    const float* b_out    = (const float*)d_in[23];
    float* out = (float*)d_out;

    cudaFuncSetAttribute(mgmq_gemm, cudaFuncAttributeMaxDynamicSharedMemorySize, SMEM_GEMM);
    cudaFuncSetAttribute(mgmq_k2, cudaFuncAttributeMaxDynamicSharedMemorySize, SMEM_K2);

    mgmq_wsplit<<<128, 256>>>(W_fuse);
    mgmq_k1<<<NODES, 128>>>(self_f, nbr_f, W_coop, a_src_c, a_dst_c,
                            W_conf, a_src_f2, a_dst_f2);
    mgmq_gemm<<<NTILES, 384, SMEM_GEMM>>>(b_fuse, out);
    mgmq_k2<<<NB / 8, 256, SMEM_K2>>>(mask, dirs, W_proj, b_proj,
                                      Wih_f, Whh_f, bih_f, bhh_f,
                                      Wih_b, Whh_b, bih_b, bhh_b,
                                      W_out, b_out, out);
}

// round 6
// speedup vs baseline: 1.6525x; 1.0272x over previous
#include <cuda_runtime.h>
#include <cuda_bf16.h>
#include <cstdint>

// ---------------------------------------------------------------------------
// MGMQTorchModel R6:
//   wsplit: W_fuse -> transposed bf16 hi/lo images  Wt[term][n=128][k=256]
//   k1    : GAT per node, ALL weights staged in smem (kills LDG-issue wall)
//   gemm  : mma.sync bf16x3, B resident in smem, 4 M-tiles per block
//   k2    : proj + biGRU + out, 8 batch elements per 256-thread block
// ---------------------------------------------------------------------------

#define NB 8192
#define NODES (NB*5)          // 40960
#define NTILES (NODES/8)      // 5120 M-tiles (8 nodes x 12 rows = 96)
#define TILES_PER_BLK 4

__device__ float g_nbr_emb[NB * 4 * 128];
__device__ __nv_bfloat16 g_catA_hi[(size_t)NTILES * 24576];
__device__ __nv_bfloat16 g_catA_lo[(size_t)NTILES * 24576];
__device__ __nv_bfloat16 g_WtT[2 * 32768];   // [term][n 128][k 256]

__device__ __forceinline__ float tanh_fast(float x) {
    float y; asm("tanh.approx.f32 %0, %1;" : "=f"(y) : "f"(x)); return y;
}
__device__ __forceinline__ float sigmoid_fast(float x) {
    return 1.f / (1.f + __expf(-x));
}
__device__ __forceinline__ float elu_f(float x) {
    return (x > 0.f) ? x : (__expf(x) - 1.f);
}

__device__ __forceinline__ void mma16816(float* d, const uint32_t* a,
                                         uint32_t b0, uint32_t b1) {
    asm volatile(
        "mma.sync.aligned.m16n8k16.row.col.f32.bf16.bf16.f32 "
        "{%0,%1,%2,%3}, {%4,%5,%6,%7}, {%8,%9}, {%0,%1,%2,%3};"
        : "+f"(d[0]), "+f"(d[1]), "+f"(d[2]), "+f"(d[3])
        : "r"(a[0]), "r"(a[1]), "r"(a[2]), "r"(a[3]), "r"(b0), "r"(b1));
}

// ======================= setup: W_fuse -> Wt images =========================
__global__ void mgmq_wsplit(const float* __restrict__ W_fuse) {
    int idx = blockIdx.x * blockDim.x + threadIdx.x;
    if (idx >= 128 * 256) return;
    int n = idx >> 8;
    int k = idx & 255;
    float w = W_fuse[k * 128 + n];
    __nv_bfloat16 hi = __float2bfloat16(w);
    __nv_bfloat16 lo = __float2bfloat16(w - __bfloat162float(hi));
    g_WtT[n * 256 + k] = hi;
    g_WtT[32768 + n * 256 + k] = lo;
}

// ============================ KERNEL 1 (GAT) ================================
__global__ __launch_bounds__(128) void mgmq_k1(
    const float* __restrict__ self_f, const float* __restrict__ nbr_f,
    const float* __restrict__ W_coop, const float* __restrict__ a_src_coop,
    const float* __restrict__ a_dst_coop, const float* __restrict__ W_conf,
    const float* __restrict__ a_src_conf, const float* __restrict__ a_dst_conf)
{
    const int n = blockIdx.x;
    const int b = n / 5;
    const int slot = n - b * 5;
    const int t = threadIdx.x;

    __shared__ float sx[48];
    __shared__ float sW[2][512];      // [stream][h*128 + f*32 + o]
    __shared__ float sAv[4][128];     // src_coop, dst_coop, src_conf, dst_conf
    __shared__ float sWh[2][4][12][32];
    __shared__ float sES[2][4][12];
    __shared__ float sED[2][4][12];
    __shared__ float sAtt[2][4][12][12];
    __shared__ float sCat[12][256];

    // ---- stage inputs + ALL weights into smem ----
    const float* xsrc = (slot == 0) ? (self_f + (size_t)b * 48)
                                    : (nbr_f + ((size_t)b * 4 + (slot - 1)) * 48);
    if (t < 48) sx[t] = xsrc[t];
    ((float4*)sW[0])[t] = __ldg(&((const float4*)W_coop)[t]);
    ((float4*)sW[1])[t] = __ldg(&((const float4*)W_conf)[t]);
    {
        int arr = t >> 5, i = t & 31;
        const float* src = (arr == 0) ? a_src_coop : (arr == 1) ? a_dst_coop
                         : (arr == 2) ? a_src_conf : a_dst_conf;
        ((float4*)sAv[arr])[i] = __ldg(&((const float4*)src)[i]);
    }
    __syncthreads();

    // ---- Wh[s][h][l][o] ----
    for (int idx = t; idx < 768; idx += 128) {
        int s = idx / 384, r = idx - s * 384, h = r / 96;
        int rem = r - h * 96, l = rem >> 3, oq = (rem & 7) << 2;
        const float* W = sW[s];
        float4 acc = make_float4(0.f, 0.f, 0.f, 0.f);
        #pragma unroll
        for (int f = 0; f < 4; f++) {
            float xv = sx[l * 4 + f];
            float4 w = *(const float4*)&W[h * 128 + f * 32 + oq];
            acc.x += xv * w.x; acc.y += xv * w.y; acc.z += xv * w.z; acc.w += xv * w.w;
        }
        *(float4*)&sWh[s][h][l][oq] = acc;
    }
    __syncthreads();

    // ---- e_s, e_d ----
    if (t < 96) {
        int s = t / 48, r = t - s * 48, h = r / 12, l = r - h * 12;
        const float* as = sAv[s * 2];
        const float* ad = sAv[s * 2 + 1];
        float es = 0.f, ed = 0.f;
        #pragma unroll
        for (int oq = 0; oq < 32; oq += 4) {
            float4 w = *(const float4*)&sWh[s][h][l][oq];
            float4 a1 = *(const float4*)&as[h * 32 + oq];
            float4 a2 = *(const float4*)&ad[h * 32 + oq];
            es += w.x*a1.x + w.y*a1.y + w.z*a1.z + w.w*a1.w;
            ed += w.x*a2.x + w.y*a2.y + w.z*a2.z + w.w*a2.w;
        }
        sES[s][h][l] = es; sED[s][h][l] = ed;
    }
    __syncthreads();

    // ---- masked softmax ----
    if (t < 96) {
        int s = t / 48, r = t - s * 48, h = r / 12, i = r - h * 12;
        int gi = i / 3;
        float es = sES[s][h][i];
        float ev[12], m = -1e30f;
        #pragma unroll
        for (int j = 0; j < 12; j++) {
            bool same = ((j / 3) == gi);
            bool valid = (s == 0) ? same : !same;
            float e = es + sED[s][h][j];
            e = (e > 0.f) ? e : 0.2f * e;
            ev[j] = valid ? e : -1e30f;
            if (valid && e > m) m = e;
        }
        float sum = 0.f, ex[12];
        #pragma unroll
        for (int j = 0; j < 12; j++) {
            float v = (ev[j] > -1e29f) ? __expf(ev[j] - m) : 0.f;
            ex[j] = v; sum += v;
        }
        float inv = 1.f / sum;
        #pragma unroll
        for (int j = 0; j < 12; j++) sAtt[s][h][i][j] = ex[j] * inv;
    }
    __syncthreads();

    // ---- aggregation + elu ----
    {
        int o = t & 31, h = (t >> 5) & 3;
        #pragma unroll
        for (int s = 0; s < 2; s++) {
            float wh[12];
            #pragma unroll
            for (int j = 0; j < 12; j++) wh[j] = sWh[s][h][j][o];
            int c = s * 128 + h * 32 + o;
            #pragma unroll
            for (int i = 0; i < 12; i++) {
                const float4* ar = (const float4*)sAtt[s][h][i];
                float4 a0 = ar[0], a1 = ar[1], a2 = ar[2];
                float acc = a0.x*wh[0] + a0.y*wh[1] + a0.z*wh[2] + a0.w*wh[3]
                          + a1.x*wh[4] + a1.y*wh[5] + a1.z*wh[6] + a1.w*wh[7]
                          + a2.x*wh[8] + a2.y*wh[9] + a2.z*wh[10] + a2.w*wh[11];
                sCat[i][c] = elu_f(acc);
            }
        }
    }
    __syncthreads();

    // ---- write 12 cat rows as bf16 hi/lo, tight-packed tiles (M=96) ----
    const int tile = n >> 3;
    const int rbase = (n & 7) * 12;
    __nv_bfloat16* gH = g_catA_hi + (size_t)tile * 24576;
    __nv_bfloat16* gL = g_catA_lo + (size_t)tile * 24576;
    for (int seg = t; seg < 384; seg += 128) {
        int r = seg >> 5;
        int c8 = (seg & 31) << 3;
        float4 p0 = *(const float4*)&sCat[r][c8];
        float4 p1 = *(const float4*)&sCat[r][c8 + 4];
        float v[8] = {p0.x, p0.y, p0.z, p0.w, p1.x, p1.y, p1.z, p1.w};
        uint32_t hw[4], lw[4];
        #pragma unroll
        for (int j = 0; j < 4; j++) {
            __nv_bfloat16 h0 = __float2bfloat16(v[2*j]);
            __nv_bfloat16 h1 = __float2bfloat16(v[2*j+1]);
            float r0 = v[2*j]   - __bfloat162float(h0);
            float r1 = v[2*j+1] - __bfloat162float(h1);
            __nv_bfloat16 l0 = __float2bfloat16(r0);
            __nv_bfloat16 l1 = __float2bfloat16(r1);
            hw[j] = (uint32_t)__bfloat16_as_ushort(h0) | ((uint32_t)__bfloat16_as_ushort(h1) << 16);
            lw[j] = (uint32_t)__bfloat16_as_ushort(l0) | ((uint32_t)__bfloat16_as_ushort(l1) << 16);
        }
        size_t eoff = (size_t)(rbase + r) * 256 + c8;
        *(uint4*)(gH + eoff) = make_uint4(hw[0], hw[1], hw[2], hw[3]);
        *(uint4*)(gL + eoff) = make_uint4(lw[0], lw[1], lw[2], lw[3]);
    }
}

// ======================== GEMM kernel (mma.sync bf16) =======================
// B resident (4 chunk-images), 4 M-tiles per block.
// smem: A hi@0 (26112) | A lo@26112 | B: hi_kc0@52224 hi_kc1@87040
//       lo_kc0@121856 lo_kc1@156672  (each 34816)   total 191488
// Dbuf[96][132] f32 (50688) reuses the A region per tile.
#define AH_OFF 0
#define AL_OFF 26112
#define B_OFF  52224
#define B_IMG  34816
#define SMEM_GEMM 191488
#define CH_RS 272

__global__ __launch_bounds__(384) void mgmq_gemm(
    const float* __restrict__ b_fuse,
    float* __restrict__ out)
{
    extern __shared__ char dsm[];
    __shared__ float sbias[128];

    const int t = threadIdx.x;
    const int wid = t >> 5;
    const int lid = t & 31;

    if (t < 128) sbias[t] = __ldg(&b_fuse[t]);

    // ---- load B once: 4 chunk-images ----
    {
        const uint4* gB = (const uint4*)g_WtT;   // [term][n][k/8] uint4: n*32+c16 per term
        for (int i = t; i < 8192; i += 384) {
            int img = i >> 11;                   // 0..3 : term*2 + kc
            int r = i & 2047;
            int nr = r >> 4, c16 = r & 15;
            int term = img >> 1, kc = img & 1;
            *(uint4*)(dsm + B_OFF + img * B_IMG + nr * CH_RS + c16 * 16)
                = gB[term * 4096 + nr * 32 + kc * 16 + c16];
        }
    }

    const int mtile = wid >> 1;
    const int nhalf = wid & 1;
    const int g = lid >> 2;
    const int q = lid & 3;
    const int row0 = mtile * 16 + g;
    const int row1 = row0 + 8;

    for (int tt = 0; tt < TILES_PER_BLK; tt++) {
        const int tile = blockIdx.x * TILES_PER_BLK + tt;
        const uint4* gAH = (const uint4*)(g_catA_hi + (size_t)tile * 24576);
        const uint4* gAL = (const uint4*)(g_catA_lo + (size_t)tile * 24576);

        float d[8][4];
        #pragma unroll
        for (int nt = 0; nt < 8; nt++) {
            d[nt][0] = 0.f; d[nt][1] = 0.f; d[nt][2] = 0.f; d[nt][3] = 0.f;
        }

        #pragma unroll
        for (int kc = 0; kc < 2; kc++) {
            __syncthreads();
            for (int i = t; i < 1536; i += 384) {
                int row = i >> 4, c16 = i & 15;
                *(uint4*)(dsm + AH_OFF + row * CH_RS + c16 * 16) = gAH[row * 32 + kc * 16 + c16];
                *(uint4*)(dsm + AL_OFF + row * CH_RS + c16 * 16) = gAL[row * 32 + kc * 16 + c16];
            }
            __syncthreads();

            const char* bH = dsm + B_OFF + kc * B_IMG;
            const char* bL = dsm + B_OFF + 2 * B_IMG + kc * B_IMG;

            #pragma unroll
            for (int ks = 0; ks < 8; ks++) {
                const int col = (ks * 16 + q * 2) * 2;
                uint32_t ah[4], al[4];
                ah[0] = *(const uint32_t*)(dsm + AH_OFF + row0 * CH_RS + col);
                ah[1] = *(const uint32_t*)(dsm + AH_OFF + row1 * CH_RS + col);
                ah[2] = *(const uint32_t*)(dsm + AH_OFF + row0 * CH_RS + col + 16);
                ah[3] = *(const uint32_t*)(dsm + AH_OFF + row1 * CH_RS + col + 16);
                al[0] = *(const uint32_t*)(dsm + AL_OFF + row0 * CH_RS + col);
                al[1] = *(const uint32_t*)(dsm + AL_OFF + row1 * CH_RS + col);
                al[2] = *(const uint32_t*)(dsm + AL_OFF + row0 * CH_RS + col + 16);
                al[3] = *(const uint32_t*)(dsm + AL_OFF + row1 * CH_RS + col + 16);

                #pragma unroll
                for (int nt = 0; nt < 8; nt++) {
                    const int nrow = nhalf * 64 + nt * 8 + g;
                    uint32_t bh0 = *(const uint32_t*)(bH + nrow * CH_RS + col);
                    uint32_t bh1 = *(const uint32_t*)(bH + nrow * CH_RS + col + 16);
                    uint32_t bl0 = *(const uint32_t*)(bL + nrow * CH_RS + col);
                    uint32_t bl1 = *(const uint32_t*)(bL + nrow * CH_RS + col + 16);
                    mma16816(d[nt], ah, bh0, bh1);
                    mma16816(d[nt], ah, bl0, bl1);
                    mma16816(d[nt], al, bh0, bh1);
                }
            }
        }
        __syncthreads();   // all warps done reading A before Dbuf overwrite

        // ---- stage elu(D + bias) into Dbuf (reuses A region) ----
        float* Dbuf = (float*)dsm;
        #pragma unroll
        for (int nt = 0; nt < 8; nt++) {
            int c0 = nhalf * 64 + nt * 8 + q * 2;
            float b0 = sbias[c0], b1 = sbias[c0 + 1];
            float2 v0 = make_float2(elu_f(d[nt][0] + b0), elu_f(d[nt][1] + b1));
            float2 v1 = make_float2(elu_f(d[nt][2] + b0), elu_f(d[nt][3] + b1));
            *(float2*)&Dbuf[row0 * 132 + c0] = v0;
            *(float2*)&Dbuf[row1 * 132 + c0] = v1;
        }
        __syncthreads();

        // ---- per-node 12-row mean + scatter ----
        if (t < 256) {
            int nl = t >> 5;
            int c4 = (t & 31) << 2;
            float4 s = make_float4(0.f, 0.f, 0.f, 0.f);
            #pragma unroll
            for (int j = 0; j < 12; j++) {
                float4 v = *(const float4*)&Dbuf[(nl * 12 + j) * 132 + c4];
                s.x += v.x; s.y += v.y; s.z += v.z; s.w += v.w;
            }
            s.x *= (1.f/12.f); s.y *= (1.f/12.f); s.z *= (1.f/12.f); s.w *= (1.f/12.f);
            int node = tile * 8 + nl;
            int b = node / 5, slot = node - b * 5;
            if (slot == 0) *(float4*)&out[(size_t)b * 192 + c4] = s;
            else *(float4*)&g_nbr_emb[((size_t)b * 4 + (slot - 1)) * 128 + c4] = s;
        }
    }
}

// ============================ KERNEL 2 ======================================
struct K2Smem {
    float nbr[8][4][132];
    float x[8][4][64];
    float gi[8][2][4][96];
    float gh[8][2][96];
    float h[8][2][32];
    float cat[8][192];
};
#define SMEM_K2 ((int)sizeof(K2Smem))

__global__ __launch_bounds__(256) void mgmq_k2(
    const float* __restrict__ mask, const float* __restrict__ dirs,
    const float* __restrict__ W_proj, const float* __restrict__ b_proj,
    const float* __restrict__ Wih_f, const float* __restrict__ Whh_f,
    const float* __restrict__ bih_f, const float* __restrict__ bhh_f,
    const float* __restrict__ Wih_b, const float* __restrict__ Whh_b,
    const float* __restrict__ bih_b, const float* __restrict__ bhh_b,
    const float* __restrict__ W_out, const float* __restrict__ b_out,
    float* __restrict__ out)
{
    extern __shared__ char k2dsm[];
    K2Smem* S = (K2Smem*)k2dsm;
    const int b0 = blockIdx.x * 8;
    const int t = threadIdx.x;

    for (int i = t; i < 1024; i += 256) {
        int bb = i >> 7, kk = (i >> 5) & 3, c4 = (i & 31) << 2;
        *(float4*)&S->nbr[bb][kk][c4] =
            *(const float4*)&g_nbr_emb[(((size_t)(b0 + bb)) * 4 + kk) * 128 + c4];
    }
    if (t < 32) S->nbr[t >> 2][t & 3][128] = dirs[(b0 + (t >> 2)) * 4 + (t & 3)];
    {
        int bb = t >> 5, c4 = (t & 31) << 2;
        *(float4*)&S->cat[bb][c4] = *(const float4*)&out[(size_t)(b0 + bb) * 192 + c4];
    }
    if (t < 128) {
        int bb = t >> 4, d = (t >> 3) & 1, g8 = (t & 7) << 2;
        *(float4*)&S->h[bb][d][g8] = make_float4(0.f, 0.f, 0.f, 0.f);
    }
    __syncthreads();

    {
        int combo = t & 63, grp = t >> 6;
        int kk = combo >> 4, j4 = (combo & 15) << 2;
        int bA = grp, bB = grp + 4;
        float4 bs = __ldg((const float4*)&b_proj[j4]);
        float4 a0 = bs, a1 = bs;
        #pragma unroll 4
        for (int i = 0; i < 129; i++) {
            float4 w = __ldg((const float4*)&W_proj[i * 64 + j4]);
            float x0 = S->nbr[bA][kk][i], x1 = S->nbr[bB][kk][i];
            a0.x += x0*w.x; a0.y += x0*w.y; a0.z += x0*w.z; a0.w += x0*w.w;
            a1.x += x1*w.x; a1.y += x1*w.y; a1.z += x1*w.z; a1.w += x1*w.w;
        }
        float m0 = mask[(b0 + bA) * 4 + kk], m1 = mask[(b0 + bB) * 4 + kk];
        a0.x = (a0.x > 0.f ? a0.x : 0.f) * m0; a0.y = (a0.y > 0.f ? a0.y : 0.f) * m0;
        a0.z = (a0.z > 0.f ? a0.z : 0.f) * m0; a0.w = (a0.w > 0.f ? a0.w : 0.f) * m0;
        a1.x = (a1.x > 0.f ? a1.x : 0.f) * m1; a1.y = (a1.y > 0.f ? a1.y : 0.f) * m1;
        a1.z = (a1.z > 0.f ? a1.z : 0.f) * m1; a1.w = (a1.w > 0.f ? a1.w : 0.f) * m1;
        *(float4*)&S->x[bA][kk][j4] = a0;
        *(float4*)&S->x[bB][kk][j4] = a1;
    }
    __syncthreads();

    if (t < 192) {
        int d = t / 96, r = t % 96, kk = r / 24, j4 = (r % 24) << 2;
        const float* Wih = d ? Wih_b : Wih_f;
        const float* bih = d ? bih_b : bih_f;
        float4 bs = __ldg((const float4*)&bih[j4]);
        float4 acc[8];
        #pragma unroll
        for (int bb = 0; bb < 8; bb++) acc[bb] = bs;
        for (int i = 0; i < 64; i++) {
            float4 w = __ldg((const float4*)&Wih[i * 96 + j4]);
            #pragma unroll
            for (int bb = 0; bb < 8; bb++) {
                float xv = S->x[bb][kk][i];
                acc[bb].x += xv*w.x; acc[bb].y += xv*w.y;
                acc[bb].z += xv*w.z; acc[bb].w += xv*w.w;
            }
        }
        #pragma unroll
        for (int bb = 0; bb < 8; bb++) *(float4*)&S->gi[bb][d][kk][j4] = acc[bb];
    }
    __syncthreads();

    for (int step = 0; step < 4; step++) {
        if (t < 192) {
            int combo = t % 48, grp = t / 48;
            int d = combo / 24, j4 = (combo % 24) << 2;
            int bA = grp, bB = grp + 4;
            const float* Whh = d ? Whh_b : Whh_f;
            const float* bhh = d ? bhh_b : bhh_f;
            float4 bs = __ldg((const float4*)&bhh[j4]);
            float4 a0 = bs, a1 = bs;
            #pragma unroll
            for (int i = 0; i < 32; i++) {
                float4 w = __ldg((const float4*)&Whh[i * 96 + j4]);
                float h0 = S->h[bA][d][i], h1 = S->h[bB][d][i];
                a0.x += h0*w.x; a0.y += h0*w.y; a0.z += h0*w.z; a0.w += h0*w.w;
                a1.x += h1*w.x; a1.y += h1*w.y; a1.z += h1*w.z; a1.w += h1*w.w;
            }
            *(float4*)&S->gh[bA][d][j4] = a0;
            *(float4*)&S->gh[bB][d][j4] = a1;
        }
        __syncthreads();
        {
            int bA = t >> 6, d = (t >> 5) & 1, g = t & 31;
            #pragma unroll
            for (int p = 0; p < 2; p++) {
                int bb = bA + p * 4;
                int kf = d ? (3 - step) : step;
                float r = sigmoid_fast(S->gi[bb][d][kf][g]      + S->gh[bb][d][g]);
                float z = sigmoid_fast(S->gi[bb][d][kf][32 + g] + S->gh[bb][d][32 + g]);
                float nn = tanh_fast(S->gi[bb][d][kf][64 + g] + r * S->gh[bb][d][64 + g]);
                S->h[bb][d][g] = (1.f - z) * nn + z * S->h[bb][d][g];
            }
        }
        __syncthreads();
    }

    for (int i = t; i < 512; i += 256) {
        int bb = i >> 6, r = i & 63;
        S->cat[bb][128 + r] = S->h[bb][r >> 5][r & 31];
    }
    __syncthreads();

    if (t < 128) {
        int bb = t >> 4, j4 = (t & 15) << 2;
        float4 acc = __ldg((const float4*)&b_out[j4]);
        #pragma unroll 4
        for (int i = 0; i < 192; i++) {
            float cv = S->cat[bb][i];
            float4 w = __ldg((const float4*)&W_out[i * 64 + j4]);
            acc.x += cv*w.x; acc.y += cv*w.y; acc.z += cv*w.z; acc.w += cv*w.w;
        }
        acc.x = acc.x > 0.f ? acc.x : 0.f;
        acc.y = acc.y > 0.f ? acc.y : 0.f;
        acc.z = acc.z > 0.f ? acc.z : 0.f;
        acc.w = acc.w > 0.f ? acc.w : 0.f;
        *(float4*)&out[(size_t)(b0 + bb) * 192 + 128 + j4] = acc;
    }
}

// ============================ launch ========================================
extern "C" void kernel_launch(void* const* d_in, const int* in_sizes, int n_in,
                              void* d_out, int out_size) {
    const float* self_f   = (const float*)d_in[0];
    const float* nbr_f    = (const float*)d_in[1];
    const float* mask     = (const float*)d_in[2];
    const float* dirs     = (const float*)d_in[3];
    const float* W_coop   = (const float*)d_in[4];
    const float* a_src_c  = (const float*)d_in[5];
    const float* a_dst_c  = (const float*)d_in[6];
    const float* W_conf   = (const float*)d_in[7];
    const float* a_src_f2 = (const float*)d_in[8];
    const float* a_dst_f2 = (const float*)d_in[9];
    const float* W_fuse   = (const float*)d_in[10];
    const float* b_fuse   = (const float*)d_in[11];
    const float* W_proj   = (const float*)d_in[12];
    const float* b_proj   = (const float*)d_in[13];
    const float* Wih_f    = (const float*)d_in[14];
    const float* Whh_f    = (const float*)d_in[15];
    const float* bih_f    = (const float*)d_in[16];
    const float* bhh_f    = (const float*)d_in[17];
    const float* Wih_b    = (const float*)d_in[18];
    const float* Whh_b    = (const float*)d_in[19];
    const float* bih_b    = (const float*)d_in[20];
    const float* bhh_b    = (const float*)d_in[21];
    const float* W_out    = (const float*)d_in[22];
    const float* b_out    = (const float*)d_in[23];
    float* out = (float*)d_out;

    cudaFuncSetAttribute(mgmq_gemm, cudaFuncAttributeMaxDynamicSharedMemorySize, SMEM_GEMM);
    cudaFuncSetAttribute(mgmq_k2, cudaFuncAttributeMaxDynamicSharedMemorySize, SMEM_K2);

    mgmq_wsplit<<<128, 256>>>(W_fuse);
    mgmq_k1<<<NODES, 128>>>(self_f, nbr_f, W_coop, a_src_c, a_dst_c,
                            W_conf, a_src_f2, a_dst_f2);
    mgmq_gemm<<<NTILES / TILES_PER_BLK, 384, SMEM_GEMM>>>(b_fuse, out);
    mgmq_k2<<<NB / 8, 256, SMEM_K2>>>(mask, dirs, W_proj, b_proj,
                                      Wih_f, Whh_f, bih_f, bhh_f,
                                      Wih_b, Whh_b, bih_b, bhh_b,
                                      W_out, b_out, out);
}

// round 7
// speedup vs baseline: 1.7395x; 1.0527x over previous
#include <cuda_runtime.h>
#include <cuda_bf16.h>
#include <cstdint>

// ---------------------------------------------------------------------------
// MGMQTorchModel R7:
//   gemm: ldmatrix operand loads (issue-bound test); k1: coop/conf-specialized
//   softmax + aggregation (3-term / 9-term). k2 unchanged (control).
// ---------------------------------------------------------------------------

#define NB 8192
#define NODES (NB*5)          // 40960
#define NTILES (NODES/8)      // 5120 M-tiles (8 nodes x 12 rows = 96)
#define TILES_PER_BLK 4

__device__ float g_nbr_emb[NB * 4 * 128];
__device__ __nv_bfloat16 g_catA_hi[(size_t)NTILES * 24576];
__device__ __nv_bfloat16 g_catA_lo[(size_t)NTILES * 24576];
__device__ __nv_bfloat16 g_WtT[2 * 32768];   // [term][n 128][k 256]

__device__ __forceinline__ float tanh_fast(float x) {
    float y; asm("tanh.approx.f32 %0, %1;" : "=f"(y) : "f"(x)); return y;
}
__device__ __forceinline__ float sigmoid_fast(float x) {
    return 1.f / (1.f + __expf(-x));
}
__device__ __forceinline__ float elu_f(float x) {
    return (x > 0.f) ? x : (__expf(x) - 1.f);
}
__device__ __forceinline__ uint32_t smem_u32(const void* p) {
    uint32_t a;
    asm("{ .reg .u64 t; cvta.to.shared.u64 t, %1; cvt.u32.u64 %0, t; }" : "=r"(a) : "l"(p));
    return a;
}

__device__ __forceinline__ void mma16816(float* d, const uint32_t* a,
                                         uint32_t b0, uint32_t b1) {
    asm volatile(
        "mma.sync.aligned.m16n8k16.row.col.f32.bf16.bf16.f32 "
        "{%0,%1,%2,%3}, {%4,%5,%6,%7}, {%8,%9}, {%0,%1,%2,%3};"
        : "+f"(d[0]), "+f"(d[1]), "+f"(d[2]), "+f"(d[3])
        : "r"(a[0]), "r"(a[1]), "r"(a[2]), "r"(a[3]), "r"(b0), "r"(b1));
}
#define LDSM_X4(r, addr) \
    asm volatile("ldmatrix.sync.aligned.m8n8.x4.shared.b16 {%0,%1,%2,%3}, [%4];" \
        : "=r"((r)[0]), "=r"((r)[1]), "=r"((r)[2]), "=r"((r)[3]) : "r"(addr))

// ======================= setup: W_fuse -> Wt images =========================
__global__ void mgmq_wsplit(const float* __restrict__ W_fuse) {
    int idx = blockIdx.x * blockDim.x + threadIdx.x;
    if (idx >= 128 * 256) return;
    int n = idx >> 8;
    int k = idx & 255;
    float w = W_fuse[k * 128 + n];
    __nv_bfloat16 hi = __float2bfloat16(w);
    __nv_bfloat16 lo = __float2bfloat16(w - __bfloat162float(hi));
    g_WtT[n * 256 + k] = hi;
    g_WtT[32768 + n * 256 + k] = lo;
}

// ============================ KERNEL 1 (GAT) ================================
__global__ __launch_bounds__(128) void mgmq_k1(
    const float* __restrict__ self_f, const float* __restrict__ nbr_f,
    const float* __restrict__ W_coop, const float* __restrict__ a_src_coop,
    const float* __restrict__ a_dst_coop, const float* __restrict__ W_conf,
    const float* __restrict__ a_src_conf, const float* __restrict__ a_dst_conf)
{
    const int n = blockIdx.x;
    const int b = n / 5;
    const int slot = n - b * 5;
    const int t = threadIdx.x;

    __shared__ float sx[48];
    __shared__ float sW[2][512];
    __shared__ float sAv[4][128];
    __shared__ float sWh[2][4][12][32];
    __shared__ float sES[2][4][12];
    __shared__ float sED[2][4][12];
    __shared__ float4 sAttC[4][12];      // coop: 3 atts + pad
    __shared__ float sAttF[4][12][12];   // conf: full rows (group cols unused)
    __shared__ float sCat[12][256];

    const float* xsrc = (slot == 0) ? (self_f + (size_t)b * 48)
                                    : (nbr_f + ((size_t)b * 4 + (slot - 1)) * 48);
    if (t < 48) sx[t] = xsrc[t];
    ((float4*)sW[0])[t] = __ldg(&((const float4*)W_coop)[t]);
    ((float4*)sW[1])[t] = __ldg(&((const float4*)W_conf)[t]);
    {
        int arr = t >> 5, i = t & 31;
        const float* src = (arr == 0) ? a_src_coop : (arr == 1) ? a_dst_coop
                         : (arr == 2) ? a_src_conf : a_dst_conf;
        ((float4*)sAv[arr])[i] = __ldg(&((const float4*)src)[i]);
    }
    __syncthreads();

    // ---- Wh ----
    for (int idx = t; idx < 768; idx += 128) {
        int s = idx / 384, r = idx - s * 384, h = r / 96;
        int rem = r - h * 96, l = rem >> 3, oq = (rem & 7) << 2;
        const float* W = sW[s];
        float4 acc = make_float4(0.f, 0.f, 0.f, 0.f);
        #pragma unroll
        for (int f = 0; f < 4; f++) {
            float xv = sx[l * 4 + f];
            float4 w = *(const float4*)&W[h * 128 + f * 32 + oq];
            acc.x += xv * w.x; acc.y += xv * w.y; acc.z += xv * w.z; acc.w += xv * w.w;
        }
        *(float4*)&sWh[s][h][l][oq] = acc;
    }
    __syncthreads();

    // ---- e_s, e_d ----
    if (t < 96) {
        int s = t / 48, r = t - s * 48, h = r / 12, l = r - h * 12;
        const float* as = sAv[s * 2];
        const float* ad = sAv[s * 2 + 1];
        float es = 0.f, ed = 0.f;
        #pragma unroll
        for (int oq = 0; oq < 32; oq += 4) {
            float4 w = *(const float4*)&sWh[s][h][l][oq];
            float4 a1 = *(const float4*)&as[h * 32 + oq];
            float4 a2 = *(const float4*)&ad[h * 32 + oq];
            es += w.x*a1.x + w.y*a1.y + w.z*a1.z + w.w*a1.w;
            ed += w.x*a2.x + w.y*a2.y + w.z*a2.z + w.w*a2.w;
        }
        sES[s][h][l] = es; sED[s][h][l] = ed;
    }
    __syncthreads();

    // ---- specialized masked softmax ----
    if (t < 48) {
        // coop: valid j = own group of 3
        int h = t / 12, i = t - h * 12, j0 = (i / 3) * 3;
        float es = sES[0][h][i];
        float e0 = es + sED[0][h][j0];     e0 = (e0 > 0.f) ? e0 : 0.2f * e0;
        float e1 = es + sED[0][h][j0 + 1]; e1 = (e1 > 0.f) ? e1 : 0.2f * e1;
        float e2 = es + sED[0][h][j0 + 2]; e2 = (e2 > 0.f) ? e2 : 0.2f * e2;
        float m = fmaxf(e0, fmaxf(e1, e2));
        float x0 = __expf(e0 - m), x1 = __expf(e1 - m), x2 = __expf(e2 - m);
        float inv = 1.f / (x0 + x1 + x2);
        sAttC[h][i] = make_float4(x0 * inv, x1 * inv, x2 * inv, 0.f);
    } else if (t < 96) {
        // conf: valid j = 9 lanes outside own group
        int r = t - 48;
        int h = r / 12, i = r - h * 12;
        int gi = i / 3;
        float es = sES[1][h][i];
        float ev[12], m = -1e30f;
        #pragma unroll
        for (int j = 0; j < 12; j++) {
            bool valid = ((j / 3) != gi);
            float e = es + sED[1][h][j];
            e = (e > 0.f) ? e : 0.2f * e;
            ev[j] = valid ? e : -1e30f;
            if (valid && e > m) m = e;
        }
        float sum = 0.f, ex[12];
        #pragma unroll
        for (int j = 0; j < 12; j++) {
            float v = (ev[j] > -1e29f) ? __expf(ev[j] - m) : 0.f;
            ex[j] = v; sum += v;
        }
        float inv = 1.f / sum;
        #pragma unroll
        for (int j = 0; j < 12; j++) sAttF[h][i][j] = ex[j] * inv;
    }
    __syncthreads();

    // ---- specialized aggregation + elu ----
    {
        int o = t & 31, h = (t >> 5) & 3;
        float wh0[12], wh1[12];
        #pragma unroll
        for (int j = 0; j < 12; j++) { wh0[j] = sWh[0][h][j][o]; wh1[j] = sWh[1][h][j][o]; }
        // coop: 3-term
        #pragma unroll
        for (int i = 0; i < 12; i++) {
            const int j0 = (i / 3) * 3;
            float4 a = sAttC[h][i];
            float acc = a.x * wh0[j0] + a.y * wh0[j0 + 1] + a.z * wh0[j0 + 2];
            sCat[i][h * 32 + o] = elu_f(acc);
        }
        // conf: 9-term, group columns skipped at compile time
        #pragma unroll
        for (int i = 0; i < 12; i++) {
            const int g0 = (i / 3) * 3;
            const float* ar = sAttF[h][i];
            float acc = 0.f;
            #pragma unroll
            for (int j = 0; j < 12; j++)
                if (j < g0 || j >= g0 + 3) acc += ar[j] * wh1[j];
            sCat[i][128 + h * 32 + o] = elu_f(acc);
        }
    }
    __syncthreads();

    // ---- write 12 cat rows as bf16 hi/lo, tight-packed tiles (M=96) ----
    const int tile = n >> 3;
    const int rbase = (n & 7) * 12;
    __nv_bfloat16* gH = g_catA_hi + (size_t)tile * 24576;
    __nv_bfloat16* gL = g_catA_lo + (size_t)tile * 24576;
    for (int seg = t; seg < 384; seg += 128) {
        int r = seg >> 5;
        int c8 = (seg & 31) << 3;
        float4 p0 = *(const float4*)&sCat[r][c8];
        float4 p1 = *(const float4*)&sCat[r][c8 + 4];
        float v[8] = {p0.x, p0.y, p0.z, p0.w, p1.x, p1.y, p1.z, p1.w};
        uint32_t hw[4], lw[4];
        #pragma unroll
        for (int j = 0; j < 4; j++) {
            __nv_bfloat16 h0 = __float2bfloat16(v[2*j]);
            __nv_bfloat16 h1 = __float2bfloat16(v[2*j+1]);
            float r0 = v[2*j]   - __bfloat162float(h0);
            float r1 = v[2*j+1] - __bfloat162float(h1);
            __nv_bfloat16 l0 = __float2bfloat16(r0);
            __nv_bfloat16 l1 = __float2bfloat16(r1);
            hw[j] = (uint32_t)__bfloat16_as_ushort(h0) | ((uint32_t)__bfloat16_as_ushort(h1) << 16);
            lw[j] = (uint32_t)__bfloat16_as_ushort(l0) | ((uint32_t)__bfloat16_as_ushort(l1) << 16);
        }
        size_t eoff = (size_t)(rbase + r) * 256 + c8;
        *(uint4*)(gH + eoff) = make_uint4(hw[0], hw[1], hw[2], hw[3]);
        *(uint4*)(gL + eoff) = make_uint4(lw[0], lw[1], lw[2], lw[3]);
    }
}

// ======================== GEMM kernel (mma.sync bf16) =======================
#define AH_OFF 0
#define AL_OFF 26112
#define B_OFF  52224
#define B_IMG  34816
#define SMEM_GEMM 191488
#define CH_RS 272

__global__ __launch_bounds__(384) void mgmq_gemm(
    const float* __restrict__ b_fuse,
    float* __restrict__ out)
{
    extern __shared__ char dsm[];
    __shared__ float sbias[128];

    const int t = threadIdx.x;
    const int wid = t >> 5;
    const int lid = t & 31;

    if (t < 128) sbias[t] = __ldg(&b_fuse[t]);

    // ---- load B once: 4 chunk-images ----
    {
        const uint4* gB = (const uint4*)g_WtT;
        for (int i = t; i < 8192; i += 384) {
            int img = i >> 11;
            int r = i & 2047;
            int nr = r >> 4, c16 = r & 15;
            int term = img >> 1, kc = img & 1;
            *(uint4*)(dsm + B_OFF + img * B_IMG + nr * CH_RS + c16 * 16)
                = gB[term * 4096 + nr * 32 + kc * 16 + c16];
        }
    }

    const int mtile = wid >> 1;
    const int nhalf = wid & 1;
    const int g = lid >> 2;
    const int q = lid & 3;
    const int row0 = mtile * 16 + g;
    const int row1 = row0 + 8;

    // ldmatrix lane-constant offsets
    const uint32_t sbase = smem_u32(dsm);
    const uint32_t a_lane = (uint32_t)((mtile * 16 + ((lid >> 3) & 1) * 8 + (lid & 7)) * CH_RS
                          + ((lid >> 4) & 1) * 16);
    const uint32_t b_lane = (uint32_t)((nhalf * 64 + ((lid >> 4) & 1) * 8 + (lid & 7)) * CH_RS
                          + ((lid >> 3) & 1) * 16);

    for (int tt = 0; tt < TILES_PER_BLK; tt++) {
        const int tile = blockIdx.x * TILES_PER_BLK + tt;
        const uint4* gAH = (const uint4*)(g_catA_hi + (size_t)tile * 24576);
        const uint4* gAL = (const uint4*)(g_catA_lo + (size_t)tile * 24576);

        float d[8][4];
        #pragma unroll
        for (int nt = 0; nt < 8; nt++) {
            d[nt][0] = 0.f; d[nt][1] = 0.f; d[nt][2] = 0.f; d[nt][3] = 0.f;
        }

        #pragma unroll
        for (int kc = 0; kc < 2; kc++) {
            __syncthreads();
            for (int i = t; i < 1536; i += 384) {
                int row = i >> 4, c16 = i & 15;
                *(uint4*)(dsm + AH_OFF + row * CH_RS + c16 * 16) = gAH[row * 32 + kc * 16 + c16];
                *(uint4*)(dsm + AL_OFF + row * CH_RS + c16 * 16) = gAL[row * 32 + kc * 16 + c16];
            }
            __syncthreads();

            const uint32_t aHb = sbase + AH_OFF + a_lane;
            const uint32_t aLb = sbase + AL_OFF + a_lane;
            const uint32_t bHb = sbase + B_OFF + kc * B_IMG + b_lane;
            const uint32_t bLb = sbase + B_OFF + 2 * B_IMG + kc * B_IMG + b_lane;

            #pragma unroll
            for (int ks = 0; ks < 8; ks++) {
                const uint32_t koff = ks * 32;
                uint32_t ah[4], al[4];
                LDSM_X4(ah, aHb + koff);
                LDSM_X4(al, aLb + koff);
                #pragma unroll
                for (int p = 0; p < 4; p++) {
                    uint32_t bh[4], bl[4];
                    LDSM_X4(bh, bHb + p * (16 * CH_RS) + koff);
                    LDSM_X4(bl, bLb + p * (16 * CH_RS) + koff);
                    mma16816(d[2*p],     ah, bh[0], bh[1]);
                    mma16816(d[2*p],     ah, bl[0], bl[1]);
                    mma16816(d[2*p],     al, bh[0], bh[1]);
                    mma16816(d[2*p + 1], ah, bh[2], bh[3]);
                    mma16816(d[2*p + 1], ah, bl[2], bl[3]);
                    mma16816(d[2*p + 1], al, bh[2], bh[3]);
                }
            }
        }
        __syncthreads();

        // ---- stage elu(D + bias) into Dbuf (reuses A region) ----
        float* Dbuf = (float*)dsm;
        #pragma unroll
        for (int nt = 0; nt < 8; nt++) {
            int c0 = nhalf * 64 + nt * 8 + q * 2;
            float b0 = sbias[c0], b1 = sbias[c0 + 1];
            float2 v0 = make_float2(elu_f(d[nt][0] + b0), elu_f(d[nt][1] + b1));
            float2 v1 = make_float2(elu_f(d[nt][2] + b0), elu_f(d[nt][3] + b1));
            *(float2*)&Dbuf[row0 * 132 + c0] = v0;
            *(float2*)&Dbuf[row1 * 132 + c0] = v1;
        }
        __syncthreads();

        // ---- per-node 12-row mean + scatter ----
        if (t < 256) {
            int nl = t >> 5;
            int c4 = (t & 31) << 2;
            float4 s = make_float4(0.f, 0.f, 0.f, 0.f);
            #pragma unroll
            for (int j = 0; j < 12; j++) {
                float4 v = *(const float4*)&Dbuf[(nl * 12 + j) * 132 + c4];
                s.x += v.x; s.y += v.y; s.z += v.z; s.w += v.w;
            }
            s.x *= (1.f/12.f); s.y *= (1.f/12.f); s.z *= (1.f/12.f); s.w *= (1.f/12.f);
            int node = tile * 8 + nl;
            int b = node / 5, slot = node - b * 5;
            if (slot == 0) *(float4*)&out[(size_t)b * 192 + c4] = s;
            else *(float4*)&g_nbr_emb[((size_t)b * 4 + (slot - 1)) * 128 + c4] = s;
        }
    }
}

// ============================ KERNEL 2 ======================================
struct K2Smem {
    float nbr[8][4][132];
    float x[8][4][64];
    float gi[8][2][4][96];
    float gh[8][2][96];
    float h[8][2][32];
    float cat[8][192];
};
#define SMEM_K2 ((int)sizeof(K2Smem))

__global__ __launch_bounds__(256) void mgmq_k2(
    const float* __restrict__ mask, const float* __restrict__ dirs,
    const float* __restrict__ W_proj, const float* __restrict__ b_proj,
    const float* __restrict__ Wih_f, const float* __restrict__ Whh_f,
    const float* __restrict__ bih_f, const float* __restrict__ bhh_f,
    const float* __restrict__ Wih_b, const float* __restrict__ Whh_b,
    const float* __restrict__ bih_b, const float* __restrict__ bhh_b,
    const float* __restrict__ W_out, const float* __restrict__ b_out,
    float* __restrict__ out)
{
    extern __shared__ char k2dsm[];
    K2Smem* S = (K2Smem*)k2dsm;
    const int b0 = blockIdx.x * 8;
    const int t = threadIdx.x;

    for (int i = t; i < 1024; i += 256) {
        int bb = i >> 7, kk = (i >> 5) & 3, c4 = (i & 31) << 2;
        *(float4*)&S->nbr[bb][kk][c4] =
            *(const float4*)&g_nbr_emb[(((size_t)(b0 + bb)) * 4 + kk) * 128 + c4];
    }
    if (t < 32) S->nbr[t >> 2][t & 3][128] = dirs[(b0 + (t >> 2)) * 4 + (t & 3)];
    {
        int bb = t >> 5, c4 = (t & 31) << 2;
        *(float4*)&S->cat[bb][c4] = *(const float4*)&out[(size_t)(b0 + bb) * 192 + c4];
    }
    if (t < 128) {
        int bb = t >> 4, d = (t >> 3) & 1, g8 = (t & 7) << 2;
        *(float4*)&S->h[bb][d][g8] = make_float4(0.f, 0.f, 0.f, 0.f);
    }
    __syncthreads();

    {
        int combo = t & 63, grp = t >> 6;
        int kk = combo >> 4, j4 = (combo & 15) << 2;
        int bA = grp, bB = grp + 4;
        float4 bs = __ldg((const float4*)&b_proj[j4]);
        float4 a0 = bs, a1 = bs;
        #pragma unroll 4
        for (int i = 0; i < 129; i++) {
            float4 w = __ldg((const float4*)&W_proj[i * 64 + j4]);
            float x0 = S->nbr[bA][kk][i], x1 = S->nbr[bB][kk][i];
            a0.x += x0*w.x; a0.y += x0*w.y; a0.z += x0*w.z; a0.w += x0*w.w;
            a1.x += x1*w.x; a1.y += x1*w.y; a1.z += x1*w.z; a1.w += x1*w.w;
        }
        float m0 = mask[(b0 + bA) * 4 + kk], m1 = mask[(b0 + bB) * 4 + kk];
        a0.x = (a0.x > 0.f ? a0.x : 0.f) * m0; a0.y = (a0.y > 0.f ? a0.y : 0.f) * m0;
        a0.z = (a0.z > 0.f ? a0.z : 0.f) * m0; a0.w = (a0.w > 0.f ? a0.w : 0.f) * m0;
        a1.x = (a1.x > 0.f ? a1.x : 0.f) * m1; a1.y = (a1.y > 0.f ? a1.y : 0.f) * m1;
        a1.z = (a1.z > 0.f ? a1.z : 0.f) * m1; a1.w = (a1.w > 0.f ? a1.w : 0.f) * m1;
        *(float4*)&S->x[bA][kk][j4] = a0;
        *(float4*)&S->x[bB][kk][j4] = a1;
    }
    __syncthreads();

    if (t < 192) {
        int d = t / 96, r = t % 96, kk = r / 24, j4 = (r % 24) << 2;
        const float* Wih = d ? Wih_b : Wih_f;
        const float* bih = d ? bih_b : bih_f;
        float4 bs = __ldg((const float4*)&bih[j4]);
        float4 acc[8];
        #pragma unroll
        for (int bb = 0; bb < 8; bb++) acc[bb] = bs;
        for (int i = 0; i < 64; i++) {
            float4 w = __ldg((const float4*)&Wih[i * 96 + j4]);
            #pragma unroll
            for (int bb = 0; bb < 8; bb++) {
                float xv = S->x[bb][kk][i];
                acc[bb].x += xv*w.x; acc[bb].y += xv*w.y;
                acc[bb].z += xv*w.z; acc[bb].w += xv*w.w;
            }
        }
        #pragma unroll
        for (int bb = 0; bb < 8; bb++) *(float4*)&S->gi[bb][d][kk][j4] = acc[bb];
    }
    __syncthreads();

    for (int step = 0; step < 4; step++) {
        if (t < 192) {
            int combo = t % 48, grp = t / 48;
            int d = combo / 24, j4 = (combo % 24) << 2;
            int bA = grp, bB = grp + 4;
            const float* Whh = d ? Whh_b : Whh_f;
            const float* bhh = d ? bhh_b : bhh_f;
            float4 bs = __ldg((const float4*)&bhh[j4]);
            float4 a0 = bs, a1 = bs;
            #pragma unroll
            for (int i = 0; i < 32; i++) {
                float4 w = __ldg((const float4*)&Whh[i * 96 + j4]);
                float h0 = S->h[bA][d][i], h1 = S->h[bB][d][i];
                a0.x += h0*w.x; a0.y += h0*w.y; a0.z += h0*w.z; a0.w += h0*w.w;
                a1.x += h1*w.x; a1.y += h1*w.y; a1.z += h1*w.z; a1.w += h1*w.w;
            }
            *(float4*)&S->gh[bA][d][j4] = a0;
            *(float4*)&S->gh[bB][d][j4] = a1;
        }
        __syncthreads();
        {
            int bA = t >> 6, d = (t >> 5) & 1, g = t & 31;
            #pragma unroll
            for (int p = 0; p < 2; p++) {
                int bb = bA + p * 4;
                int kf = d ? (3 - step) : step;
                float r = sigmoid_fast(S->gi[bb][d][kf][g]      + S->gh[bb][d][g]);
                float z = sigmoid_fast(S->gi[bb][d][kf][32 + g] + S->gh[bb][d][32 + g]);
                float nn = tanh_fast(S->gi[bb][d][kf][64 + g] + r * S->gh[bb][d][64 + g]);
                S->h[bb][d][g] = (1.f - z) * nn + z * S->h[bb][d][g];
            }
        }
        __syncthreads();
    }

    for (int i = t; i < 512; i += 256) {
        int bb = i >> 6, r = i & 63;
        S->cat[bb][128 + r] = S->h[bb][r >> 5][r & 31];
    }
    __syncthreads();

    if (t < 128) {
        int bb = t >> 4, j4 = (t & 15) << 2;
        float4 acc = __ldg((const float4*)&b_out[j4]);
        #pragma unroll 4
        for (int i = 0; i < 192; i++) {
            float cv = S->cat[bb][i];
            float4 w = __ldg((const float4*)&W_out[i * 64 + j4]);
            acc.x += cv*w.x; acc.y += cv*w.y; acc.z += cv*w.z; acc.w += cv*w.w;
        }
        acc.x = acc.x > 0.f ? acc.x : 0.f;
        acc.y = acc.y > 0.f ? acc.y : 0.f;
        acc.z = acc.z > 0.f ? acc.z : 0.f;
        acc.w = acc.w > 0.f ? acc.w : 0.f;
        *(float4*)&out[(size_t)(b0 + bb) * 192 + 128 + j4] = acc;
    }
}

// ============================ launch ========================================
extern "C" void kernel_launch(void* const* d_in, const int* in_sizes, int n_in,
                              void* d_out, int out_size) {
    const float* self_f   = (const float*)d_in[0];
    const float* nbr_f    = (const float*)d_in[1];
    const float* mask     = (const float*)d_in[2];
    const float* dirs     = (const float*)d_in[3];
    const float* W_coop   = (const float*)d_in[4];
    const float* a_src_c  = (const float*)d_in[5];
    const float* a_dst_c  = (const float*)d_in[6];
    const float* W_conf   = (const float*)d_in[7];
    const float* a_src_f2 = (const float*)d_in[8];
    const float* a_dst_f2 = (const float*)d_in[9];
    const float* W_fuse   = (const float*)d_in[10];
    const float* b_fuse   = (const float*)d_in[11];
    const float* W_proj   = (const float*)d_in[12];
    const float* b_proj   = (const float*)d_in[13];
    const float* Wih_f    = (const float*)d_in[14];
    const float* Whh_f    = (const float*)d_in[15];
    const float* bih_f    = (const float*)d_in[16];
    const float* bhh_f    = (const float*)d_in[17];
    const float* Wih_b    = (const float*)d_in[18];
    const float* Whh_b    = (const float*)d_in[19];
    const float* bih_b    = (const float*)d_in[20];
    const float* bhh_b    = (const float*)d_in[21];
    const float* W_out    = (const float*)d_in[22];
    const float* b_out    = (const float*)d_in[23];
    float* out = (float*)d_out;

    cudaFuncSetAttribute(mgmq_gemm, cudaFuncAttributeMaxDynamicSharedMemorySize, SMEM_GEMM);
    cudaFuncSetAttribute(mgmq_k2, cudaFuncAttributeMaxDynamicSharedMemorySize, SMEM_K2);

    mgmq_wsplit<<<128, 256>>>(W_fuse);
    mgmq_k1<<<NODES, 128>>>(self_f, nbr_f, W_coop, a_src_c, a_dst_c,
                            W_conf, a_src_f2, a_dst_f2);
    mgmq_gemm<<<NTILES / TILES_PER_BLK, 384, SMEM_GEMM>>>(b_fuse, out);
    mgmq_k2<<<NB / 8, 256, SMEM_K2>>>(mask, dirs, W_proj, b_proj,
                                      Wih_f, Whh_f, bih_f, bhh_f,
                                      Wih_b, Whh_b, bih_b, bhh_b,
                                      W_out, b_out, out);
}

// round 8
// speedup vs baseline: 2.1877x; 1.2577x over previous
#include <cuda_runtime.h>
#include <cuda_bf16.h>
#include <cstdint>

// ---------------------------------------------------------------------------
// MGMQTorchModel R8:
//   k1 restructured: e-scores via precomputed Wa (= W @ a) -> no sWh smem,
//   no e-phase, 3 syncs, ~20KB smem (latency/occupancy fix).
//   gemm (ldmatrix, B-resident) and k2 unchanged.
// ---------------------------------------------------------------------------

#define NB 8192
#define NODES (NB*5)          // 40960
#define NTILES (NODES/8)      // 5120 M-tiles (8 nodes x 12 rows = 96)
#define TILES_PER_BLK 4

__device__ float g_nbr_emb[NB * 4 * 128];
__device__ __nv_bfloat16 g_catA_hi[(size_t)NTILES * 24576];
__device__ __nv_bfloat16 g_catA_lo[(size_t)NTILES * 24576];
__device__ __nv_bfloat16 g_WtT[2 * 32768];   // [term][n 128][k 256]
__device__ float g_Wa[64];                   // [s][src/dst][h][f]

__device__ __forceinline__ float tanh_fast(float x) {
    float y; asm("tanh.approx.f32 %0, %1;" : "=f"(y) : "f"(x)); return y;
}
__device__ __forceinline__ float sigmoid_fast(float x) {
    return 1.f / (1.f + __expf(-x));
}
__device__ __forceinline__ float elu_f(float x) {
    return (x > 0.f) ? x : (__expf(x) - 1.f);
}
__device__ __forceinline__ uint32_t smem_u32(const void* p) {
    uint32_t a;
    asm("{ .reg .u64 t; cvta.to.shared.u64 t, %1; cvt.u32.u64 %0, t; }" : "=r"(a) : "l"(p));
    return a;
}

__device__ __forceinline__ void mma16816(float* d, const uint32_t* a,
                                         uint32_t b0, uint32_t b1) {
    asm volatile(
        "mma.sync.aligned.m16n8k16.row.col.f32.bf16.bf16.f32 "
        "{%0,%1,%2,%3}, {%4,%5,%6,%7}, {%8,%9}, {%0,%1,%2,%3};"
        : "+f"(d[0]), "+f"(d[1]), "+f"(d[2]), "+f"(d[3])
        : "r"(a[0]), "r"(a[1]), "r"(a[2]), "r"(a[3]), "r"(b0), "r"(b1));
}
#define LDSM_X4(r, addr) \
    asm volatile("ldmatrix.sync.aligned.m8n8.x4.shared.b16 {%0,%1,%2,%3}, [%4];" \
        : "=r"((r)[0]), "=r"((r)[1]), "=r"((r)[2]), "=r"((r)[3]) : "r"(addr))

// ======================= setup: W_fuse -> Wt images + Wa ====================
__global__ void mgmq_wsplit(const float* __restrict__ W_fuse,
                            const float* __restrict__ W_coop,
                            const float* __restrict__ a_src_coop,
                            const float* __restrict__ a_dst_coop,
                            const float* __restrict__ W_conf,
                            const float* __restrict__ a_src_conf,
                            const float* __restrict__ a_dst_conf) {
    int idx = blockIdx.x * blockDim.x + threadIdx.x;
    if (blockIdx.x == 0 && threadIdx.x < 64) {
        int i = threadIdx.x;
        int s = i >> 5, v = (i >> 4) & 1, h = (i >> 2) & 3, f = i & 3;
        const float* W = s ? W_conf : W_coop;
        const float* a = s ? (v ? a_dst_conf : a_src_conf)
                           : (v ? a_dst_coop : a_src_coop);
        float acc = 0.f;
        #pragma unroll
        for (int o = 0; o < 32; o++)
            acc += __ldg(&W[(h * 4 + f) * 32 + o]) * __ldg(&a[h * 32 + o]);
        g_Wa[i] = acc;
    }
    if (idx >= 128 * 256) return;
    int n = idx >> 8;
    int k = idx & 255;
    float w = W_fuse[k * 128 + n];
    __nv_bfloat16 hi = __float2bfloat16(w);
    __nv_bfloat16 lo = __float2bfloat16(w - __bfloat162float(hi));
    g_WtT[n * 256 + k] = hi;
    g_WtT[32768 + n * 256 + k] = lo;
}

// ============================ KERNEL 1 (GAT) ================================
__global__ __launch_bounds__(128) void mgmq_k1(
    const float* __restrict__ self_f, const float* __restrict__ nbr_f,
    const float* __restrict__ W_coop, const float* __restrict__ W_conf)
{
    const int n = blockIdx.x;
    const int b = n / 5;
    const int slot = n - b * 5;
    const int t = threadIdx.x;

    __shared__ float sx[48];
    __shared__ float4 sAttC[4][12];      // coop: 3 atts + pad
    __shared__ float sAttF[4][12][12];   // conf: full rows
    __shared__ float sW[2][512];
    __shared__ float sCat[12][256];

    const float* xsrc = (slot == 0) ? (self_f + (size_t)b * 48)
                                    : (nbr_f + ((size_t)b * 4 + (slot - 1)) * 48);
    if (t < 48) sx[t] = xsrc[t];
    ((float4*)sW[0])[t] = __ldg(&((const float4*)W_coop)[t]);
    ((float4*)sW[1])[t] = __ldg(&((const float4*)W_conf)[t]);
    __syncthreads();

    // ---- softmax (t<96), no Wh needed: e = x . Wa ----
    if (t < 48) {
        // coop: valid j = own group of 3
        int h = t / 12, i = t - h * 12, j0 = (i / 3) * 3;
        float was0 = __ldg(&g_Wa[h * 4 + 0]),  was1 = __ldg(&g_Wa[h * 4 + 1]);
        float was2 = __ldg(&g_Wa[h * 4 + 2]),  was3 = __ldg(&g_Wa[h * 4 + 3]);
        float wad0 = __ldg(&g_Wa[16 + h * 4 + 0]), wad1 = __ldg(&g_Wa[16 + h * 4 + 1]);
        float wad2 = __ldg(&g_Wa[16 + h * 4 + 2]), wad3 = __ldg(&g_Wa[16 + h * 4 + 3]);
        float es = sx[i*4]*was0 + sx[i*4+1]*was1 + sx[i*4+2]*was2 + sx[i*4+3]*was3;
        float e[3];
        #pragma unroll
        for (int jj = 0; jj < 3; jj++) {
            int j = j0 + jj;
            float ed = sx[j*4]*wad0 + sx[j*4+1]*wad1 + sx[j*4+2]*wad2 + sx[j*4+3]*wad3;
            float v = es + ed;
            e[jj] = (v > 0.f) ? v : 0.2f * v;
        }
        float m = fmaxf(e[0], fmaxf(e[1], e[2]));
        float x0 = __expf(e[0] - m), x1 = __expf(e[1] - m), x2 = __expf(e[2] - m);
        float inv = 1.f / (x0 + x1 + x2);
        sAttC[h][i] = make_float4(x0 * inv, x1 * inv, x2 * inv, 0.f);
    } else if (t < 96) {
        // conf: valid j = 9 lanes outside own group
        int r = t - 48;
        int h = r / 12, i = r - h * 12;
        int gi = i / 3;
        float was0 = __ldg(&g_Wa[32 + h * 4 + 0]), was1 = __ldg(&g_Wa[32 + h * 4 + 1]);
        float was2 = __ldg(&g_Wa[32 + h * 4 + 2]), was3 = __ldg(&g_Wa[32 + h * 4 + 3]);
        float wad0 = __ldg(&g_Wa[48 + h * 4 + 0]), wad1 = __ldg(&g_Wa[48 + h * 4 + 1]);
        float wad2 = __ldg(&g_Wa[48 + h * 4 + 2]), wad3 = __ldg(&g_Wa[48 + h * 4 + 3]);
        float es = sx[i*4]*was0 + sx[i*4+1]*was1 + sx[i*4+2]*was2 + sx[i*4+3]*was3;
        float ev[12], m = -1e30f;
        #pragma unroll
        for (int j = 0; j < 12; j++) {
            float ed = sx[j*4]*wad0 + sx[j*4+1]*wad1 + sx[j*4+2]*wad2 + sx[j*4+3]*wad3;
            float e = es + ed;
            e = (e > 0.f) ? e : 0.2f * e;
            bool valid = ((j / 3) != gi);
            ev[j] = valid ? e : -1e30f;
            if (valid && e > m) m = e;
        }
        float sum = 0.f, ex[12];
        #pragma unroll
        for (int j = 0; j < 12; j++) {
            float v = (ev[j] > -1e29f) ? __expf(ev[j] - m) : 0.f;
            ex[j] = v; sum += v;
        }
        float inv = 1.f / sum;
        #pragma unroll
        for (int j = 0; j < 12; j++) sAttF[h][i][j] = ex[j] * inv;
    }

    // ---- all threads: Wh columns in registers (independent of softmax) ----
    const int o = t & 31, h = t >> 5;
    float wh0[12], wh1[12];
    {
        float w00 = sW[0][h * 128 +  0 + o], w01 = sW[0][h * 128 + 32 + o];
        float w02 = sW[0][h * 128 + 64 + o], w03 = sW[0][h * 128 + 96 + o];
        float w10 = sW[1][h * 128 +  0 + o], w11 = sW[1][h * 128 + 32 + o];
        float w12 = sW[1][h * 128 + 64 + o], w13 = sW[1][h * 128 + 96 + o];
        #pragma unroll
        for (int j = 0; j < 12; j++) {
            float x0 = sx[j*4], x1 = sx[j*4+1], x2 = sx[j*4+2], x3 = sx[j*4+3];
            wh0[j] = x0*w00 + x1*w01 + x2*w02 + x3*w03;
            wh1[j] = x0*w10 + x1*w11 + x2*w12 + x3*w13;
        }
    }
    __syncthreads();

    // ---- aggregation + elu -> sCat ----
    {
        #pragma unroll
        for (int i = 0; i < 12; i++) {
            const int j0 = (i / 3) * 3;
            float4 a = sAttC[h][i];
            float acc = a.x * wh0[j0] + a.y * wh0[j0 + 1] + a.z * wh0[j0 + 2];
            sCat[i][h * 32 + o] = elu_f(acc);
        }
        #pragma unroll
        for (int i = 0; i < 12; i++) {
            const int g0 = (i / 3) * 3;
            const float* ar = sAttF[h][i];
            float acc = 0.f;
            #pragma unroll
            for (int j = 0; j < 12; j++)
                if (j < g0 || j >= g0 + 3) acc += ar[j] * wh1[j];
            sCat[i][128 + h * 32 + o] = elu_f(acc);
        }
    }
    __syncthreads();

    // ---- write 12 cat rows as bf16 hi/lo, tight-packed tiles (M=96) ----
    const int tile = n >> 3;
    const int rbase = (n & 7) * 12;
    __nv_bfloat16* gH = g_catA_hi + (size_t)tile * 24576;
    __nv_bfloat16* gL = g_catA_lo + (size_t)tile * 24576;
    for (int seg = t; seg < 384; seg += 128) {
        int r = seg >> 5;
        int c8 = (seg & 31) << 3;
        float4 p0 = *(const float4*)&sCat[r][c8];
        float4 p1 = *(const float4*)&sCat[r][c8 + 4];
        float v[8] = {p0.x, p0.y, p0.z, p0.w, p1.x, p1.y, p1.z, p1.w};
        uint32_t hw[4], lw[4];
        #pragma unroll
        for (int j = 0; j < 4; j++) {
            __nv_bfloat16 h0 = __float2bfloat16(v[2*j]);
            __nv_bfloat16 h1 = __float2bfloat16(v[2*j+1]);
            float r0 = v[2*j]   - __bfloat162float(h0);
            float r1 = v[2*j+1] - __bfloat162float(h1);
            __nv_bfloat16 l0 = __float2bfloat16(r0);
            __nv_bfloat16 l1 = __float2bfloat16(r1);
            hw[j] = (uint32_t)__bfloat16_as_ushort(h0) | ((uint32_t)__bfloat16_as_ushort(h1) << 16);
            lw[j] = (uint32_t)__bfloat16_as_ushort(l0) | ((uint32_t)__bfloat16_as_ushort(l1) << 16);
        }
        size_t eoff = (size_t)(rbase + r) * 256 + c8;
        *(uint4*)(gH + eoff) = make_uint4(hw[0], hw[1], hw[2], hw[3]);
        *(uint4*)(gL + eoff) = make_uint4(lw[0], lw[1], lw[2], lw[3]);
    }
}

// ======================== GEMM kernel (mma.sync bf16) =======================
#define AH_OFF 0
#define AL_OFF 26112
#define B_OFF  52224
#define B_IMG  34816
#define SMEM_GEMM 191488
#define CH_RS 272

__global__ __launch_bounds__(384) void mgmq_gemm(
    const float* __restrict__ b_fuse,
    float* __restrict__ out)
{
    extern __shared__ char dsm[];
    __shared__ float sbias[128];

    const int t = threadIdx.x;
    const int wid = t >> 5;
    const int lid = t & 31;

    if (t < 128) sbias[t] = __ldg(&b_fuse[t]);

    {
        const uint4* gB = (const uint4*)g_WtT;
        for (int i = t; i < 8192; i += 384) {
            int img = i >> 11;
            int r = i & 2047;
            int nr = r >> 4, c16 = r & 15;
            int term = img >> 1, kc = img & 1;
            *(uint4*)(dsm + B_OFF + img * B_IMG + nr * CH_RS + c16 * 16)
                = gB[term * 4096 + nr * 32 + kc * 16 + c16];
        }
    }

    const int mtile = wid >> 1;
    const int nhalf = wid & 1;
    const int g = lid >> 2;
    const int q = lid & 3;
    const int row0 = mtile * 16 + g;
    const int row1 = row0 + 8;

    const uint32_t sbase = smem_u32(dsm);
    const uint32_t a_lane = (uint32_t)((mtile * 16 + ((lid >> 3) & 1) * 8 + (lid & 7)) * CH_RS
                          + ((lid >> 4) & 1) * 16);
    const uint32_t b_lane = (uint32_t)((nhalf * 64 + ((lid >> 4) & 1) * 8 + (lid & 7)) * CH_RS
                          + ((lid >> 3) & 1) * 16);

    for (int tt = 0; tt < TILES_PER_BLK; tt++) {
        const int tile = blockIdx.x * TILES_PER_BLK + tt;
        const uint4* gAH = (const uint4*)(g_catA_hi + (size_t)tile * 24576);
        const uint4* gAL = (const uint4*)(g_catA_lo + (size_t)tile * 24576);

        float d[8][4];
        #pragma unroll
        for (int nt = 0; nt < 8; nt++) {
            d[nt][0] = 0.f; d[nt][1] = 0.f; d[nt][2] = 0.f; d[nt][3] = 0.f;
        }

        #pragma unroll
        for (int kc = 0; kc < 2; kc++) {
            __syncthreads();
            for (int i = t; i < 1536; i += 384) {
                int row = i >> 4, c16 = i & 15;
                *(uint4*)(dsm + AH_OFF + row * CH_RS + c16 * 16) = gAH[row * 32 + kc * 16 + c16];
                *(uint4*)(dsm + AL_OFF + row * CH_RS + c16 * 16) = gAL[row * 32 + kc * 16 + c16];
            }
            __syncthreads();

            const uint32_t aHb = sbase + AH_OFF + a_lane;
            const uint32_t aLb = sbase + AL_OFF + a_lane;
            const uint32_t bHb = sbase + B_OFF + kc * B_IMG + b_lane;
            const uint32_t bLb = sbase + B_OFF + 2 * B_IMG + kc * B_IMG + b_lane;

            #pragma unroll
            for (int ks = 0; ks < 8; ks++) {
                const uint32_t koff = ks * 32;
                uint32_t ah[4], al[4];
                LDSM_X4(ah, aHb + koff);
                LDSM_X4(al, aLb + koff);
                #pragma unroll
                for (int p = 0; p < 4; p++) {
                    uint32_t bh[4], bl[4];
                    LDSM_X4(bh, bHb + p * (16 * CH_RS) + koff);
                    LDSM_X4(bl, bLb + p * (16 * CH_RS) + koff);
                    mma16816(d[2*p],     ah, bh[0], bh[1]);
                    mma16816(d[2*p],     ah, bl[0], bl[1]);
                    mma16816(d[2*p],     al, bh[0], bh[1]);
                    mma16816(d[2*p + 1], ah, bh[2], bh[3]);
                    mma16816(d[2*p + 1], ah, bl[2], bl[3]);
                    mma16816(d[2*p + 1], al, bh[2], bh[3]);
                }
            }
        }
        __syncthreads();

        float* Dbuf = (float*)dsm;
        #pragma unroll
        for (int nt = 0; nt < 8; nt++) {
            int c0 = nhalf * 64 + nt * 8 + q * 2;
            float b0 = sbias[c0], b1 = sbias[c0 + 1];
            float2 v0 = make_float2(elu_f(d[nt][0] + b0), elu_f(d[nt][1] + b1));
            float2 v1 = make_float2(elu_f(d[nt][2] + b0), elu_f(d[nt][3] + b1));
            *(float2*)&Dbuf[row0 * 132 + c0] = v0;
            *(float2*)&Dbuf[row1 * 132 + c0] = v1;
        }
        __syncthreads();

        if (t < 256) {
            int nl = t >> 5;
            int c4 = (t & 31) << 2;
            float4 s = make_float4(0.f, 0.f, 0.f, 0.f);
            #pragma unroll
            for (int j = 0; j < 12; j++) {
                float4 v = *(const float4*)&Dbuf[(nl * 12 + j) * 132 + c4];
                s.x += v.x; s.y += v.y; s.z += v.z; s.w += v.w;
            }
            s.x *= (1.f/12.f); s.y *= (1.f/12.f); s.z *= (1.f/12.f); s.w *= (1.f/12.f);
            int node = tile * 8 + nl;
            int b = node / 5, slot = node - b * 5;
            if (slot == 0) *(float4*)&out[(size_t)b * 192 + c4] = s;
            else *(float4*)&g_nbr_emb[((size_t)b * 4 + (slot - 1)) * 128 + c4] = s;
        }
    }
}

// ============================ KERNEL 2 ======================================
struct K2Smem {
    float nbr[8][4][132];
    float x[8][4][64];
    float gi[8][2][4][96];
    float gh[8][2][96];
    float h[8][2][32];
    float cat[8][192];
};
#define SMEM_K2 ((int)sizeof(K2Smem))

__global__ __launch_bounds__(256) void mgmq_k2(
    const float* __restrict__ mask, const float* __restrict__ dirs,
    const float* __restrict__ W_proj, const float* __restrict__ b_proj,
    const float* __restrict__ Wih_f, const float* __restrict__ Whh_f,
    const float* __restrict__ bih_f, const float* __restrict__ bhh_f,
    const float* __restrict__ Wih_b, const float* __restrict__ Whh_b,
    const float* __restrict__ bih_b, const float* __restrict__ bhh_b,
    const float* __restrict__ W_out, const float* __restrict__ b_out,
    float* __restrict__ out)
{
    extern __shared__ char k2dsm[];
    K2Smem* S = (K2Smem*)k2dsm;
    const int b0 = blockIdx.x * 8;
    const int t = threadIdx.x;

    for (int i = t; i < 1024; i += 256) {
        int bb = i >> 7, kk = (i >> 5) & 3, c4 = (i & 31) << 2;
        *(float4*)&S->nbr[bb][kk][c4] =
            *(const float4*)&g_nbr_emb[(((size_t)(b0 + bb)) * 4 + kk) * 128 + c4];
    }
    if (t < 32) S->nbr[t >> 2][t & 3][128] = dirs[(b0 + (t >> 2)) * 4 + (t & 3)];
    {
        int bb = t >> 5, c4 = (t & 31) << 2;
        *(float4*)&S->cat[bb][c4] = *(const float4*)&out[(size_t)(b0 + bb) * 192 + c4];
    }
    if (t < 128) {
        int bb = t >> 4, d = (t >> 3) & 1, g8 = (t & 7) << 2;
        *(float4*)&S->h[bb][d][g8] = make_float4(0.f, 0.f, 0.f, 0.f);
    }
    __syncthreads();

    {
        int combo = t & 63, grp = t >> 6;
        int kk = combo >> 4, j4 = (combo & 15) << 2;
        int bA = grp, bB = grp + 4;
        float4 bs = __ldg((const float4*)&b_proj[j4]);
        float4 a0 = bs, a1 = bs;
        #pragma unroll 4
        for (int i = 0; i < 129; i++) {
            float4 w = __ldg((const float4*)&W_proj[i * 64 + j4]);
            float x0 = S->nbr[bA][kk][i], x1 = S->nbr[bB][kk][i];
            a0.x += x0*w.x; a0.y += x0*w.y; a0.z += x0*w.z; a0.w += x0*w.w;
            a1.x += x1*w.x; a1.y += x1*w.y; a1.z += x1*w.z; a1.w += x1*w.w;
        }
        float m0 = mask[(b0 + bA) * 4 + kk], m1 = mask[(b0 + bB) * 4 + kk];
        a0.x = (a0.x > 0.f ? a0.x : 0.f) * m0; a0.y = (a0.y > 0.f ? a0.y : 0.f) * m0;
        a0.z = (a0.z > 0.f ? a0.z : 0.f) * m0; a0.w = (a0.w > 0.f ? a0.w : 0.f) * m0;
        a1.x = (a1.x > 0.f ? a1.x : 0.f) * m1; a1.y = (a1.y > 0.f ? a1.y : 0.f) * m1;
        a1.z = (a1.z > 0.f ? a1.z : 0.f) * m1; a1.w = (a1.w > 0.f ? a1.w : 0.f) * m1;
        *(float4*)&S->x[bA][kk][j4] = a0;
        *(float4*)&S->x[bB][kk][j4] = a1;
    }
    __syncthreads();

    if (t < 192) {
        int d = t / 96, r = t % 96, kk = r / 24, j4 = (r % 24) << 2;
        const float* Wih = d ? Wih_b : Wih_f;
        const float* bih = d ? bih_b : bih_f;
        float4 bs = __ldg((const float4*)&bih[j4]);
        float4 acc[8];
        #pragma unroll
        for (int bb = 0; bb < 8; bb++) acc[bb] = bs;
        for (int i = 0; i < 64; i++) {
            float4 w = __ldg((const float4*)&Wih[i * 96 + j4]);
            #pragma unroll
            for (int bb = 0; bb < 8; bb++) {
                float xv = S->x[bb][kk][i];
                acc[bb].x += xv*w.x; acc[bb].y += xv*w.y;
                acc[bb].z += xv*w.z; acc[bb].w += xv*w.w;
            }
        }
        #pragma unroll
        for (int bb = 0; bb < 8; bb++) *(float4*)&S->gi[bb][d][kk][j4] = acc[bb];
    }
    __syncthreads();

    for (int step = 0; step < 4; step++) {
        if (t < 192) {
            int combo = t % 48, grp = t / 48;
            int d = combo / 24, j4 = (combo % 24) << 2;
            int bA = grp, bB = grp + 4;
            const float* Whh = d ? Whh_b : Whh_f;
            const float* bhh = d ? bhh_b : bhh_f;
            float4 bs = __ldg((const float4*)&bhh[j4]);
            float4 a0 = bs, a1 = bs;
            #pragma unroll
            for (int i = 0; i < 32; i++) {
                float4 w = __ldg((const float4*)&Whh[i * 96 + j4]);
                float h0 = S->h[bA][d][i], h1 = S->h[bB][d][i];
                a0.x += h0*w.x; a0.y += h0*w.y; a0.z += h0*w.z; a0.w += h0*w.w;
                a1.x += h1*w.x; a1.y += h1*w.y; a1.z += h1*w.z; a1.w += h1*w.w;
            }
            *(float4*)&S->gh[bA][d][j4] = a0;
            *(float4*)&S->gh[bB][d][j4] = a1;
        }
        __syncthreads();
        {
            int bA = t >> 6, d = (t >> 5) & 1, g = t & 31;
            #pragma unroll
            for (int p = 0; p < 2; p++) {
                int bb = bA + p * 4;
                int kf = d ? (3 - step) : step;
                float r = sigmoid_fast(S->gi[bb][d][kf][g]      + S->gh[bb][d][g]);
                float z = sigmoid_fast(S->gi[bb][d][kf][32 + g] + S->gh[bb][d][32 + g]);
                float nn = tanh_fast(S->gi[bb][d][kf][64 + g] + r * S->gh[bb][d][64 + g]);
                S->h[bb][d][g] = (1.f - z) * nn + z * S->h[bb][d][g];
            }
        }
        __syncthreads();
    }

    for (int i = t; i < 512; i += 256) {
        int bb = i >> 6, r = i & 63;
        S->cat[bb][128 + r] = S->h[bb][r >> 5][r & 31];
    }
    __syncthreads();

    if (t < 128) {
        int bb = t >> 4, j4 = (t & 15) << 2;
        float4 acc = __ldg((const float4*)&b_out[j4]);
        #pragma unroll 4
        for (int i = 0; i < 192; i++) {
            float cv = S->cat[bb][i];
            float4 w = __ldg((const float4*)&W_out[i * 64 + j4]);
            acc.x += cv*w.x; acc.y += cv*w.y; acc.z += cv*w.z; acc.w += cv*w.w;
        }
        acc.x = acc.x > 0.f ? acc.x : 0.f;
        acc.y = acc.y > 0.f ? acc.y : 0.f;
        acc.z = acc.z > 0.f ? acc.z : 0.f;
        acc.w = acc.w > 0.f ? acc.w : 0.f;
        *(float4*)&out[(size_t)(b0 + bb) * 192 + 128 + j4] = acc;
    }
}

// ============================ launch ========================================
extern "C" void kernel_launch(void* const* d_in, const int* in_sizes, int n_in,
                              void* d_out, int out_size) {
    const float* self_f   = (const float*)d_in[0];
    const float* nbr_f    = (const float*)d_in[1];
    const float* mask     = (const float*)d_in[2];
    const float* dirs     = (const float*)d_in[3];
    const float* W_coop   = (const float*)d_in[4];
    const float* a_src_c  = (const float*)d_in[5];
    const float* a_dst_c  = (const float*)d_in[6];
    const float* W_conf   = (const float*)d_in[7];
    const float* a_src_f2 = (const float*)d_in[8];
    const float* a_dst_f2 = (const float*)d_in[9];
    const float* W_fuse   = (const float*)d_in[10];
    const float* b_fuse   = (const float*)d_in[11];
    const float* W_proj   = (const float*)d_in[12];
    const float* b_proj   = (const float*)d_in[13];
    const float* Wih_f    = (const float*)d_in[14];
    const float* Whh_f    = (const float*)d_in[15];
    const float* bih_f    = (const float*)d_in[16];
    const float* bhh_f    = (const float*)d_in[17];
    const float* Wih_b    = (const float*)d_in[18];
    const float* Whh_b    = (const float*)d_in[19];
    const float* bih_b    = (const float*)d_in[20];
    const float* bhh_b    = (const float*)d_in[21];
    const float* W_out    = (const float*)d_in[22];
    const float* b_out    = (const float*)d_in[23];
    float* out = (float*)d_out;

    cudaFuncSetAttribute(mgmq_gemm, cudaFuncAttributeMaxDynamicSharedMemorySize, SMEM_GEMM);
    cudaFuncSetAttribute(mgmq_k2, cudaFuncAttributeMaxDynamicSharedMemorySize, SMEM_K2);

    mgmq_wsplit<<<128, 256>>>(W_fuse, W_coop, a_src_c, a_dst_c,
                              W_conf, a_src_f2, a_dst_f2);
    mgmq_k1<<<NODES, 128>>>(self_f, nbr_f, W_coop, W_conf);
    mgmq_gemm<<<NTILES / TILES_PER_BLK, 384, SMEM_GEMM>>>(b_fuse, out);
    mgmq_k2<<<NB / 8, 256, SMEM_K2>>>(mask, dirs, W_proj, b_proj,
                                      Wih_f, Whh_f, bih_f, bhh_f,
                                      Wih_b, Whh_b, bih_b, bhh_b,
                                      W_out, b_out, out);
}

// round 11
// speedup vs baseline: 2.3713x; 1.0839x over previous
#include <cuda_runtime.h>
#include <cuda_bf16.h>
#include <cstdint>

// ---------------------------------------------------------------------------
// MGMQTorchModel R11 (= R10 with per-head attention indexing fixed):
//   fused : GAT (8 nodes) -> pack bf16 hi/lo into smem A images -> HMMA GEMM
//           -> bias+elu+mean -> scatter.  One 512-thread block per M-tile.
//   wsplit: W_fuse -> Wt images + Wa precompute.   k2 unchanged.
// ---------------------------------------------------------------------------

#define NB 8192
#define NODES (NB*5)          // 40960
#define NTILES (NODES/8)      // 5120 (8 nodes x 12 rows = M 96)

__device__ float g_nbr_emb[NB * 4 * 128];
__device__ __nv_bfloat16 g_WtT[2 * 32768];   // [term][n 128][k 256]
__device__ float g_Wa[64];                   // [s][src/dst][h][f]

__device__ __forceinline__ float tanh_fast(float x) {
    float y; asm("tanh.approx.f32 %0, %1;" : "=f"(y) : "f"(x)); return y;
}
__device__ __forceinline__ float sigmoid_fast(float x) {
    return 1.f / (1.f + __expf(-x));
}
__device__ __forceinline__ float elu_f(float x) {
    return (x > 0.f) ? x : (__expf(x) - 1.f);
}
__device__ __forceinline__ uint32_t smem_u32(const void* p) {
    uint32_t a;
    asm("{ .reg .u64 t; cvta.to.shared.u64 t, %1; cvt.u32.u64 %0, t; }" : "=r"(a) : "l"(p));
    return a;
}
__device__ __forceinline__ void mma16816(float* d, const uint32_t* a,
                                         uint32_t b0, uint32_t b1) {
    asm volatile(
        "mma.sync.aligned.m16n8k16.row.col.f32.bf16.bf16.f32 "
        "{%0,%1,%2,%3}, {%4,%5,%6,%7}, {%8,%9}, {%0,%1,%2,%3};"
        : "+f"(d[0]), "+f"(d[1]), "+f"(d[2]), "+f"(d[3])
        : "r"(a[0]), "r"(a[1]), "r"(a[2]), "r"(a[3]), "r"(b0), "r"(b1));
}
#define LDSM_X4(r, addr) \
    asm volatile("ldmatrix.sync.aligned.m8n8.x4.shared.b16 {%0,%1,%2,%3}, [%4];" \
        : "=r"((r)[0]), "=r"((r)[1]), "=r"((r)[2]), "=r"((r)[3]) : "r"(addr))

// ======================= setup: W_fuse -> Wt images + Wa ====================
__global__ void mgmq_wsplit(const float* __restrict__ W_fuse,
                            const float* __restrict__ W_coop,
                            const float* __restrict__ a_src_coop,
                            const float* __restrict__ a_dst_coop,
                            const float* __restrict__ W_conf,
                            const float* __restrict__ a_src_conf,
                            const float* __restrict__ a_dst_conf) {
    int idx = blockIdx.x * blockDim.x + threadIdx.x;
    if (blockIdx.x == 0 && threadIdx.x < 64) {
        int i = threadIdx.x;
        int s = i >> 5, v = (i >> 4) & 1, h = (i >> 2) & 3, f = i & 3;
        const float* W = s ? W_conf : W_coop;
        const float* a = s ? (v ? a_dst_conf : a_src_conf)
                           : (v ? a_dst_coop : a_src_coop);
        float acc = 0.f;
        #pragma unroll
        for (int o = 0; o < 32; o++)
            acc += __ldg(&W[(h * 4 + f) * 32 + o]) * __ldg(&a[h * 32 + o]);
        g_Wa[i] = acc;
    }
    if (idx >= 128 * 256) return;
    int n = idx >> 8;
    int k = idx & 255;
    float w = W_fuse[k * 128 + n];
    __nv_bfloat16 hi = __float2bfloat16(w);
    __nv_bfloat16 lo = __float2bfloat16(w - __bfloat162float(hi));
    g_WtT[n * 256 + k] = hi;
    g_WtT[32768 + n * 256 + k] = lo;
}

// ======================== FUSED kernel ======================================
// smem layout (dynamic):
//   Ahi [96][528B]  @0        (50688)
//   Alo             @50688    (50688)                 -> 101376
//   X region        @101376   (69632):  B hi/lo chunk (2x34816)
//                                        | sCatX f32 [4][12][256] (49152)
//                                        | Dbuf f32 [96][132] (50688)
//   sW  2x512 f32   @171008   (4096)
//   sx  8x48 f32    @175104   (1536)
//   AttC [4][4][12]f4 @176640 (3072)
//   AttF [4][4][12][12] @179712 (9216)
//   bias 128 f32    @188928   (512)     total 189440
#define A_RS    528
#define AHI_OFF 0
#define ALO_OFF 50688
#define X_OFF   101376
#define B_IMG   34816
#define SW_OFF  171008
#define SX_OFF  175104
#define ATTC_OFF 176640
#define ATTF_OFF 179712
#define BIAS_OFF 188928
#define SMEM_FUSED 189440
#define CH_RS   272

__global__ __launch_bounds__(512) void mgmq_fused(
    const float* __restrict__ self_f, const float* __restrict__ nbr_f,
    const float* __restrict__ W_coop, const float* __restrict__ W_conf,
    const float* __restrict__ b_fuse, float* __restrict__ out)
{
    extern __shared__ char dsm[];
    float* sW   = (float*)(dsm + SW_OFF);
    float* sx   = (float*)(dsm + SX_OFF);
    float4* sAttC = (float4*)(dsm + ATTC_OFF);   // [(nl*4 + h)*12 + i]
    float*  sAttF = (float*)(dsm + ATTF_OFF);    // [((nl*4 + h)*12 + i)*12 + j]
    float* sbias = (float*)(dsm + BIAS_OFF);
    float* sCatX = (float*)(dsm + X_OFF);        // [nl][i][c] = nl*3072+i*256+c

    const int t = threadIdx.x;
    const int wid = t >> 5;
    const int lid = t & 31;
    const int tile = blockIdx.x;

    // ---- stage weights, bias, and 8 nodes' features ----
    if (t < 128) ((float4*)sW)[t] = __ldg(&((const float4*)W_coop)[t]);
    else if (t < 256) ((float4*)sW)[t] = __ldg(&((const float4*)W_conf)[t - 128]);
    if (t >= 384) sbias[t - 384] = __ldg(&b_fuse[t - 384]);
    if (t < 384) {
        int n8 = t / 48, f = t % 48;
        int node = tile * 8 + n8;
        int b = node / 5, slot = node - b * 5;
        const float* xsrc = (slot == 0) ? (self_f + (size_t)b * 48)
                                        : (nbr_f + ((size_t)b * 4 + (slot - 1)) * 48);
        sx[n8 * 48 + f] = __ldg(&xsrc[f]);
    }
    __syncthreads();

    // ==================== GAT: 2 passes of 4 nodes =========================
    #pragma unroll
    for (int p = 0; p < 2; p++) {
        const int nl = t >> 7;          // 0..3
        const int tt = t & 127;
        const int n8 = p * 4 + nl;
        const float* nx = sx + n8 * 48;

        // ---- softmax (tt<96), per-head slots ----
        if (tt < 48) {
            int h = tt / 12, i = tt - h * 12, j0 = (i / 3) * 3;
            float was0 = __ldg(&g_Wa[h*4+0]), was1 = __ldg(&g_Wa[h*4+1]);
            float was2 = __ldg(&g_Wa[h*4+2]), was3 = __ldg(&g_Wa[h*4+3]);
            float wad0 = __ldg(&g_Wa[16+h*4+0]), wad1 = __ldg(&g_Wa[16+h*4+1]);
            float wad2 = __ldg(&g_Wa[16+h*4+2]), wad3 = __ldg(&g_Wa[16+h*4+3]);
            float es = nx[i*4]*was0 + nx[i*4+1]*was1 + nx[i*4+2]*was2 + nx[i*4+3]*was3;
            float e[3];
            #pragma unroll
            for (int jj = 0; jj < 3; jj++) {
                int j = j0 + jj;
                float ed = nx[j*4]*wad0 + nx[j*4+1]*wad1 + nx[j*4+2]*wad2 + nx[j*4+3]*wad3;
                float v = es + ed;
                e[jj] = (v > 0.f) ? v : 0.2f * v;
            }
            float m = fmaxf(e[0], fmaxf(e[1], e[2]));
            float x0 = __expf(e[0]-m), x1 = __expf(e[1]-m), x2 = __expf(e[2]-m);
            float inv = 1.f / (x0 + x1 + x2);
            sAttC[(nl * 4 + h) * 12 + i] = make_float4(x0*inv, x1*inv, x2*inv, 0.f);
        } else if (tt < 96) {
            int r = tt - 48;
            int h = r / 12, i = r - h * 12;
            int gi = i / 3;
            float was0 = __ldg(&g_Wa[32+h*4+0]), was1 = __ldg(&g_Wa[32+h*4+1]);
            float was2 = __ldg(&g_Wa[32+h*4+2]), was3 = __ldg(&g_Wa[32+h*4+3]);
            float wad0 = __ldg(&g_Wa[48+h*4+0]), wad1 = __ldg(&g_Wa[48+h*4+1]);
            float wad2 = __ldg(&g_Wa[48+h*4+2]), wad3 = __ldg(&g_Wa[48+h*4+3]);
            float es = nx[i*4]*was0 + nx[i*4+1]*was1 + nx[i*4+2]*was2 + nx[i*4+3]*was3;
            float ev[12], m = -1e30f;
            #pragma unroll
            for (int j = 0; j < 12; j++) {
                float ed = nx[j*4]*wad0 + nx[j*4+1]*wad1 + nx[j*4+2]*wad2 + nx[j*4+3]*wad3;
                float e = es + ed;
                e = (e > 0.f) ? e : 0.2f * e;
                bool valid = ((j / 3) != gi);
                ev[j] = valid ? e : -1e30f;
                if (valid && e > m) m = e;
            }
            float sum = 0.f, ex[12];
            #pragma unroll
            for (int j = 0; j < 12; j++) {
                float v = (ev[j] > -1e29f) ? __expf(ev[j] - m) : 0.f;
                ex[j] = v; sum += v;
            }
            float inv = 1.f / sum;
            #pragma unroll
            for (int j = 0; j < 12; j++)
                sAttF[((nl * 4 + h) * 12 + i) * 12 + j] = ex[j] * inv;
        }

        // ---- Wh columns in registers ----
        const int o = tt & 31, h = tt >> 5;
        float wh0[12], wh1[12];
        {
            float w00 = sW[h*128 +  0 + o], w01 = sW[h*128 + 32 + o];
            float w02 = sW[h*128 + 64 + o], w03 = sW[h*128 + 96 + o];
            float w10 = sW[512 + h*128 +  0 + o], w11 = sW[512 + h*128 + 32 + o];
            float w12 = sW[512 + h*128 + 64 + o], w13 = sW[512 + h*128 + 96 + o];
            #pragma unroll
            for (int j = 0; j < 12; j++) {
                float x0 = nx[j*4], x1 = nx[j*4+1], x2 = nx[j*4+2], x3 = nx[j*4+3];
                wh0[j] = x0*w00 + x1*w01 + x2*w02 + x3*w03;
                wh1[j] = x0*w10 + x1*w11 + x2*w12 + x3*w13;
            }
        }
        __syncthreads();

        // ---- aggregation + elu -> sCatX[nl][i][c] ----
        {
            float* catn = sCatX + nl * 3072;
            #pragma unroll
            for (int i = 0; i < 12; i++) {
                const int j0 = (i / 3) * 3;
                float4 a = sAttC[(nl * 4 + h) * 12 + i];
                float acc = a.x * wh0[j0] + a.y * wh0[j0+1] + a.z * wh0[j0+2];
                catn[i * 256 + h * 32 + o] = elu_f(acc);
            }
            #pragma unroll
            for (int i = 0; i < 12; i++) {
                const int g0 = (i / 3) * 3;
                const float* ar = sAttF + ((nl * 4 + h) * 12 + i) * 12;
                float acc = 0.f;
                #pragma unroll
                for (int j = 0; j < 12; j++)
                    if (j < g0 || j >= g0 + 3) acc += ar[j] * wh1[j];
                catn[i * 256 + 128 + h * 32 + o] = elu_f(acc);
            }
        }
        __syncthreads();

        // ---- pack 4 nodes into A images (bf16 hi/lo) ----
        for (int item = t; item < 1536; item += 512) {
            int pnl = item / 384;
            int rr = (item % 384) >> 5;
            int c8 = (item & 31) << 3;
            const float* src = sCatX + pnl * 3072 + rr * 256 + c8;
            float4 p0 = *(const float4*)src;
            float4 p1 = *(const float4*)(src + 4);
            float v[8] = {p0.x, p0.y, p0.z, p0.w, p1.x, p1.y, p1.z, p1.w};
            uint32_t hw[4], lw[4];
            #pragma unroll
            for (int j = 0; j < 4; j++) {
                __nv_bfloat16 h0 = __float2bfloat16(v[2*j]);
                __nv_bfloat16 h1 = __float2bfloat16(v[2*j+1]);
                float r0 = v[2*j]   - __bfloat162float(h0);
                float r1 = v[2*j+1] - __bfloat162float(h1);
                __nv_bfloat16 l0 = __float2bfloat16(r0);
                __nv_bfloat16 l1 = __float2bfloat16(r1);
                hw[j] = (uint32_t)__bfloat16_as_ushort(h0) | ((uint32_t)__bfloat16_as_ushort(h1) << 16);
                lw[j] = (uint32_t)__bfloat16_as_ushort(l0) | ((uint32_t)__bfloat16_as_ushort(l1) << 16);
            }
            int row = (p * 4 + pnl) * 12 + rr;
            uint32_t boff = (uint32_t)row * A_RS + (uint32_t)c8 * 2;
            *(uint4*)(dsm + AHI_OFF + boff) = make_uint4(hw[0], hw[1], hw[2], hw[3]);
            *(uint4*)(dsm + ALO_OFF + boff) = make_uint4(lw[0], lw[1], lw[2], lw[3]);
        }
        __syncthreads();
    }

    // ==================== GEMM ==============================================
    const int mtile = wid >> 1;
    const int nhalf = wid & 1;
    const int g = lid >> 2;
    const int q = lid & 3;
    const int row0 = mtile * 16 + g;
    const int row1 = row0 + 8;
    const bool mma_w = (wid < 12);

    const uint32_t sbase = smem_u32(dsm);
    const uint32_t a_lane = (uint32_t)((mtile * 16 + ((lid >> 3) & 1) * 8 + (lid & 7)) * A_RS
                          + ((lid >> 4) & 1) * 16);
    const uint32_t b_lane = (uint32_t)((nhalf * 64 + ((lid >> 4) & 1) * 8 + (lid & 7)) * CH_RS
                          + ((lid >> 3) & 1) * 16);

    float d[8][4];
    #pragma unroll
    for (int nt = 0; nt < 8; nt++) {
        d[nt][0] = 0.f; d[nt][1] = 0.f; d[nt][2] = 0.f; d[nt][3] = 0.f;
    }

    const uint4* gBH = (const uint4*)g_WtT;
    const uint4* gBL = (const uint4*)(g_WtT + 32768);

    #pragma unroll
    for (int kc = 0; kc < 2; kc++) {
        // load B chunk (both terms) into X region
        for (int i = t; i < 4096; i += 512) {
            int term = i >> 11;
            int r = i & 2047;
            int nr = r >> 4, c16 = r & 15;
            const uint4* gB = term ? gBL : gBH;
            *(uint4*)(dsm + X_OFF + term * B_IMG + nr * CH_RS + c16 * 16)
                = gB[nr * 32 + kc * 16 + c16];
        }
        __syncthreads();

        if (mma_w) {
            const uint32_t aHb = sbase + AHI_OFF + a_lane + kc * 256;
            const uint32_t aLb = sbase + ALO_OFF + a_lane + kc * 256;
            const uint32_t bHb = sbase + X_OFF + b_lane;
            const uint32_t bLb = sbase + X_OFF + B_IMG + b_lane;

            #pragma unroll
            for (int ks = 0; ks < 8; ks++) {
                const uint32_t koff = ks * 32;
                uint32_t ah[4], al[4];
                LDSM_X4(ah, aHb + koff);
                LDSM_X4(al, aLb + koff);
                #pragma unroll
                for (int pp = 0; pp < 4; pp++) {
                    uint32_t bh[4], bl[4];
                    LDSM_X4(bh, bHb + pp * (16 * CH_RS) + koff);
                    LDSM_X4(bl, bLb + pp * (16 * CH_RS) + koff);
                    mma16816(d[2*pp],     ah, bh[0], bh[1]);
                    mma16816(d[2*pp],     ah, bl[0], bl[1]);
                    mma16816(d[2*pp],     al, bh[0], bh[1]);
                    mma16816(d[2*pp + 1], ah, bh[2], bh[3]);
                    mma16816(d[2*pp + 1], ah, bl[2], bl[3]);
                    mma16816(d[2*pp + 1], al, bh[2], bh[3]);
                }
            }
        }
        __syncthreads();
    }

    // ---- epilogue: elu(D+bias) -> Dbuf (X region), then 12-row mean ----
    float* Dbuf = (float*)(dsm + X_OFF);
    if (mma_w) {
        #pragma unroll
        for (int nt = 0; nt < 8; nt++) {
            int c0 = nhalf * 64 + nt * 8 + q * 2;
            float b0 = sbias[c0], b1 = sbias[c0 + 1];
            float2 v0 = make_float2(elu_f(d[nt][0] + b0), elu_f(d[nt][1] + b1));
            float2 v1 = make_float2(elu_f(d[nt][2] + b0), elu_f(d[nt][3] + b1));
            *(float2*)&Dbuf[row0 * 132 + c0] = v0;
            *(float2*)&Dbuf[row1 * 132 + c0] = v1;
        }
    }
    __syncthreads();

    if (t < 256) {
        int nl8 = t >> 5;
        int c4 = (t & 31) << 2;
        float4 s = make_float4(0.f, 0.f, 0.f, 0.f);
        #pragma unroll
        for (int j = 0; j < 12; j++) {
            float4 v = *(const float4*)&Dbuf[(nl8 * 12 + j) * 132 + c4];
            s.x += v.x; s.y += v.y; s.z += v.z; s.w += v.w;
        }
        s.x *= (1.f/12.f); s.y *= (1.f/12.f); s.z *= (1.f/12.f); s.w *= (1.f/12.f);
        int node = tile * 8 + nl8;
        int b = node / 5, slot = node - b * 5;
        if (slot == 0) *(float4*)&out[(size_t)b * 192 + c4] = s;
        else *(float4*)&g_nbr_emb[((size_t)b * 4 + (slot - 1)) * 128 + c4] = s;
    }
}

// ============================ KERNEL 2 ======================================
struct K2Smem {
    float nbr[8][4][132];
    float x[8][4][64];
    float gi[8][2][4][96];
    float gh[8][2][96];
    float h[8][2][32];
    float cat[8][192];
};
#define SMEM_K2 ((int)sizeof(K2Smem))

__global__ __launch_bounds__(256) void mgmq_k2(
    const float* __restrict__ mask, const float* __restrict__ dirs,
    const float* __restrict__ W_proj, const float* __restrict__ b_proj,
    const float* __restrict__ Wih_f, const float* __restrict__ Whh_f,
    const float* __restrict__ bih_f, const float* __restrict__ bhh_f,
    const float* __restrict__ Wih_b, const float* __restrict__ Whh_b,
    const float* __restrict__ bih_b, const float* __restrict__ bhh_b,
    const float* __restrict__ W_out, const float* __restrict__ b_out,
    float* __restrict__ out)
{
    extern __shared__ char k2dsm[];
    K2Smem* S = (K2Smem*)k2dsm;
    const int b0 = blockIdx.x * 8;
    const int t = threadIdx.x;

    for (int i = t; i < 1024; i += 256) {
        int bb = i >> 7, kk = (i >> 5) & 3, c4 = (i & 31) << 2;
        *(float4*)&S->nbr[bb][kk][c4] =
            *(const float4*)&g_nbr_emb[(((size_t)(b0 + bb)) * 4 + kk) * 128 + c4];
    }
    if (t < 32) S->nbr[t >> 2][t & 3][128] = dirs[(b0 + (t >> 2)) * 4 + (t & 3)];
    {
        int bb = t >> 5, c4 = (t & 31) << 2;
        *(float4*)&S->cat[bb][c4] = *(const float4*)&out[(size_t)(b0 + bb) * 192 + c4];
    }
    if (t < 128) {
        int bb = t >> 4, d = (t >> 3) & 1, g8 = (t & 7) << 2;
        *(float4*)&S->h[bb][d][g8] = make_float4(0.f, 0.f, 0.f, 0.f);
    }
    __syncthreads();

    {
        int combo = t & 63, grp = t >> 6;
        int kk = combo >> 4, j4 = (combo & 15) << 2;
        int bA = grp, bB = grp + 4;
        float4 bs = __ldg((const float4*)&b_proj[j4]);
        float4 a0 = bs, a1 = bs;
        #pragma unroll 4
        for (int i = 0; i < 129; i++) {
            float4 w = __ldg((const float4*)&W_proj[i * 64 + j4]);
            float x0 = S->nbr[bA][kk][i], x1 = S->nbr[bB][kk][i];
            a0.x += x0*w.x; a0.y += x0*w.y; a0.z += x0*w.z; a0.w += x0*w.w;
            a1.x += x1*w.x; a1.y += x1*w.y; a1.z += x1*w.z; a1.w += x1*w.w;
        }
        float m0 = mask[(b0 + bA) * 4 + kk], m1 = mask[(b0 + bB) * 4 + kk];
        a0.x = (a0.x > 0.f ? a0.x : 0.f) * m0; a0.y = (a0.y > 0.f ? a0.y : 0.f) * m0;
        a0.z = (a0.z > 0.f ? a0.z : 0.f) * m0; a0.w = (a0.w > 0.f ? a0.w : 0.f) * m0;
        a1.x = (a1.x > 0.f ? a1.x : 0.f) * m1; a1.y = (a1.y > 0.f ? a1.y : 0.f) * m1;
        a1.z = (a1.z > 0.f ? a1.z : 0.f) * m1; a1.w = (a1.w > 0.f ? a1.w : 0.f) * m1;
        *(float4*)&S->x[bA][kk][j4] = a0;
        *(float4*)&S->x[bB][kk][j4] = a1;
    }
    __syncthreads();

    if (t < 192) {
        int d = t / 96, r = t % 96, kk = r / 24, j4 = (r % 24) << 2;
        const float* Wih = d ? Wih_b : Wih_f;
        const float* bih = d ? bih_b : bih_f;
        float4 bs = __ldg((const float4*)&bih[j4]);
        float4 acc[8];
        #pragma unroll
        for (int bb = 0; bb < 8; bb++) acc[bb] = bs;
        for (int i = 0; i < 64; i++) {
            float4 w = __ldg((const float4*)&Wih[i * 96 + j4]);
            #pragma unroll
            for (int bb = 0; bb < 8; bb++) {
                float xv = S->x[bb][kk][i];
                acc[bb].x += xv*w.x; acc[bb].y += xv*w.y;
                acc[bb].z += xv*w.z; acc[bb].w += xv*w.w;
            }
        }
        #pragma unroll
        for (int bb = 0; bb < 8; bb++) *(float4*)&S->gi[bb][d][kk][j4] = acc[bb];
    }
    __syncthreads();

    for (int step = 0; step < 4; step++) {
        if (t < 192) {
            int combo = t % 48, grp = t / 48;
            int d = combo / 24, j4 = (combo % 24) << 2;
            int bA = grp, bB = grp + 4;
            const float* Whh = d ? Whh_b : Whh_f;
            const float* bhh = d ? bhh_b : bhh_f;
            float4 bs = __ldg((const float4*)&bhh[j4]);
            float4 a0 = bs, a1 = bs;
            #pragma unroll
            for (int i = 0; i < 32; i++) {
                float4 w = __ldg((const float4*)&Whh[i * 96 + j4]);
                float h0 = S->h[bA][d][i], h1 = S->h[bB][d][i];
                a0.x += h0*w.x; a0.y += h0*w.y; a0.z += h0*w.z; a0.w += h0*w.w;
                a1.x += h1*w.x; a1.y += h1*w.y; a1.z += h1*w.z; a1.w += h1*w.w;
            }
            *(float4*)&S->gh[bA][d][j4] = a0;
            *(float4*)&S->gh[bB][d][j4] = a1;
        }
        __syncthreads();
        {
            int bA = t >> 6, d = (t >> 5) & 1, g = t & 31;
            #pragma unroll
            for (int p = 0; p < 2; p++) {
                int bb = bA + p * 4;
                int kf = d ? (3 - step) : step;
                float r = sigmoid_fast(S->gi[bb][d][kf][g]      + S->gh[bb][d][g]);
                float z = sigmoid_fast(S->gi[bb][d][kf][32 + g] + S->gh[bb][d][32 + g]);
                float nn = tanh_fast(S->gi[bb][d][kf][64 + g] + r * S->gh[bb][d][64 + g]);
                S->h[bb][d][g] = (1.f - z) * nn + z * S->h[bb][d][g];
            }
        }
        __syncthreads();
    }

    for (int i = t; i < 512; i += 256) {
        int bb = i >> 6, r = i & 63;
        S->cat[bb][128 + r] = S->h[bb][r >> 5][r & 31];
    }
    __syncthreads();

    if (t < 128) {
        int bb = t >> 4, j4 = (t & 15) << 2;
        float4 acc = __ldg((const float4*)&b_out[j4]);
        #pragma unroll 4
        for (int i = 0; i < 192; i++) {
            float cv = S->cat[bb][i];
            float4 w = __ldg((const float4*)&W_out[i * 64 + j4]);
            acc.x += cv*w.x; acc.y += cv*w.y; acc.z += cv*w.z; acc.w += cv*w.w;
        }
        acc.x = acc.x > 0.f ? acc.x : 0.f;
        acc.y = acc.y > 0.f ? acc.y : 0.f;
        acc.z = acc.z > 0.f ? acc.z : 0.f;
        acc.w = acc.w > 0.f ? acc.w : 0.f;
        *(float4*)&out[(size_t)(b0 + bb) * 192 + 128 + j4] = acc;
    }
}

// ============================ launch ========================================
extern "C" void kernel_launch(void* const* d_in, const int* in_sizes, int n_in,
                              void* d_out, int out_size) {
    const float* self_f   = (const float*)d_in[0];
    const float* nbr_f    = (const float*)d_in[1];
    const float* mask     = (const float*)d_in[2];
    const float* dirs     = (const float*)d_in[3];
    const float* W_coop   = (const float*)d_in[4];
    const float* a_src_c  = (const float*)d_in[5];
    const float* a_dst_c  = (const float*)d_in[6];
    const float* W_conf   = (const float*)d_in[7];
    const float* a_src_f2 = (const float*)d_in[8];
    const float* a_dst_f2 = (const float*)d_in[9];
    const float* W_fuse   = (const float*)d_in[10];
    const float* b_fuse   = (const float*)d_in[11];
    const float* W_proj   = (const float*)d_in[12];
    const float* b_proj   = (const float*)d_in[13];
    const float* Wih_f    = (const float*)d_in[14];
    const float* Whh_f    = (const float*)d_in[15];
    const float* bih_f    = (const float*)d_in[16];
    const float* bhh_f    = (const float*)d_in[17];
    const float* Wih_b    = (const float*)d_in[18];
    const float* Whh_b    = (const float*)d_in[19];
    const float* bih_b    = (const float*)d_in[20];
    const float* bhh_b    = (const float*)d_in[21];
    const float* W_out    = (const float*)d_in[22];
    const float* b_out    = (const float*)d_in[23];
    float* out = (float*)d_out;

    cudaFuncSetAttribute(mgmq_fused, cudaFuncAttributeMaxDynamicSharedMemorySize, SMEM_FUSED);
    cudaFuncSetAttribute(mgmq_k2, cudaFuncAttributeMaxDynamicSharedMemorySize, SMEM_K2);

    mgmq_wsplit<<<128, 256>>>(W_fuse, W_coop, a_src_c, a_dst_c,
                              W_conf, a_src_f2, a_dst_f2);
    mgmq_fused<<<NTILES, 512, SMEM_FUSED>>>(self_f, nbr_f, W_coop, W_conf,
                                            b_fuse, out);
    mgmq_k2<<<NB / 8, 256, SMEM_K2>>>(mask, dirs, W_proj, b_proj,
                                      Wih_f, Whh_f, bih_f, bhh_f,
                                      Wih_b, Whh_b, bih_b, bhh_b,
                                      W_out, b_out, out);
}

// round 12
// speedup vs baseline: 2.4354x; 1.0270x over previous
#include <cuda_runtime.h>
#include <cuda_bf16.h>
#include <cstdint>

// ---------------------------------------------------------------------------
// MGMQTorchModel R12 (= R11 with GAT group-local named barriers):
//   fused : GAT (8 nodes, 4 independent 128-thread groups with bar.sync)
//           -> pack bf16 hi/lo into smem A images -> HMMA GEMM
//           -> bias+elu+mean -> scatter.  One 512-thread block per M-tile.
//   wsplit: W_fuse -> Wt images + Wa precompute.   k2 unchanged.
// ---------------------------------------------------------------------------

#define NB 8192
#define NODES (NB*5)          // 40960
#define NTILES (NODES/8)      // 5120 (8 nodes x 12 rows = M 96)

__device__ float g_nbr_emb[NB * 4 * 128];
__device__ __nv_bfloat16 g_WtT[2 * 32768];   // [term][n 128][k 256]
__device__ float g_Wa[64];                   // [s][src/dst][h][f]

__device__ __forceinline__ float tanh_fast(float x) {
    float y; asm("tanh.approx.f32 %0, %1;" : "=f"(y) : "f"(x)); return y;
}
__device__ __forceinline__ float sigmoid_fast(float x) {
    return 1.f / (1.f + __expf(-x));
}
__device__ __forceinline__ float elu_f(float x) {
    return (x > 0.f) ? x : (__expf(x) - 1.f);
}
__device__ __forceinline__ uint32_t smem_u32(const void* p) {
    uint32_t a;
    asm("{ .reg .u64 t; cvta.to.shared.u64 t, %1; cvt.u32.u64 %0, t; }" : "=r"(a) : "l"(p));
    return a;
}
__device__ __forceinline__ void mma16816(float* d, const uint32_t* a,
                                         uint32_t b0, uint32_t b1) {
    asm volatile(
        "mma.sync.aligned.m16n8k16.row.col.f32.bf16.bf16.f32 "
        "{%0,%1,%2,%3}, {%4,%5,%6,%7}, {%8,%9}, {%0,%1,%2,%3};"
        : "+f"(d[0]), "+f"(d[1]), "+f"(d[2]), "+f"(d[3])
        : "r"(a[0]), "r"(a[1]), "r"(a[2]), "r"(a[3]), "r"(b0), "r"(b1));
}
#define LDSM_X4(r, addr) \
    asm volatile("ldmatrix.sync.aligned.m8n8.x4.shared.b16 {%0,%1,%2,%3}, [%4];" \
        : "=r"((r)[0]), "=r"((r)[1]), "=r"((r)[2]), "=r"((r)[3]) : "r"(addr))
#define GBAR(id) \
    asm volatile("bar.sync %0, 128;" :: "r"((id) + 1) : "memory")

// ======================= setup: W_fuse -> Wt images + Wa ====================
__global__ void mgmq_wsplit(const float* __restrict__ W_fuse,
                            const float* __restrict__ W_coop,
                            const float* __restrict__ a_src_coop,
                            const float* __restrict__ a_dst_coop,
                            const float* __restrict__ W_conf,
                            const float* __restrict__ a_src_conf,
                            const float* __restrict__ a_dst_conf) {
    int idx = blockIdx.x * blockDim.x + threadIdx.x;
    if (blockIdx.x == 0 && threadIdx.x < 64) {
        int i = threadIdx.x;
        int s = i >> 5, v = (i >> 4) & 1, h = (i >> 2) & 3, f = i & 3;
        const float* W = s ? W_conf : W_coop;
        const float* a = s ? (v ? a_dst_conf : a_src_conf)
                           : (v ? a_dst_coop : a_src_coop);
        float acc = 0.f;
        #pragma unroll
        for (int o = 0; o < 32; o++)
            acc += __ldg(&W[(h * 4 + f) * 32 + o]) * __ldg(&a[h * 32 + o]);
        g_Wa[i] = acc;
    }
    if (idx >= 128 * 256) return;
    int n = idx >> 8;
    int k = idx & 255;
    float w = W_fuse[k * 128 + n];
    __nv_bfloat16 hi = __float2bfloat16(w);
    __nv_bfloat16 lo = __float2bfloat16(w - __bfloat162float(hi));
    g_WtT[n * 256 + k] = hi;
    g_WtT[32768 + n * 256 + k] = lo;
}

// ======================== FUSED kernel ======================================
#define A_RS    528
#define AHI_OFF 0
#define ALO_OFF 50688
#define X_OFF   101376
#define B_IMG   34816
#define SW_OFF  171008
#define SX_OFF  175104
#define ATTC_OFF 176640
#define ATTF_OFF 179712
#define BIAS_OFF 188928
#define SMEM_FUSED 189440
#define CH_RS   272

__global__ __launch_bounds__(512) void mgmq_fused(
    const float* __restrict__ self_f, const float* __restrict__ nbr_f,
    const float* __restrict__ W_coop, const float* __restrict__ W_conf,
    const float* __restrict__ b_fuse, float* __restrict__ out)
{
    extern __shared__ char dsm[];
    float* sW   = (float*)(dsm + SW_OFF);
    float* sx   = (float*)(dsm + SX_OFF);
    float4* sAttC = (float4*)(dsm + ATTC_OFF);   // [(nl*4 + h)*12 + i]
    float*  sAttF = (float*)(dsm + ATTF_OFF);    // [((nl*4 + h)*12 + i)*12 + j]
    float* sbias = (float*)(dsm + BIAS_OFF);
    float* sCatX = (float*)(dsm + X_OFF);        // [nl][i][c] = nl*3072+i*256+c

    const int t = threadIdx.x;
    const int wid = t >> 5;
    const int lid = t & 31;
    const int tile = blockIdx.x;

    // ---- stage weights, bias, and 8 nodes' features ----
    if (t < 128) ((float4*)sW)[t] = __ldg(&((const float4*)W_coop)[t]);
    else if (t < 256) ((float4*)sW)[t] = __ldg(&((const float4*)W_conf)[t - 128]);
    if (t >= 384) sbias[t - 384] = __ldg(&b_fuse[t - 384]);
    if (t < 384) {
        int n8 = t / 48, f = t % 48;
        int node = tile * 8 + n8;
        int b = node / 5, slot = node - b * 5;
        const float* xsrc = (slot == 0) ? (self_f + (size_t)b * 48)
                                        : (nbr_f + ((size_t)b * 4 + (slot - 1)) * 48);
        sx[n8 * 48 + f] = __ldg(&xsrc[f]);
    }
    __syncthreads();

    // ==================== GAT: 2 passes x 4 independent groups =============
    const int nl = t >> 7;          // 0..3 : group / node-lane
    const int tt = t & 127;
    #pragma unroll
    for (int p = 0; p < 2; p++) {
        const int n8 = p * 4 + nl;
        const float* nx = sx + n8 * 48;

        // ---- softmax (tt<96), per-head slots ----
        if (tt < 48) {
            int h = tt / 12, i = tt - h * 12, j0 = (i / 3) * 3;
            float was0 = __ldg(&g_Wa[h*4+0]), was1 = __ldg(&g_Wa[h*4+1]);
            float was2 = __ldg(&g_Wa[h*4+2]), was3 = __ldg(&g_Wa[h*4+3]);
            float wad0 = __ldg(&g_Wa[16+h*4+0]), wad1 = __ldg(&g_Wa[16+h*4+1]);
            float wad2 = __ldg(&g_Wa[16+h*4+2]), wad3 = __ldg(&g_Wa[16+h*4+3]);
            float es = nx[i*4]*was0 + nx[i*4+1]*was1 + nx[i*4+2]*was2 + nx[i*4+3]*was3;
            float e[3];
            #pragma unroll
            for (int jj = 0; jj < 3; jj++) {
                int j = j0 + jj;
                float ed = nx[j*4]*wad0 + nx[j*4+1]*wad1 + nx[j*4+2]*wad2 + nx[j*4+3]*wad3;
                float v = es + ed;
                e[jj] = (v > 0.f) ? v : 0.2f * v;
            }
            float m = fmaxf(e[0], fmaxf(e[1], e[2]));
            float x0 = __expf(e[0]-m), x1 = __expf(e[1]-m), x2 = __expf(e[2]-m);
            float inv = 1.f / (x0 + x1 + x2);
            sAttC[(nl * 4 + h) * 12 + i] = make_float4(x0*inv, x1*inv, x2*inv, 0.f);
        } else if (tt < 96) {
            int r = tt - 48;
            int h = r / 12, i = r - h * 12;
            int gi = i / 3;
            float was0 = __ldg(&g_Wa[32+h*4+0]), was1 = __ldg(&g_Wa[32+h*4+1]);
            float was2 = __ldg(&g_Wa[32+h*4+2]), was3 = __ldg(&g_Wa[32+h*4+3]);
            float wad0 = __ldg(&g_Wa[48+h*4+0]), wad1 = __ldg(&g_Wa[48+h*4+1]);
            float wad2 = __ldg(&g_Wa[48+h*4+2]), wad3 = __ldg(&g_Wa[48+h*4+3]);
            float es = nx[i*4]*was0 + nx[i*4+1]*was1 + nx[i*4+2]*was2 + nx[i*4+3]*was3;
            float ev[12], m = -1e30f;
            #pragma unroll
            for (int j = 0; j < 12; j++) {
                float ed = nx[j*4]*wad0 + nx[j*4+1]*wad1 + nx[j*4+2]*wad2 + nx[j*4+3]*wad3;
                float e = es + ed;
                e = (e > 0.f) ? e : 0.2f * e;
                bool valid = ((j / 3) != gi);
                ev[j] = valid ? e : -1e30f;
                if (valid && e > m) m = e;
            }
            float sum = 0.f, ex[12];
            #pragma unroll
            for (int j = 0; j < 12; j++) {
                float v = (ev[j] > -1e29f) ? __expf(ev[j] - m) : 0.f;
                ex[j] = v; sum += v;
            }
            float inv = 1.f / sum;
            #pragma unroll
            for (int j = 0; j < 12; j++)
                sAttF[((nl * 4 + h) * 12 + i) * 12 + j] = ex[j] * inv;
        }

        // ---- Wh columns in registers ----
        const int o = tt & 31, h = tt >> 5;
        float wh0[12], wh1[12];
        {
            float w00 = sW[h*128 +  0 + o], w01 = sW[h*128 + 32 + o];
            float w02 = sW[h*128 + 64 + o], w03 = sW[h*128 + 96 + o];
            float w10 = sW[512 + h*128 +  0 + o], w11 = sW[512 + h*128 + 32 + o];
            float w12 = sW[512 + h*128 + 64 + o], w13 = sW[512 + h*128 + 96 + o];
            #pragma unroll
            for (int j = 0; j < 12; j++) {
                float x0 = nx[j*4], x1 = nx[j*4+1], x2 = nx[j*4+2], x3 = nx[j*4+3];
                wh0[j] = x0*w00 + x1*w01 + x2*w02 + x3*w03;
                wh1[j] = x0*w10 + x1*w11 + x2*w12 + x3*w13;
            }
        }
        GBAR(nl);   // sAtt ready (group-local)

        // ---- aggregation + elu -> sCatX[nl][i][c] ----
        {
            float* catn = sCatX + nl * 3072;
            #pragma unroll
            for (int i = 0; i < 12; i++) {
                const int j0 = (i / 3) * 3;
                float4 a = sAttC[(nl * 4 + h) * 12 + i];
                float acc = a.x * wh0[j0] + a.y * wh0[j0+1] + a.z * wh0[j0+2];
                catn[i * 256 + h * 32 + o] = elu_f(acc);
            }
            #pragma unroll
            for (int i = 0; i < 12; i++) {
                const int g0 = (i / 3) * 3;
                const float* ar = sAttF + ((nl * 4 + h) * 12 + i) * 12;
                float acc = 0.f;
                #pragma unroll
                for (int j = 0; j < 12; j++)
                    if (j < g0 || j >= g0 + 3) acc += ar[j] * wh1[j];
                catn[i * 256 + 128 + h * 32 + o] = elu_f(acc);
            }
        }
        GBAR(nl);   // sCatX ready (group-local)

        // ---- pack this group's node into A images (bf16 hi/lo) ----
        for (int item = tt; item < 384; item += 128) {
            int rr = item >> 5;
            int c8 = (item & 31) << 3;
            const float* src = sCatX + nl * 3072 + rr * 256 + c8;
            float4 p0 = *(const float4*)src;
            float4 p1 = *(const float4*)(src + 4);
            float v[8] = {p0.x, p0.y, p0.z, p0.w, p1.x, p1.y, p1.z, p1.w};
            uint32_t hw[4], lw[4];
            #pragma unroll
            for (int j = 0; j < 4; j++) {
                __nv_bfloat16 h0 = __float2bfloat16(v[2*j]);
                __nv_bfloat16 h1 = __float2bfloat16(v[2*j+1]);
                float r0 = v[2*j]   - __bfloat162float(h0);
                float r1 = v[2*j+1] - __bfloat162float(h1);
                __nv_bfloat16 l0 = __float2bfloat16(r0);
                __nv_bfloat16 l1 = __float2bfloat16(r1);
                hw[j] = (uint32_t)__bfloat16_as_ushort(h0) | ((uint32_t)__bfloat16_as_ushort(h1) << 16);
                lw[j] = (uint32_t)__bfloat16_as_ushort(l0) | ((uint32_t)__bfloat16_as_ushort(l1) << 16);
            }
            int row = (p * 4 + nl) * 12 + rr;
            uint32_t boff = (uint32_t)row * A_RS + (uint32_t)c8 * 2;
            *(uint4*)(dsm + AHI_OFF + boff) = make_uint4(hw[0], hw[1], hw[2], hw[3]);
            *(uint4*)(dsm + ALO_OFF + boff) = make_uint4(lw[0], lw[1], lw[2], lw[3]);
        }
        GBAR(nl);   // pack done; group may reuse sAtt/sCatX next pass
    }
    __syncthreads();   // all A rows complete; X region free for B

    // ==================== GEMM ==============================================
    const int mtile = wid >> 1;
    const int nhalf = wid & 1;
    const int g = lid >> 2;
    const int q = lid & 3;
    const int row0 = mtile * 16 + g;
    const int row1 = row0 + 8;
    const bool mma_w = (wid < 12);

    const uint32_t sbase = smem_u32(dsm);
    const uint32_t a_lane = (uint32_t)((mtile * 16 + ((lid >> 3) & 1) * 8 + (lid & 7)) * A_RS
                          + ((lid >> 4) & 1) * 16);
    const uint32_t b_lane = (uint32_t)((nhalf * 64 + ((lid >> 4) & 1) * 8 + (lid & 7)) * CH_RS
                          + ((lid >> 3) & 1) * 16);

    float d[8][4];
    #pragma unroll
    for (int nt = 0; nt < 8; nt++) {
        d[nt][0] = 0.f; d[nt][1] = 0.f; d[nt][2] = 0.f; d[nt][3] = 0.f;
    }

    const uint4* gBH = (const uint4*)g_WtT;
    const uint4* gBL = (const uint4*)(g_WtT + 32768);

    #pragma unroll
    for (int kc = 0; kc < 2; kc++) {
        for (int i = t; i < 4096; i += 512) {
            int term = i >> 11;
            int r = i & 2047;
            int nr = r >> 4, c16 = r & 15;
            const uint4* gB = term ? gBL : gBH;
            *(uint4*)(dsm + X_OFF + term * B_IMG + nr * CH_RS + c16 * 16)
                = gB[nr * 32 + kc * 16 + c16];
        }
        __syncthreads();

        if (mma_w) {
            const uint32_t aHb = sbase + AHI_OFF + a_lane + kc * 256;
            const uint32_t aLb = sbase + ALO_OFF + a_lane + kc * 256;
            const uint32_t bHb = sbase + X_OFF + b_lane;
            const uint32_t bLb = sbase + X_OFF + B_IMG + b_lane;

            #pragma unroll
            for (int ks = 0; ks < 8; ks++) {
                const uint32_t koff = ks * 32;
                uint32_t ah[4], al[4];
                LDSM_X4(ah, aHb + koff);
                LDSM_X4(al, aLb + koff);
                #pragma unroll
                for (int pp = 0; pp < 4; pp++) {
                    uint32_t bh[4], bl[4];
                    LDSM_X4(bh, bHb + pp * (16 * CH_RS) + koff);
                    LDSM_X4(bl, bLb + pp * (16 * CH_RS) + koff);
                    mma16816(d[2*pp],     ah, bh[0], bh[1]);
                    mma16816(d[2*pp],     ah, bl[0], bl[1]);
                    mma16816(d[2*pp],     al, bh[0], bh[1]);
                    mma16816(d[2*pp + 1], ah, bh[2], bh[3]);
                    mma16816(d[2*pp + 1], ah, bl[2], bl[3]);
                    mma16816(d[2*pp + 1], al, bh[2], bh[3]);
                }
            }
        }
        __syncthreads();
    }

    // ---- epilogue: elu(D+bias) -> Dbuf (X region), then 12-row mean ----
    float* Dbuf = (float*)(dsm + X_OFF);
    if (mma_w) {
        #pragma unroll
        for (int nt = 0; nt < 8; nt++) {
            int c0 = nhalf * 64 + nt * 8 + q * 2;
            float b0 = sbias[c0], b1 = sbias[c0 + 1];
            float2 v0 = make_float2(elu_f(d[nt][0] + b0), elu_f(d[nt][1] + b1));
            float2 v1 = make_float2(elu_f(d[nt][2] + b0), elu_f(d[nt][3] + b1));
            *(float2*)&Dbuf[row0 * 132 + c0] = v0;
            *(float2*)&Dbuf[row1 * 132 + c0] = v1;
        }
    }
    __syncthreads();

    if (t < 256) {
        int nl8 = t >> 5;
        int c4 = (t & 31) << 2;
        float4 s = make_float4(0.f, 0.f, 0.f, 0.f);
        #pragma unroll
        for (int j = 0; j < 12; j++) {
            float4 v = *(const float4*)&Dbuf[(nl8 * 12 + j) * 132 + c4];
            s.x += v.x; s.y += v.y; s.z += v.z; s.w += v.w;
        }
        s.x *= (1.f/12.f); s.y *= (1.f/12.f); s.z *= (1.f/12.f); s.w *= (1.f/12.f);
        int node = tile * 8 + nl8;
        int b = node / 5, slot = node - b * 5;
        if (slot == 0) *(float4*)&out[(size_t)b * 192 + c4] = s;
        else *(float4*)&g_nbr_emb[((size_t)b * 4 + (slot - 1)) * 128 + c4] = s;
    }
}

// ============================ KERNEL 2 ======================================
struct K2Smem {
    float nbr[8][4][132];
    float x[8][4][64];
    float gi[8][2][4][96];
    float gh[8][2][96];
    float h[8][2][32];
    float cat[8][192];
};
#define SMEM_K2 ((int)sizeof(K2Smem))

__global__ __launch_bounds__(256) void mgmq_k2(
    const float* __restrict__ mask, const float* __restrict__ dirs,
    const float* __restrict__ W_proj, const float* __restrict__ b_proj,
    const float* __restrict__ Wih_f, const float* __restrict__ Whh_f,
    const float* __restrict__ bih_f, const float* __restrict__ bhh_f,
    const float* __restrict__ Wih_b, const float* __restrict__ Whh_b,
    const float* __restrict__ bih_b, const float* __restrict__ bhh_b,
    const float* __restrict__ W_out, const float* __restrict__ b_out,
    float* __restrict__ out)
{
    extern __shared__ char k2dsm[];
    K2Smem* S = (K2Smem*)k2dsm;
    const int b0 = blockIdx.x * 8;
    const int t = threadIdx.x;

    for (int i = t; i < 1024; i += 256) {
        int bb = i >> 7, kk = (i >> 5) & 3, c4 = (i & 31) << 2;
        *(float4*)&S->nbr[bb][kk][c4] =
            *(const float4*)&g_nbr_emb[(((size_t)(b0 + bb)) * 4 + kk) * 128 + c4];
    }
    if (t < 32) S->nbr[t >> 2][t & 3][128] = dirs[(b0 + (t >> 2)) * 4 + (t & 3)];
    {
        int bb = t >> 5, c4 = (t & 31) << 2;
        *(float4*)&S->cat[bb][c4] = *(const float4*)&out[(size_t)(b0 + bb) * 192 + c4];
    }
    if (t < 128) {
        int bb = t >> 4, d = (t >> 3) & 1, g8 = (t & 7) << 2;
        *(float4*)&S->h[bb][d][g8] = make_float4(0.f, 0.f, 0.f, 0.f);
    }
    __syncthreads();

    {
        int combo = t & 63, grp = t >> 6;
        int kk = combo >> 4, j4 = (combo & 15) << 2;
        int bA = grp, bB = grp + 4;
        float4 bs = __ldg((const float4*)&b_proj[j4]);
        float4 a0 = bs, a1 = bs;
        #pragma unroll 4
        for (int i = 0; i < 129; i++) {
            float4 w = __ldg((const float4*)&W_proj[i * 64 + j4]);
            float x0 = S->nbr[bA][kk][i], x1 = S->nbr[bB][kk][i];
            a0.x += x0*w.x; a0.y += x0*w.y; a0.z += x0*w.z; a0.w += x0*w.w;
            a1.x += x1*w.x; a1.y += x1*w.y; a1.z += x1*w.z; a1.w += x1*w.w;
        }
        float m0 = mask[(b0 + bA) * 4 + kk], m1 = mask[(b0 + bB) * 4 + kk];
        a0.x = (a0.x > 0.f ? a0.x : 0.f) * m0; a0.y = (a0.y > 0.f ? a0.y : 0.f) * m0;
        a0.z = (a0.z > 0.f ? a0.z : 0.f) * m0; a0.w = (a0.w > 0.f ? a0.w : 0.f) * m0;
        a1.x = (a1.x > 0.f ? a1.x : 0.f) * m1; a1.y = (a1.y > 0.f ? a1.y : 0.f) * m1;
        a1.z = (a1.z > 0.f ? a1.z : 0.f) * m1; a1.w = (a1.w > 0.f ? a1.w : 0.f) * m1;
        *(float4*)&S->x[bA][kk][j4] = a0;
        *(float4*)&S->x[bB][kk][j4] = a1;
    }
    __syncthreads();

    if (t < 192) {
        int d = t / 96, r = t % 96, kk = r / 24, j4 = (r % 24) << 2;
        const float* Wih = d ? Wih_b : Wih_f;
        const float* bih = d ? bih_b : bih_f;
        float4 bs = __ldg((const float4*)&bih[j4]);
        float4 acc[8];
        #pragma unroll
        for (int bb = 0; bb < 8; bb++) acc[bb] = bs;
        for (int i = 0; i < 64; i++) {
            float4 w = __ldg((const float4*)&Wih[i * 96 + j4]);
            #pragma unroll
            for (int bb = 0; bb < 8; bb++) {
                float xv = S->x[bb][kk][i];
                acc[bb].x += xv*w.x; acc[bb].y += xv*w.y;
                acc[bb].z += xv*w.z; acc[bb].w += xv*w.w;
            }
        }
        #pragma unroll
        for (int bb = 0; bb < 8; bb++) *(float4*)&S->gi[bb][d][kk][j4] = acc[bb];
    }
    __syncthreads();

    for (int step = 0; step < 4; step++) {
        if (t < 192) {
            int combo = t % 48, grp = t / 48;
            int d = combo / 24, j4 = (combo % 24) << 2;
            int bA = grp, bB = grp + 4;
            const float* Whh = d ? Whh_b : Whh_f;
            const float* bhh = d ? bhh_b : bhh_f;
            float4 bs = __ldg((const float4*)&bhh[j4]);
            float4 a0 = bs, a1 = bs;
            #pragma unroll
            for (int i = 0; i < 32; i++) {
                float4 w = __ldg((const float4*)&Whh[i * 96 + j4]);
                float h0 = S->h[bA][d][i], h1 = S->h[bB][d][i];
                a0.x += h0*w.x; a0.y += h0*w.y; a0.z += h0*w.z; a0.w += h0*w.w;
                a1.x += h1*w.x; a1.y += h1*w.y; a1.z += h1*w.z; a1.w += h1*w.w;
            }
            *(float4*)&S->gh[bA][d][j4] = a0;
            *(float4*)&S->gh[bB][d][j4] = a1;
        }
        __syncthreads();
        {
            int bA = t >> 6, d = (t >> 5) & 1, g = t & 31;
            #pragma unroll
            for (int p = 0; p < 2; p++) {
                int bb = bA + p * 4;
                int kf = d ? (3 - step) : step;
                float r = sigmoid_fast(S->gi[bb][d][kf][g]      + S->gh[bb][d][g]);
                float z = sigmoid_fast(S->gi[bb][d][kf][32 + g] + S->gh[bb][d][32 + g]);
                float nn = tanh_fast(S->gi[bb][d][kf][64 + g] + r * S->gh[bb][d][64 + g]);
                S->h[bb][d][g] = (1.f - z) * nn + z * S->h[bb][d][g];
            }
        }
        __syncthreads();
    }

    for (int i = t; i < 512; i += 256) {
        int bb = i >> 6, r = i & 63;
        S->cat[bb][128 + r] = S->h[bb][r >> 5][r & 31];
    }
    __syncthreads();

    if (t < 128) {
        int bb = t >> 4, j4 = (t & 15) << 2;
        float4 acc = __ldg((const float4*)&b_out[j4]);
        #pragma unroll 4
        for (int i = 0; i < 192; i++) {
            float cv = S->cat[bb][i];
            float4 w = __ldg((const float4*)&W_out[i * 64 + j4]);
            acc.x += cv*w.x; acc.y += cv*w.y; acc.z += cv*w.z; acc.w += cv*w.w;
        }
        acc.x = acc.x > 0.f ? acc.x : 0.f;
        acc.y = acc.y > 0.f ? acc.y : 0.f;
        acc.z = acc.z > 0.f ? acc.z : 0.f;
        acc.w = acc.w > 0.f ? acc.w : 0.f;
        *(float4*)&out[(size_t)(b0 + bb) * 192 + 128 + j4] = acc;
    }
}

// ============================ launch ========================================
extern "C" void kernel_launch(void* const* d_in, const int* in_sizes, int n_in,
                              void* d_out, int out_size) {
    const float* self_f   = (const float*)d_in[0];
    const float* nbr_f    = (const float*)d_in[1];
    const float* mask     = (const float*)d_in[2];
    const float* dirs     = (const float*)d_in[3];
    const float* W_coop   = (const float*)d_in[4];
    const float* a_src_c  = (const float*)d_in[5];
    const float* a_dst_c  = (const float*)d_in[6];
    const float* W_conf   = (const float*)d_in[7];
    const float* a_src_f2 = (const float*)d_in[8];
    const float* a_dst_f2 = (const float*)d_in[9];
    const float* W_fuse   = (const float*)d_in[10];
    const float* b_fuse   = (const float*)d_in[11];
    const float* W_proj   = (const float*)d_in[12];
    const float* b_proj   = (const float*)d_in[13];
    const float* Wih_f    = (const float*)d_in[14];
    const float* Whh_f    = (const float*)d_in[15];
    const float* bih_f    = (const float*)d_in[16];
    const float* bhh_f    = (const float*)d_in[17];
    const float* Wih_b    = (const float*)d_in[18];
    const float* Whh_b    = (const float*)d_in[19];
    const float* bih_b    = (const float*)d_in[20];
    const float* bhh_b    = (const float*)d_in[21];
    const float* W_out    = (const float*)d_in[22];
    const float* b_out    = (const float*)d_in[23];
    float* out = (float*)d_out;

    cudaFuncSetAttribute(mgmq_fused, cudaFuncAttributeMaxDynamicSharedMemorySize, SMEM_FUSED);
    cudaFuncSetAttribute(mgmq_k2, cudaFuncAttributeMaxDynamicSharedMemorySize, SMEM_K2);

    mgmq_wsplit<<<128, 256>>>(W_fuse, W_coop, a_src_c, a_dst_c,
                              W_conf, a_src_f2, a_dst_f2);
    mgmq_fused<<<NTILES, 512, SMEM_FUSED>>>(self_f, nbr_f, W_coop, W_conf,
                                            b_fuse, out);
    mgmq_k2<<<NB / 8, 256, SMEM_K2>>>(mask, dirs, W_proj, b_proj,
                                      Wih_f, Whh_f, bih_f, bhh_f,
                                      Wih_b, Whh_b, bih_b, bhh_b,
                                      W_out, b_out, out);
}

// round 13
// speedup vs baseline: 2.4791x; 1.0179x over previous
#include <cuda_runtime.h>
#include <cuda_bf16.h>
#include <cstdint>

// ---------------------------------------------------------------------------
// MGMQTorchModel R13 (= R12 with register shuffle-pack + B kc0 prefetch):
//   fused : GAT (8 nodes, group-local barriers) -> shuffle-pack bf16 hi/lo
//           straight into smem A images (no sCatX) while B kc0 streams in
//           -> HMMA GEMM -> bias+elu+mean -> scatter.
//   wsplit: W_fuse -> Wt images + Wa precompute.   k2 unchanged.
// ---------------------------------------------------------------------------

#define NB 8192
#define NODES (NB*5)          // 40960
#define NTILES (NODES/8)      // 5120 (8 nodes x 12 rows = M 96)

__device__ float g_nbr_emb[NB * 4 * 128];
__device__ __nv_bfloat16 g_WtT[2 * 32768];   // [term][n 128][k 256]
__device__ float g_Wa[64];                   // [s][src/dst][h][f]

__device__ __forceinline__ float tanh_fast(float x) {
    float y; asm("tanh.approx.f32 %0, %1;" : "=f"(y) : "f"(x)); return y;
}
__device__ __forceinline__ float sigmoid_fast(float x) {
    return 1.f / (1.f + __expf(-x));
}
__device__ __forceinline__ float elu_f(float x) {
    return (x > 0.f) ? x : (__expf(x) - 1.f);
}
__device__ __forceinline__ uint32_t smem_u32(const void* p) {
    uint32_t a;
    asm("{ .reg .u64 t; cvta.to.shared.u64 t, %1; cvt.u32.u64 %0, t; }" : "=r"(a) : "l"(p));
    return a;
}
__device__ __forceinline__ void mma16816(float* d, const uint32_t* a,
                                         uint32_t b0, uint32_t b1) {
    asm volatile(
        "mma.sync.aligned.m16n8k16.row.col.f32.bf16.bf16.f32 "
        "{%0,%1,%2,%3}, {%4,%5,%6,%7}, {%8,%9}, {%0,%1,%2,%3};"
        : "+f"(d[0]), "+f"(d[1]), "+f"(d[2]), "+f"(d[3])
        : "r"(a[0]), "r"(a[1]), "r"(a[2]), "r"(a[3]), "r"(b0), "r"(b1));
}
#define LDSM_X4(r, addr) \
    asm volatile("ldmatrix.sync.aligned.m8n8.x4.shared.b16 {%0,%1,%2,%3}, [%4];" \
        : "=r"((r)[0]), "=r"((r)[1]), "=r"((r)[2]), "=r"((r)[3]) : "r"(addr))
#define GBAR(id) \
    asm volatile("bar.sync %0, 128;" :: "r"((id) + 1) : "memory")

// ======================= setup: W_fuse -> Wt images + Wa ====================
__global__ void mgmq_wsplit(const float* __restrict__ W_fuse,
                            const float* __restrict__ W_coop,
                            const float* __restrict__ a_src_coop,
                            const float* __restrict__ a_dst_coop,
                            const float* __restrict__ W_conf,
                            const float* __restrict__ a_src_conf,
                            const float* __restrict__ a_dst_conf) {
    int idx = blockIdx.x * blockDim.x + threadIdx.x;
    if (blockIdx.x == 0 && threadIdx.x < 64) {
        int i = threadIdx.x;
        int s = i >> 5, v = (i >> 4) & 1, h = (i >> 2) & 3, f = i & 3;
        const float* W = s ? W_conf : W_coop;
        const float* a = s ? (v ? a_dst_conf : a_src_conf)
                           : (v ? a_dst_coop : a_src_coop);
        float acc = 0.f;
        #pragma unroll
        for (int o = 0; o < 32; o++)
            acc += __ldg(&W[(h * 4 + f) * 32 + o]) * __ldg(&a[h * 32 + o]);
        g_Wa[i] = acc;
    }
    if (idx >= 128 * 256) return;
    int n = idx >> 8;
    int k = idx & 255;
    float w = W_fuse[k * 128 + n];
    __nv_bfloat16 hi = __float2bfloat16(w);
    __nv_bfloat16 lo = __float2bfloat16(w - __bfloat162float(hi));
    g_WtT[n * 256 + k] = hi;
    g_WtT[32768 + n * 256 + k] = lo;
}

// ======================== FUSED kernel ======================================
// smem layout:
//   Ahi [96][528B] @0 (50688) | Alo @50688 (50688)
//   X   @101376 (69632): B hi/lo chunk (2x34816) | Dbuf f32 [96][132]
//   sW @171008 (4096) | sx @175104 (1536)
//   AttC @176640 (3072) | AttF @179712 (9216) | bias @188928 (512)
#define A_RS    528
#define AHI_OFF 0
#define ALO_OFF 50688
#define X_OFF   101376
#define B_IMG   34816
#define SW_OFF  171008
#define SX_OFF  175104
#define ATTC_OFF 176640
#define ATTF_OFF 179712
#define BIAS_OFF 188928
#define SMEM_FUSED 189440
#define CH_RS   272

__global__ __launch_bounds__(512) void mgmq_fused(
    const float* __restrict__ self_f, const float* __restrict__ nbr_f,
    const float* __restrict__ W_coop, const float* __restrict__ W_conf,
    const float* __restrict__ b_fuse, float* __restrict__ out)
{
    extern __shared__ char dsm[];
    float* sW   = (float*)(dsm + SW_OFF);
    float* sx   = (float*)(dsm + SX_OFF);
    float4* sAttC = (float4*)(dsm + ATTC_OFF);   // [(nl*4 + h)*12 + i]
    float*  sAttF = (float*)(dsm + ATTF_OFF);    // [((nl*4 + h)*12 + i)*12 + j]
    float* sbias = (float*)(dsm + BIAS_OFF);

    const int t = threadIdx.x;
    const int wid = t >> 5;
    const int lid = t & 31;
    const int tile = blockIdx.x;

    const uint4* gBH = (const uint4*)g_WtT;
    const uint4* gBL = (const uint4*)(g_WtT + 32768);

    // ---- stage weights, bias, 8 nodes' features ----
    if (t < 128) ((float4*)sW)[t] = __ldg(&((const float4*)W_coop)[t]);
    else if (t < 256) ((float4*)sW)[t] = __ldg(&((const float4*)W_conf)[t - 128]);
    if (t >= 384) sbias[t - 384] = __ldg(&b_fuse[t - 384]);
    if (t < 384) {
        int n8 = t / 48, f = t % 48;
        int node = tile * 8 + n8;
        int b = node / 5, slot = node - b * 5;
        const float* xsrc = (slot == 0) ? (self_f + (size_t)b * 48)
                                        : (nbr_f + ((size_t)b * 4 + (slot - 1)) * 48);
        sx[n8 * 48 + f] = __ldg(&xsrc[f]);
    }

    // ---- prefetch B kc0 (hi+lo) into X region; overlaps with GAT below ----
    for (int i = t; i < 4096; i += 512) {
        int term = i >> 11;
        int r = i & 2047;
        int nr = r >> 4, c16 = r & 15;
        const uint4* gB = term ? gBL : gBH;
        *(uint4*)(dsm + X_OFF + term * B_IMG + nr * CH_RS + c16 * 16)
            = gB[nr * 32 + c16];
    }
    __syncthreads();

    // ==================== GAT: 2 passes x 4 independent groups =============
    const int nl = t >> 7;          // 0..3 : group / node-lane
    const int tt = t & 127;
    const int o = tt & 31, h = tt >> 5;
    const int opair2 = (o & ~1) * 2;        // byte offset of even col of pair
    const bool evn = (o & 1) == 0;

    #pragma unroll
    for (int p = 0; p < 2; p++) {
        const int n8 = p * 4 + nl;
        const float* nx = sx + n8 * 48;

        // ---- softmax (tt<96), per-head slots ----
        if (tt < 48) {
            int hh = tt / 12, i = tt - hh * 12, j0 = (i / 3) * 3;
            float was0 = __ldg(&g_Wa[hh*4+0]), was1 = __ldg(&g_Wa[hh*4+1]);
            float was2 = __ldg(&g_Wa[hh*4+2]), was3 = __ldg(&g_Wa[hh*4+3]);
            float wad0 = __ldg(&g_Wa[16+hh*4+0]), wad1 = __ldg(&g_Wa[16+hh*4+1]);
            float wad2 = __ldg(&g_Wa[16+hh*4+2]), wad3 = __ldg(&g_Wa[16+hh*4+3]);
            float es = nx[i*4]*was0 + nx[i*4+1]*was1 + nx[i*4+2]*was2 + nx[i*4+3]*was3;
            float e[3];
            #pragma unroll
            for (int jj = 0; jj < 3; jj++) {
                int j = j0 + jj;
                float ed = nx[j*4]*wad0 + nx[j*4+1]*wad1 + nx[j*4+2]*wad2 + nx[j*4+3]*wad3;
                float v = es + ed;
                e[jj] = (v > 0.f) ? v : 0.2f * v;
            }
            float m = fmaxf(e[0], fmaxf(e[1], e[2]));
            float x0 = __expf(e[0]-m), x1 = __expf(e[1]-m), x2 = __expf(e[2]-m);
            float inv = 1.f / (x0 + x1 + x2);
            sAttC[(nl * 4 + hh) * 12 + i] = make_float4(x0*inv, x1*inv, x2*inv, 0.f);
        } else if (tt < 96) {
            int r = tt - 48;
            int hh = r / 12, i = r - hh * 12;
            int gi = i / 3;
            float was0 = __ldg(&g_Wa[32+hh*4+0]), was1 = __ldg(&g_Wa[32+hh*4+1]);
            float was2 = __ldg(&g_Wa[32+hh*4+2]), was3 = __ldg(&g_Wa[32+hh*4+3]);
            float wad0 = __ldg(&g_Wa[48+hh*4+0]), wad1 = __ldg(&g_Wa[48+hh*4+1]);
            float wad2 = __ldg(&g_Wa[48+hh*4+2]), wad3 = __ldg(&g_Wa[48+hh*4+3]);
            float es = nx[i*4]*was0 + nx[i*4+1]*was1 + nx[i*4+2]*was2 + nx[i*4+3]*was3;
            float ev[12], m = -1e30f;
            #pragma unroll
            for (int j = 0; j < 12; j++) {
                float ed = nx[j*4]*wad0 + nx[j*4+1]*wad1 + nx[j*4+2]*wad2 + nx[j*4+3]*wad3;
                float e = es + ed;
                e = (e > 0.f) ? e : 0.2f * e;
                bool valid = ((j / 3) != gi);
                ev[j] = valid ? e : -1e30f;
                if (valid && e > m) m = e;
            }
            float sum = 0.f, ex[12];
            #pragma unroll
            for (int j = 0; j < 12; j++) {
                float v = (ev[j] > -1e29f) ? __expf(ev[j] - m) : 0.f;
                ex[j] = v; sum += v;
            }
            float inv = 1.f / sum;
            #pragma unroll
            for (int j = 0; j < 12; j++)
                sAttF[((nl * 4 + hh) * 12 + i) * 12 + j] = ex[j] * inv;
        }

        // ---- Wh columns in registers ----
        float wh0[12], wh1[12];
        {
            float w00 = sW[h*128 +  0 + o], w01 = sW[h*128 + 32 + o];
            float w02 = sW[h*128 + 64 + o], w03 = sW[h*128 + 96 + o];
            float w10 = sW[512 + h*128 +  0 + o], w11 = sW[512 + h*128 + 32 + o];
            float w12 = sW[512 + h*128 + 64 + o], w13 = sW[512 + h*128 + 96 + o];
            #pragma unroll
            for (int j = 0; j < 12; j++) {
                float x0 = nx[j*4], x1 = nx[j*4+1], x2 = nx[j*4+2], x3 = nx[j*4+3];
                wh0[j] = x0*w00 + x1*w01 + x2*w02 + x3*w03;
                wh1[j] = x0*w10 + x1*w11 + x2*w12 + x3*w13;
            }
        }
        GBAR(nl);   // sAtt ready (group-local)

        // ---- aggregation (regs) + elu + shuffle-pack into A images ----
        {
            const int rbase = n8 * 12;
            #pragma unroll
            for (int i = 0; i < 12; i++) {
                const int j0 = (i / 3) * 3;
                float4 a = sAttC[(nl * 4 + h) * 12 + i];
                float vc = elu_f(a.x * wh0[j0] + a.y * wh0[j0+1] + a.z * wh0[j0+2]);
                const int g0 = j0;
                const float* ar = sAttF + ((nl * 4 + h) * 12 + i) * 12;
                float accf = 0.f;
                #pragma unroll
                for (int j = 0; j < 12; j++)
                    if (j < g0 || j >= g0 + 3) accf += ar[j] * wh1[j];
                float vf = elu_f(accf);

                const uint32_t rowoff = (uint32_t)(rbase + i) * A_RS;
                // stream 0 (coop): cols h*32 + (o,o^1)
                {
                    __nv_bfloat16 hb = __float2bfloat16(vc);
                    float rr = vc - __bfloat162float(hb);
                    __nv_bfloat16 lb = __float2bfloat16(rr);
                    uint32_t hu = (uint32_t)__bfloat16_as_ushort(hb);
                    uint32_t lu = (uint32_t)__bfloat16_as_ushort(lb);
                    uint32_t ho = __shfl_xor_sync(0xFFFFFFFFu, hu, 1);
                    uint32_t lo = __shfl_xor_sync(0xFFFFFFFFu, lu, 1);
                    uint32_t boff = rowoff + (uint32_t)(h * 64) + opair2;
                    if (evn) *(uint32_t*)(dsm + AHI_OFF + boff) = hu | (ho << 16);
                    else     *(uint32_t*)(dsm + ALO_OFF + boff) = lo | (lu << 16);
                }
                // stream 1 (conf): cols 128 + h*32 + (o,o^1)
                {
                    __nv_bfloat16 hb = __float2bfloat16(vf);
                    float rr = vf - __bfloat162float(hb);
                    __nv_bfloat16 lb = __float2bfloat16(rr);
                    uint32_t hu = (uint32_t)__bfloat16_as_ushort(hb);
                    uint32_t lu = (uint32_t)__bfloat16_as_ushort(lb);
                    uint32_t ho = __shfl_xor_sync(0xFFFFFFFFu, hu, 1);
                    uint32_t lo = __shfl_xor_sync(0xFFFFFFFFu, lu, 1);
                    uint32_t boff = rowoff + 256u + (uint32_t)(h * 64) + opair2;
                    if (evn) *(uint32_t*)(dsm + AHI_OFF + boff) = hu | (ho << 16);
                    else     *(uint32_t*)(dsm + ALO_OFF + boff) = lo | (lu << 16);
                }
            }
        }
        GBAR(nl);   // pack done; group may reuse sAtt next pass
    }
    __syncthreads();   // A images + B kc0 ready

    // ==================== GEMM ==============================================
    const int mtile = wid >> 1;
    const int nhalf = wid & 1;
    const int g = lid >> 2;
    const int q = lid & 3;
    const int row0 = mtile * 16 + g;
    const int row1 = row0 + 8;
    const bool mma_w = (wid < 12);

    const uint32_t sbase = smem_u32(dsm);
    const uint32_t a_lane = (uint32_t)((mtile * 16 + ((lid >> 3) & 1) * 8 + (lid & 7)) * A_RS
                          + ((lid >> 4) & 1) * 16);
    const uint32_t b_lane = (uint32_t)((nhalf * 64 + ((lid >> 4) & 1) * 8 + (lid & 7)) * CH_RS
                          + ((lid >> 3) & 1) * 16);

    float d[8][4];
    #pragma unroll
    for (int nt = 0; nt < 8; nt++) {
        d[nt][0] = 0.f; d[nt][1] = 0.f; d[nt][2] = 0.f; d[nt][3] = 0.f;
    }

    #pragma unroll
    for (int kc = 0; kc < 2; kc++) {
        if (kc == 1) {
            for (int i = t; i < 4096; i += 512) {
                int term = i >> 11;
                int r = i & 2047;
                int nr = r >> 4, c16 = r & 15;
                const uint4* gB = term ? gBL : gBH;
                *(uint4*)(dsm + X_OFF + term * B_IMG + nr * CH_RS + c16 * 16)
                    = gB[nr * 32 + 16 + c16];
            }
            __syncthreads();
        }

        if (mma_w) {
            const uint32_t aHb = sbase + AHI_OFF + a_lane + kc * 256;
            const uint32_t aLb = sbase + ALO_OFF + a_lane + kc * 256;
            const uint32_t bHb = sbase + X_OFF + b_lane;
            const uint32_t bLb = sbase + X_OFF + B_IMG + b_lane;

            #pragma unroll
            for (int ks = 0; ks < 8; ks++) {
                const uint32_t koff = ks * 32;
                uint32_t ah[4], al[4];
                LDSM_X4(ah, aHb + koff);
                LDSM_X4(al, aLb + koff);
                #pragma unroll
                for (int pp = 0; pp < 4; pp++) {
                    uint32_t bh[4], bl[4];
                    LDSM_X4(bh, bHb + pp * (16 * CH_RS) + koff);
                    LDSM_X4(bl, bLb + pp * (16 * CH_RS) + koff);
                    mma16816(d[2*pp],     ah, bh[0], bh[1]);
                    mma16816(d[2*pp],     ah, bl[0], bl[1]);
                    mma16816(d[2*pp],     al, bh[0], bh[1]);
                    mma16816(d[2*pp + 1], ah, bh[2], bh[3]);
                    mma16816(d[2*pp + 1], ah, bl[2], bl[3]);
                    mma16816(d[2*pp + 1], al, bh[2], bh[3]);
                }
            }
        }
        __syncthreads();
    }

    // ---- epilogue: elu(D+bias) -> Dbuf (X region), then 12-row mean ----
    float* Dbuf = (float*)(dsm + X_OFF);
    if (mma_w) {
        #pragma unroll
        for (int nt = 0; nt < 8; nt++) {
            int c0 = nhalf * 64 + nt * 8 + q * 2;
            float b0 = sbias[c0], b1 = sbias[c0 + 1];
            float2 v0 = make_float2(elu_f(d[nt][0] + b0), elu_f(d[nt][1] + b1));
            float2 v1 = make_float2(elu_f(d[nt][2] + b0), elu_f(d[nt][3] + b1));
            *(float2*)&Dbuf[row0 * 132 + c0] = v0;
            *(float2*)&Dbuf[row1 * 132 + c0] = v1;
        }
    }
    __syncthreads();

    if (t < 256) {
        int nl8 = t >> 5;
        int c4 = (t & 31) << 2;
        float4 s = make_float4(0.f, 0.f, 0.f, 0.f);
        #pragma unroll
        for (int j = 0; j < 12; j++) {
            float4 v = *(const float4*)&Dbuf[(nl8 * 12 + j) * 132 + c4];
            s.x += v.x; s.y += v.y; s.z += v.z; s.w += v.w;
        }
        s.x *= (1.f/12.f); s.y *= (1.f/12.f); s.z *= (1.f/12.f); s.w *= (1.f/12.f);
        int node = tile * 8 + nl8;
        int b = node / 5, slot = node - b * 5;
        if (slot == 0) *(float4*)&out[(size_t)b * 192 + c4] = s;
        else *(float4*)&g_nbr_emb[((size_t)b * 4 + (slot - 1)) * 128 + c4] = s;
    }
}

// ============================ KERNEL 2 ======================================
struct K2Smem {
    float nbr[8][4][132];
    float x[8][4][64];
    float gi[8][2][4][96];
    float gh[8][2][96];
    float h[8][2][32];
    float cat[8][192];
};
#define SMEM_K2 ((int)sizeof(K2Smem))

__global__ __launch_bounds__(256) void mgmq_k2(
    const float* __restrict__ mask, const float* __restrict__ dirs,
    const float* __restrict__ W_proj, const float* __restrict__ b_proj,
    const float* __restrict__ Wih_f, const float* __restrict__ Whh_f,
    const float* __restrict__ bih_f, const float* __restrict__ bhh_f,
    const float* __restrict__ Wih_b, const float* __restrict__ Whh_b,
    const float* __restrict__ bih_b, const float* __restrict__ bhh_b,
    const float* __restrict__ W_out, const float* __restrict__ b_out,
    float* __restrict__ out)
{
    extern __shared__ char k2dsm[];
    K2Smem* S = (K2Smem*)k2dsm;
    const int b0 = blockIdx.x * 8;
    const int t = threadIdx.x;

    for (int i = t; i < 1024; i += 256) {
        int bb = i >> 7, kk = (i >> 5) & 3, c4 = (i & 31) << 2;
        *(float4*)&S->nbr[bb][kk][c4] =
            *(const float4*)&g_nbr_emb[(((size_t)(b0 + bb)) * 4 + kk) * 128 + c4];
    }
    if (t < 32) S->nbr[t >> 2][t & 3][128] = dirs[(b0 + (t >> 2)) * 4 + (t & 3)];
    {
        int bb = t >> 5, c4 = (t & 31) << 2;
        *(float4*)&S->cat[bb][c4] = *(const float4*)&out[(size_t)(b0 + bb) * 192 + c4];
    }
    if (t < 128) {
        int bb = t >> 4, d = (t >> 3) & 1, g8 = (t & 7) << 2;
        *(float4*)&S->h[bb][d][g8] = make_float4(0.f, 0.f, 0.f, 0.f);
    }
    __syncthreads();

    {
        int combo = t & 63, grp = t >> 6;
        int kk = combo >> 4, j4 = (combo & 15) << 2;
        int bA = grp, bB = grp + 4;
        float4 bs = __ldg((const float4*)&b_proj[j4]);
        float4 a0 = bs, a1 = bs;
        #pragma unroll 4
        for (int i = 0; i < 129; i++) {
            float4 w = __ldg((const float4*)&W_proj[i * 64 + j4]);
            float x0 = S->nbr[bA][kk][i], x1 = S->nbr[bB][kk][i];
            a0.x += x0*w.x; a0.y += x0*w.y; a0.z += x0*w.z; a0.w += x0*w.w;
            a1.x += x1*w.x; a1.y += x1*w.y; a1.z += x1*w.z; a1.w += x1*w.w;
        }
        float m0 = mask[(b0 + bA) * 4 + kk], m1 = mask[(b0 + bB) * 4 + kk];
        a0.x = (a0.x > 0.f ? a0.x : 0.f) * m0; a0.y = (a0.y > 0.f ? a0.y : 0.f) * m0;
        a0.z = (a0.z > 0.f ? a0.z : 0.f) * m0; a0.w = (a0.w > 0.f ? a0.w : 0.f) * m0;
        a1.x = (a1.x > 0.f ? a1.x : 0.f) * m1; a1.y = (a1.y > 0.f ? a1.y : 0.f) * m1;
        a1.z = (a1.z > 0.f ? a1.z : 0.f) * m1; a1.w = (a1.w > 0.f ? a1.w : 0.f) * m1;
        *(float4*)&S->x[bA][kk][j4] = a0;
        *(float4*)&S->x[bB][kk][j4] = a1;
    }
    __syncthreads();

    if (t < 192) {
        int d = t / 96, r = t % 96, kk = r / 24, j4 = (r % 24) << 2;
        const float* Wih = d ? Wih_b : Wih_f;
        const float* bih = d ? bih_b : bih_f;
        float4 bs = __ldg((const float4*)&bih[j4]);
        float4 acc[8];
        #pragma unroll
        for (int bb = 0; bb < 8; bb++) acc[bb] = bs;
        for (int i = 0; i < 64; i++) {
            float4 w = __ldg((const float4*)&Wih[i * 96 + j4]);
            #pragma unroll
            for (int bb = 0; bb < 8; bb++) {
                float xv = S->x[bb][kk][i];
                acc[bb].x += xv*w.x; acc[bb].y += xv*w.y;
                acc[bb].z += xv*w.z; acc[bb].w += xv*w.w;
            }
        }
        #pragma unroll
        for (int bb = 0; bb < 8; bb++) *(float4*)&S->gi[bb][d][kk][j4] = acc[bb];
    }
    __syncthreads();

    for (int step = 0; step < 4; step++) {
        if (t < 192) {
            int combo = t % 48, grp = t / 48;
            int d = combo / 24, j4 = (combo % 24) << 2;
            int bA = grp, bB = grp + 4;
            const float* Whh = d ? Whh_b : Whh_f;
            const float* bhh = d ? bhh_b : bhh_f;
            float4 bs = __ldg((const float4*)&bhh[j4]);
            float4 a0 = bs, a1 = bs;
            #pragma unroll
            for (int i = 0; i < 32; i++) {
                float4 w = __ldg((const float4*)&Whh[i * 96 + j4]);
                float h0 = S->h[bA][d][i], h1 = S->h[bB][d][i];
                a0.x += h0*w.x; a0.y += h0*w.y; a0.z += h0*w.z; a0.w += h0*w.w;
                a1.x += h1*w.x; a1.y += h1*w.y; a1.z += h1*w.z; a1.w += h1*w.w;
            }
            *(float4*)&S->gh[bA][d][j4] = a0;
            *(float4*)&S->gh[bB][d][j4] = a1;
        }
        __syncthreads();
        {
            int bA = t >> 6, d = (t >> 5) & 1, g = t & 31;
            #pragma unroll
            for (int p = 0; p < 2; p++) {
                int bb = bA + p * 4;
                int kf = d ? (3 - step) : step;
                float r = sigmoid_fast(S->gi[bb][d][kf][g]      + S->gh[bb][d][g]);
                float z = sigmoid_fast(S->gi[bb][d][kf][32 + g] + S->gh[bb][d][32 + g]);
                float nn = tanh_fast(S->gi[bb][d][kf][64 + g] + r * S->gh[bb][d][64 + g]);
                S->h[bb][d][g] = (1.f - z) * nn + z * S->h[bb][d][g];
            }
        }
        __syncthreads();
    }

    for (int i = t; i < 512; i += 256) {
        int bb = i >> 6, r = i & 63;
        S->cat[bb][128 + r] = S->h[bb][r >> 5][r & 31];
    }
    __syncthreads();

    if (t < 128) {
        int bb = t >> 4, j4 = (t & 15) << 2;
        float4 acc = __ldg((const float4*)&b_out[j4]);
        #pragma unroll 4
        for (int i = 0; i < 192; i++) {
            float cv = S->cat[bb][i];
            float4 w = __ldg((const float4*)&W_out[i * 64 + j4]);
            acc.x += cv*w.x; acc.y += cv*w.y; acc.z += cv*w.z; acc.w += cv*w.w;
        }
        acc.x = acc.x > 0.f ? acc.x : 0.f;
        acc.y = acc.y > 0.f ? acc.y : 0.f;
        acc.z = acc.z > 0.f ? acc.z : 0.f;
        acc.w = acc.w > 0.f ? acc.w : 0.f;
        *(float4*)&out[(size_t)(b0 + bb) * 192 + 128 + j4] = acc;
    }
}

// ============================ launch ========================================
extern "C" void kernel_launch(void* const* d_in, const int* in_sizes, int n_in,
                              void* d_out, int out_size) {
    const float* self_f   = (const float*)d_in[0];
    const float* nbr_f    = (const float*)d_in[1];
    const float* mask     = (const float*)d_in[2];
    const float* dirs     = (const float*)d_in[3];
    const float* W_coop   = (const float*)d_in[4];
    const float* a_src_c  = (const float*)d_in[5];
    const float* a_dst_c  = (const float*)d_in[6];
    const float* W_conf   = (const float*)d_in[7];
    const float* a_src_f2 = (const float*)d_in[8];
    const float* a_dst_f2 = (const float*)d_in[9];
    const float* W_fuse   = (const float*)d_in[10];
    const float* b_fuse   = (const float*)d_in[11];
    const float* W_proj   = (const float*)d_in[12];
    const float* b_proj   = (const float*)d_in[13];
    const float* Wih_f    = (const float*)d_in[14];
    const float* Whh_f    = (const float*)d_in[15];
    const float* bih_f    = (const float*)d_in[16];
    const float* bhh_f    = (const float*)d_in[17];
    const float* Wih_b    = (const float*)d_in[18];
    const float* Whh_b    = (const float*)d_in[19];
    const float* bih_b    = (const float*)d_in[20];
    const float* bhh_b    = (const float*)d_in[21];
    const float* W_out    = (const float*)d_in[22];
    const float* b_out    = (const float*)d_in[23];
    float* out = (float*)d_out;

    cudaFuncSetAttribute(mgmq_fused, cudaFuncAttributeMaxDynamicSharedMemorySize, SMEM_FUSED);
    cudaFuncSetAttribute(mgmq_k2, cudaFuncAttributeMaxDynamicSharedMemorySize, SMEM_K2);

    mgmq_wsplit<<<128, 256>>>(W_fuse, W_coop, a_src_c, a_dst_c,
                              W_conf, a_src_f2, a_dst_f2);
    mgmq_fused<<<NTILES, 512, SMEM_FUSED>>>(self_f, nbr_f, W_coop, W_conf,
                                            b_fuse, out);
    mgmq_k2<<<NB / 8, 256, SMEM_K2>>>(mask, dirs, W_proj, b_proj,
                                      Wih_f, Whh_f, bih_f, bhh_f,
                                      Wih_b, Whh_b, bih_b, bhh_b,
                                      W_out, b_out, out);
}